// round 2
// baseline (speedup 1.0000x reference)
#include <cuda_runtime.h>

#define N_NODES  150000
#define N_EDGES  300000
#define N_GRAPHS 6000
#define HID      256

// ---------------- scratch (device globals; no allocations allowed) ----------
__device__ float g_bufA[N_NODES * HID];   // post-GEMM1 intermediate
__device__ float g_bufB[N_NODES * HID];   // layer output h
__device__ float g_bufC[N_NODES * HID];   // agg + x (pre-MLP)
__device__ float g_agg7[N_NODES * 7];     // layer-1 aggregate (dim 7)
__device__ float g_pooled[N_GRAPHS * HID];
__device__ float g_counts[N_GRAPHS];
__device__ float g_hid[N_GRAPHS * 128];

// ---------------- kernels ---------------------------------------------------

// scatter-add for layer 1 (feature dim 7): agg[dst] += x[src]
__global__ void scatter_add_7(const float* __restrict__ x,
                              const int* __restrict__ ei,
                              float* __restrict__ agg) {
    int e = blockIdx.x * blockDim.x + threadIdx.x;
    if (e >= N_EDGES) return;
    int s = ei[e];
    int d = ei[N_EDGES + e];
#pragma unroll
    for (int j = 0; j < 7; j++)
        atomicAdd(&agg[(long long)d * 7 + j], x[(long long)s * 7 + j]);
}

// scatter-add for 256-dim features: one warp per edge
__global__ void scatter_add_256(const float* __restrict__ x,
                                const int* __restrict__ ei,
                                float* __restrict__ agg) {
    int gw   = (blockIdx.x * blockDim.x + threadIdx.x) >> 5;
    int lane = threadIdx.x & 31;
    if (gw >= N_EDGES) return;
    int s = ei[gw];
    int d = ei[N_EDGES + gw];
    const float* xs = x + (long long)s * HID;
    float* ad = agg + (long long)d * HID;
#pragma unroll
    for (int j = 0; j < 8; j++)
        atomicAdd(ad + lane + 32 * j, xs[lane + 32 * j]);
}

// layer-1 first GEMM: C[m][n] = relu(b[n] + sum_{k<7} A[m][k] * W[k][n]), N=256
__global__ void gemm_k7_relu(const float* __restrict__ A,
                             const float* __restrict__ W,
                             const float* __restrict__ bias,
                             float* __restrict__ C) {
    int m = blockIdx.x;
    int n = threadIdx.x;  // 256 threads
    __shared__ float xs[7];
    if (n < 7) xs[n] = A[(long long)m * 7 + n];
    __syncthreads();
    float acc = bias[n];
#pragma unroll
    for (int j = 0; j < 7; j++)
        acc = fmaf(xs[j], W[j * 256 + n], acc);
    C[(long long)m * 256 + n] = fmaxf(acc, 0.0f);
}

// Tiled SGEMM: C[M,N] = act(A[M,K] @ B[K,N] + bias), BM=BN=128, BK=8, 8x8/thread.
// N must be a multiple of 128, K a multiple of 8. M is guarded.
__global__ __launch_bounds__(256)
void sgemm_bias_relu(int M, const float* __restrict__ A,
                     const float* __restrict__ B,
                     const float* __restrict__ bias,
                     float* __restrict__ C,
                     int N, int K, int doRelu) {
    __shared__ float As[8][128];
    __shared__ float Bs[8][128];

    const int tid       = threadIdx.x;
    const int block_row = blockIdx.y * 128;
    const int block_col = blockIdx.x * 128;

    // global-load mapping
    const int aRow = tid >> 1;           // 0..127 (2 threads per A row)
    const int aCol = (tid & 1) << 2;     // 0 or 4
    const int bRow = tid >> 5;           // 0..7
    const int bCol = (tid & 31) << 2;    // 0..124

    // compute mapping: 16x16 threads, each 8x8
    const int trow = (tid >> 4) << 3;
    const int tcol = (tid & 15) << 3;

    float acc[8][8];
#pragma unroll
    for (int i = 0; i < 8; i++)
#pragma unroll
        for (int j = 0; j < 8; j++) acc[i][j] = 0.0f;

    for (int kt = 0; kt < K; kt += 8) {
        float4 av = make_float4(0.f, 0.f, 0.f, 0.f);
        if (block_row + aRow < M)
            av = *reinterpret_cast<const float4*>(&A[(long long)(block_row + aRow) * K + kt + aCol]);
        As[aCol + 0][aRow] = av.x;
        As[aCol + 1][aRow] = av.y;
        As[aCol + 2][aRow] = av.z;
        As[aCol + 3][aRow] = av.w;

        float4 bv = *reinterpret_cast<const float4*>(&B[(long long)(kt + bRow) * N + block_col + bCol]);
        *reinterpret_cast<float4*>(&Bs[bRow][bCol]) = bv;

        __syncthreads();

#pragma unroll
        for (int k = 0; k < 8; k++) {
            float ra[8], rb[8];
#pragma unroll
            for (int i = 0; i < 8; i++) ra[i] = As[k][trow + i];
#pragma unroll
            for (int j = 0; j < 8; j++) rb[j] = Bs[k][tcol + j];
#pragma unroll
            for (int i = 0; i < 8; i++)
#pragma unroll
                for (int j = 0; j < 8; j++)
                    acc[i][j] = fmaf(ra[i], rb[j], acc[i][j]);
        }
        __syncthreads();
    }

    // epilogue: bias + optional relu
#pragma unroll
    for (int i = 0; i < 8; i++) {
        int r = block_row + trow + i;
        if (r < M) {
#pragma unroll
            for (int j = 0; j < 8; j += 4) {
                float4 v;
                v.x = acc[i][j + 0] + bias[block_col + tcol + j + 0];
                v.y = acc[i][j + 1] + bias[block_col + tcol + j + 1];
                v.z = acc[i][j + 2] + bias[block_col + tcol + j + 2];
                v.w = acc[i][j + 3] + bias[block_col + tcol + j + 3];
                if (doRelu) {
                    v.x = fmaxf(v.x, 0.f); v.y = fmaxf(v.y, 0.f);
                    v.z = fmaxf(v.z, 0.f); v.w = fmaxf(v.w, 0.f);
                }
                *reinterpret_cast<float4*>(&C[(long long)r * N + block_col + tcol + j]) = v;
            }
        }
    }
}

// mean-pool accumulation: one warp per node
__global__ void pool_kernel(const float* __restrict__ h,
                            const int* __restrict__ batch,
                            float* __restrict__ pooled,
                            float* __restrict__ counts) {
    int node = (blockIdx.x * blockDim.x + threadIdx.x) >> 5;
    int lane = threadIdx.x & 31;
    if (node >= N_NODES) return;
    int b = batch[node];
    const float* hs = h + (long long)node * HID;
    float* pd = pooled + (long long)b * HID;
#pragma unroll
    for (int j = 0; j < 8; j++)
        atomicAdd(pd + lane + 32 * j, hs[lane + 32 * j]);
    if (lane == 0) atomicAdd(&counts[b], 1.0f);
}

__global__ void pool_div(float* __restrict__ pooled,
                         const float* __restrict__ counts) {
    int i = blockIdx.x * blockDim.x + threadIdx.x;  // N_GRAPHS*HID threads
    float c = counts[i >> 8];
    pooled[i] = pooled[i] / fmaxf(c, 1.0f);
}

// final head: out[m][0..2] = hid[m] @ Wh2 + bh2  (K=128, N=3, no relu)
__global__ void head_final(const float* __restrict__ hid,
                           const float* __restrict__ W,
                           const float* __restrict__ b,
                           float* __restrict__ out) {
    int m = blockIdx.x * blockDim.x + threadIdx.x;
    if (m >= N_GRAPHS) return;
    float a0 = b[0], a1 = b[1], a2 = b[2];
    const float* hs = hid + (long long)m * 128;
#pragma unroll 8
    for (int k = 0; k < 128; k++) {
        float h = hs[k];
        a0 = fmaf(h, W[k * 3 + 0], a0);
        a1 = fmaf(h, W[k * 3 + 1], a1);
        a2 = fmaf(h, W[k * 3 + 2], a2);
    }
    out[m * 3 + 0] = a0;
    out[m * 3 + 1] = a1;
    out[m * 3 + 2] = a2;
}

// ---------------- launch ----------------------------------------------------

extern "C" void kernel_launch(void* const* d_in, const int* in_sizes, int n_in,
                              void* d_out, int out_size) {
    const float* x     = (const float*)d_in[0];
    const int*   ei    = (const int*)d_in[1];    // int32 (JAX x64 disabled)
    const int*   batch = (const int*)d_in[2];    // int32

    const float* Wa[4], *ba[4], *Wb[4], *bb[4];
    for (int l = 0; l < 4; l++) {
        Wa[l] = (const float*)d_in[3 + 4 * l + 0];
        ba[l] = (const float*)d_in[3 + 4 * l + 1];
        Wb[l] = (const float*)d_in[3 + 4 * l + 2];
        bb[l] = (const float*)d_in[3 + 4 * l + 3];
    }
    const float* Wh1 = (const float*)d_in[19];
    const float* bh1 = (const float*)d_in[20];
    const float* Wh2 = (const float*)d_in[21];
    const float* bh2 = (const float*)d_in[22];
    float* out = (float*)d_out;

    float *bufA, *bufB, *bufC, *agg7, *pooled, *counts, *hid;
    cudaGetSymbolAddress((void**)&bufA,   g_bufA);
    cudaGetSymbolAddress((void**)&bufB,   g_bufB);
    cudaGetSymbolAddress((void**)&bufC,   g_bufC);
    cudaGetSymbolAddress((void**)&agg7,   g_agg7);
    cudaGetSymbolAddress((void**)&pooled, g_pooled);
    cudaGetSymbolAddress((void**)&counts, g_counts);
    cudaGetSymbolAddress((void**)&hid,    g_hid);

    dim3 gemm_grid(HID / 128, (N_NODES + 127) / 128);

    // ---- layer 1 (input dim 7) ----
    cudaMemcpyAsync(agg7, x, (size_t)N_NODES * 7 * sizeof(float),
                    cudaMemcpyDeviceToDevice);
    scatter_add_7<<<(N_EDGES + 255) / 256, 256>>>(x, ei, agg7);
    gemm_k7_relu<<<N_NODES, 256>>>(agg7, Wa[0], ba[0], bufA);
    sgemm_bias_relu<<<gemm_grid, 256>>>(N_NODES, bufA, Wb[0], bb[0], bufB,
                                        256, 256, 1);

    // ---- layers 2..4 ----
    for (int l = 1; l < 4; l++) {
        cudaMemcpyAsync(bufC, bufB, (size_t)N_NODES * HID * sizeof(float),
                        cudaMemcpyDeviceToDevice);
        scatter_add_256<<<((size_t)N_EDGES * 32 + 255) / 256, 256>>>(bufB, ei, bufC);
        sgemm_bias_relu<<<gemm_grid, 256>>>(N_NODES, bufC, Wa[l], ba[l], bufA,
                                            256, 256, 1);
        sgemm_bias_relu<<<gemm_grid, 256>>>(N_NODES, bufA, Wb[l], bb[l], bufB,
                                            256, 256, 1);
    }

    // ---- mean pool ----
    cudaMemsetAsync(pooled, 0, (size_t)N_GRAPHS * HID * sizeof(float));
    cudaMemsetAsync(counts, 0, (size_t)N_GRAPHS * sizeof(float));
    pool_kernel<<<((size_t)N_NODES * 32 + 255) / 256, 256>>>(bufB, batch,
                                                             pooled, counts);
    pool_div<<<N_GRAPHS * HID / 256, 256>>>(pooled, counts);

    // ---- head ----
    dim3 head_grid(128 / 128, (N_GRAPHS + 127) / 128);
    sgemm_bias_relu<<<head_grid, 256>>>(N_GRAPHS, pooled, Wh1, bh1, hid,
                                        128, 256, 1);
    head_final<<<(N_GRAPHS + 255) / 256, 256>>>(hid, Wh2, bh2, out);
}

// round 4
// speedup vs baseline: 1.8480x; 1.8480x over previous
#include <cuda_runtime.h>
#include <cuda_bf16.h>
#include <cstdint>

#define N_NODES  150000
#define N_EDGES  300000
#define N_GRAPHS 6000
#define HID      256

// ============================ mma.sync helpers ==============================

__device__ __forceinline__ uint32_t smem_u32(const void* p) {
    uint32_t addr;
    asm("{ .reg .u64 tmp; cvta.to.shared.u64 tmp, %1; cvt.u32.u64 %0, tmp; }"
        : "=r"(addr) : "l"(p));
    return addr;
}

__device__ __forceinline__ void ldsm_x4(uint32_t addr, uint32_t* r) {
    asm volatile("ldmatrix.sync.aligned.m8n8.x4.shared.b16 {%0,%1,%2,%3}, [%4];"
                 : "=r"(r[0]), "=r"(r[1]), "=r"(r[2]), "=r"(r[3]) : "r"(addr));
}

__device__ __forceinline__ void mma16816(float* d, const uint32_t* a,
                                         uint32_t b0, uint32_t b1) {
    asm volatile(
        "mma.sync.aligned.m16n8k16.row.col.f32.bf16.bf16.f32 "
        "{%0,%1,%2,%3}, {%4,%5,%6,%7}, {%8,%9}, {%0,%1,%2,%3};"
        : "+f"(d[0]), "+f"(d[1]), "+f"(d[2]), "+f"(d[3])
        : "r"(a[0]), "r"(a[1]), "r"(a[2]), "r"(a[3]), "r"(b0), "r"(b1));
}

// ============================ scratch buffers ===============================

__device__ __nv_bfloat16 g_Ahi[(size_t)N_NODES * HID];
__device__ __nv_bfloat16 g_Alo[(size_t)N_NODES * HID];
__device__ __nv_bfloat16 g_A2hi[(size_t)N_NODES * HID];
__device__ __nv_bfloat16 g_A2lo[(size_t)N_NODES * HID];
__device__ float g_bufB[(size_t)N_NODES * HID];   // layer output (fp32)
__device__ float g_bufC[(size_t)N_NODES * HID];   // scatter accumulator
__device__ float g_agg7[N_NODES * 7];
__device__ __nv_bfloat16 g_Whi[7 * HID * HID];    // weights, [N][K] bf16 hi
__device__ __nv_bfloat16 g_Wlo[7 * HID * HID];    // weights, [N][K] bf16 lo
__device__ float g_pooled[N_GRAPHS * HID];
__device__ float g_counts[N_GRAPHS];
__device__ float g_hid[N_GRAPHS * 128];

// ============================ small kernels =================================

// weight fp32 [K][N] -> bf16 hi/lo [N][K] (transpose + split)
__global__ void convert_weight(const float* __restrict__ W,
                               __nv_bfloat16* __restrict__ Bhi,
                               __nv_bfloat16* __restrict__ Blo) {
    int n = blockIdx.x;   // 256
    int k = threadIdx.x;  // 256
    float v = W[k * HID + n];
    __nv_bfloat16 h = __float2bfloat16(v);
    Bhi[n * HID + k] = h;
    Blo[n * HID + k] = __float2bfloat16(v - __bfloat162float(h));
}

// hi/lo split of (agg + x), vectorized float4 -> 4 bf16 (uint2)
__global__ void convert_add_split(const float4* __restrict__ agg,
                                  const float4* __restrict__ x,
                                  uint2* __restrict__ hi,
                                  uint2* __restrict__ lo) {
    int i = blockIdx.x * blockDim.x + threadIdx.x;  // N_NODES*HID/4
    if (i >= N_NODES * HID / 4) return;
    float4 a = agg[i], b = x[i];
    float v0 = a.x + b.x, v1 = a.y + b.y, v2 = a.z + b.z, v3 = a.w + b.w;
    __nv_bfloat16 h0 = __float2bfloat16(v0), h1 = __float2bfloat16(v1);
    __nv_bfloat16 h2 = __float2bfloat16(v2), h3 = __float2bfloat16(v3);
    __nv_bfloat16 g0 = __float2bfloat16(v0 - __bfloat162float(h0));
    __nv_bfloat16 g1 = __float2bfloat16(v1 - __bfloat162float(h1));
    __nv_bfloat16 g2 = __float2bfloat16(v2 - __bfloat162float(h2));
    __nv_bfloat16 g3 = __float2bfloat16(v3 - __bfloat162float(h3));
    uint2 hp, lp;
    hp.x = ((uint32_t)__bfloat16_as_ushort(h1) << 16) | __bfloat16_as_ushort(h0);
    hp.y = ((uint32_t)__bfloat16_as_ushort(h3) << 16) | __bfloat16_as_ushort(h2);
    lp.x = ((uint32_t)__bfloat16_as_ushort(g1) << 16) | __bfloat16_as_ushort(g0);
    lp.y = ((uint32_t)__bfloat16_as_ushort(g3) << 16) | __bfloat16_as_ushort(g2);
    hi[i] = hp;
    lo[i] = lp;
}

// scatter-add for layer 1 (feature dim 7)
__global__ void scatter_add_7(const float* __restrict__ x,
                              const int* __restrict__ ei,
                              float* __restrict__ agg) {
    int e = blockIdx.x * blockDim.x + threadIdx.x;
    if (e >= N_EDGES) return;
    int s = ei[e];
    int d = ei[N_EDGES + e];
#pragma unroll
    for (int j = 0; j < 7; j++)
        atomicAdd(&agg[(size_t)d * 7 + j], x[(size_t)s * 7 + j]);
}

// scatter-add 256-dim: one warp per edge
__global__ void scatter_add_256(const float* __restrict__ x,
                                const int* __restrict__ ei,
                                float* __restrict__ agg) {
    int gw   = (blockIdx.x * blockDim.x + threadIdx.x) >> 5;
    int lane = threadIdx.x & 31;
    if (gw >= N_EDGES) return;
    int s = ei[gw];
    int d = ei[N_EDGES + gw];
    const float* xs = x + (size_t)s * HID;
    float* ad = agg + (size_t)d * HID;
#pragma unroll
    for (int j = 0; j < 8; j++)
        atomicAdd(ad + lane + 32 * j, xs[lane + 32 * j]);
}

// layer-1 first GEMM (K=7): writes relu result split into bf16 hi/lo
__global__ void gemm_k7_relu_split(const float* __restrict__ A,
                                   const float* __restrict__ W,
                                   const float* __restrict__ bias,
                                   __nv_bfloat16* __restrict__ Chi,
                                   __nv_bfloat16* __restrict__ Clo) {
    int m = blockIdx.x;
    int n = threadIdx.x;  // 256
    __shared__ float xs[7];
    if (n < 7) xs[n] = A[(size_t)m * 7 + n];
    __syncthreads();
    float acc = bias[n];
#pragma unroll
    for (int j = 0; j < 7; j++)
        acc = fmaf(xs[j], W[j * HID + n], acc);
    float v = fmaxf(acc, 0.0f);
    __nv_bfloat16 h = __float2bfloat16(v);
    Chi[(size_t)m * HID + n] = h;
    Clo[(size_t)m * HID + n] = __float2bfloat16(v - __bfloat162float(h));
}

// =================== bf16x3-split GEMM via mma.sync =========================
// D[M,256] = relu( (Ahi+Alo)[M,256] @ (Bhi+Blo)^T + bias ),
// computing AhiBhi + AhiBlo + AloBhi with fp32 accumulation.
// A: [M][256] bf16 row-major. B: [256(N)][256(K)] bf16 K-major.
// mode 0: write fp32 to Cf.   mode 1: write bf16 hi/lo to Chi/Clo.
// Block tile 128(M) x 128(N), K-chunk 32. 8 warps: 2(M) x 4(N) -> 64x32/warp.

#define ASTRIDE 40   // bf16 elements per smem row (80B) -> conflict-free LDSM

__global__ __launch_bounds__(256, 2)
void mma_gemm_split(int M,
                    const uint4* __restrict__ Ahi4, const uint4* __restrict__ Alo4,
                    const uint4* __restrict__ Bhi4, const uint4* __restrict__ Blo4,
                    const float* __restrict__ bias,
                    float* __restrict__ Cf,
                    __nv_bfloat16* __restrict__ Chi,
                    __nv_bfloat16* __restrict__ Clo,
                    int mode) {
    __shared__ __align__(16) __nv_bfloat16 sAhi[128 * ASTRIDE];
    __shared__ __align__(16) __nv_bfloat16 sAlo[128 * ASTRIDE];
    __shared__ __align__(16) __nv_bfloat16 sBhi[128 * ASTRIDE];
    __shared__ __align__(16) __nv_bfloat16 sBlo[128 * ASTRIDE];

    const int tid  = threadIdx.x;
    const int wid  = tid >> 5;
    const int lane = tid & 31;
    const int wm   = wid & 1;        // M half (64 rows)
    const int wn   = wid >> 1;       // N quarter (32 cols)
    const int block_col = blockIdx.x * 128;
    const int block_row = blockIdx.y * 128;

    const uint32_t uAhi = smem_u32(sAhi);
    const uint32_t uAlo = smem_u32(sAlo);
    const uint32_t uBhi = smem_u32(sBhi);
    const uint32_t uBlo = smem_u32(sBlo);

    // ldmatrix lane addressing
    const int a_lrow = lane & 15;
    const int a_lcol = (lane >> 4) << 3;
    const int b_lrow = (lane & 7) + ((lane >> 4) & 1) * 8;
    const int b_lcol = ((lane >> 3) & 1) << 3;

    float acc[4][4][4];
#pragma unroll
    for (int i = 0; i < 4; i++)
#pragma unroll
        for (int j = 0; j < 4; j++)
#pragma unroll
            for (int c = 0; c < 4; c++) acc[i][j][c] = 0.0f;

    // gmem load mapping: 512 uint4 per tile, 2 per thread per tile
    const int ldrow = tid >> 2;        // 0..63 (x2 via +64)
    const int ldc   = tid & 3;         // 0..3

    for (int kc = 0; kc < 8; kc++) {
        // ---- load tiles ----
#pragma unroll
        for (int h = 0; h < 2; h++) {
            int row = ldrow + h * 64;
            int rg = block_row + row;
            if (rg >= M) rg = M - 1;
            int gA = rg * 32 + kc * 4 + ldc;
            uint32_t so = (uint32_t)(row * ASTRIDE + ldc * 8) * 2;
            *reinterpret_cast<uint4*>((char*)sAhi + so) = Ahi4[gA];
            *reinterpret_cast<uint4*>((char*)sAlo + so) = Alo4[gA];
            int gB = (block_col + row) * 32 + kc * 4 + ldc;
            *reinterpret_cast<uint4*>((char*)sBhi + so) = Bhi4[gB];
            *reinterpret_cast<uint4*>((char*)sBlo + so) = Blo4[gB];
        }
        __syncthreads();

        // ---- compute: 2 k-steps of 16 ----
#pragma unroll
        for (int ks = 0; ks < 32; ks += 16) {
            uint32_t ah[4][4], al[4][4], bh[2][4], bl[2][4];
#pragma unroll
            for (int f = 0; f < 4; f++) {
                uint32_t off = (uint32_t)((wm * 64 + f * 16 + a_lrow) * ASTRIDE +
                                          ks + a_lcol) * 2;
                ldsm_x4(uAhi + off, ah[f]);
                ldsm_x4(uAlo + off, al[f]);
            }
#pragma unroll
            for (int p = 0; p < 2; p++) {
                uint32_t off = (uint32_t)((wn * 32 + p * 16 + b_lrow) * ASTRIDE +
                                          ks + b_lcol) * 2;
                ldsm_x4(uBhi + off, bh[p]);
                ldsm_x4(uBlo + off, bl[p]);
            }
#pragma unroll
            for (int mf = 0; mf < 4; mf++) {
#pragma unroll
                for (int nf = 0; nf < 4; nf++) {
                    int p = nf >> 1, q = (nf & 1) * 2;
                    mma16816(acc[mf][nf], ah[mf], bh[p][q], bh[p][q + 1]); // hi*hi
                    mma16816(acc[mf][nf], ah[mf], bl[p][q], bl[p][q + 1]); // hi*lo
                    mma16816(acc[mf][nf], al[mf], bh[p][q], bh[p][q + 1]); // lo*hi
                }
            }
        }
        __syncthreads();
    }

    // ---- epilogue ----
#pragma unroll
    for (int mf = 0; mf < 4; mf++) {
        int r0 = block_row + wm * 64 + mf * 16 + (lane >> 2);
        int r1 = r0 + 8;
#pragma unroll
        for (int nf = 0; nf < 4; nf++) {
            int col = block_col + wn * 32 + nf * 8 + (lane & 3) * 2;
            float b0 = bias[col], b1 = bias[col + 1];
            float v00 = fmaxf(acc[mf][nf][0] + b0, 0.f);
            float v01 = fmaxf(acc[mf][nf][1] + b1, 0.f);
            float v10 = fmaxf(acc[mf][nf][2] + b0, 0.f);
            float v11 = fmaxf(acc[mf][nf][3] + b1, 0.f);
            if (mode == 0) {
                if (r0 < M)
                    *reinterpret_cast<float2*>(&Cf[(size_t)r0 * HID + col]) =
                        make_float2(v00, v01);
                if (r1 < M)
                    *reinterpret_cast<float2*>(&Cf[(size_t)r1 * HID + col]) =
                        make_float2(v10, v11);
            } else {
                __nv_bfloat16 h0 = __float2bfloat16(v00);
                __nv_bfloat16 h1 = __float2bfloat16(v01);
                __nv_bfloat16 h2 = __float2bfloat16(v10);
                __nv_bfloat16 h3 = __float2bfloat16(v11);
                uint32_t hp0 = ((uint32_t)__bfloat16_as_ushort(h1) << 16) |
                               __bfloat16_as_ushort(h0);
                uint32_t hp1 = ((uint32_t)__bfloat16_as_ushort(h3) << 16) |
                               __bfloat16_as_ushort(h2);
                uint32_t lp0, lp1;
                {
                    __nv_bfloat16 g0 = __float2bfloat16(v00 - __bfloat162float(h0));
                    __nv_bfloat16 g1 = __float2bfloat16(v01 - __bfloat162float(h1));
                    __nv_bfloat16 g2 = __float2bfloat16(v10 - __bfloat162float(h2));
                    __nv_bfloat16 g3 = __float2bfloat16(v11 - __bfloat162float(h3));
                    lp0 = ((uint32_t)__bfloat16_as_ushort(g1) << 16) |
                          __bfloat16_as_ushort(g0);
                    lp1 = ((uint32_t)__bfloat16_as_ushort(g3) << 16) |
                          __bfloat16_as_ushort(g2);
                }
                if (r0 < M) {
                    *reinterpret_cast<uint32_t*>(Chi + (size_t)r0 * HID + col) = hp0;
                    *reinterpret_cast<uint32_t*>(Clo + (size_t)r0 * HID + col) = lp0;
                }
                if (r1 < M) {
                    *reinterpret_cast<uint32_t*>(Chi + (size_t)r1 * HID + col) = hp1;
                    *reinterpret_cast<uint32_t*>(Clo + (size_t)r1 * HID + col) = lp1;
                }
            }
        }
    }
}

// =================== fp32 tiled SGEMM (small head GEMM) =====================

__global__ __launch_bounds__(256)
void sgemm_bias_relu(int M, const float* __restrict__ A,
                     const float* __restrict__ B,
                     const float* __restrict__ bias,
                     float* __restrict__ C,
                     int N, int K, int doRelu) {
    __shared__ float As[8][128];
    __shared__ float Bs[8][128];

    const int tid       = threadIdx.x;
    const int block_row = blockIdx.y * 128;
    const int block_col = blockIdx.x * 128;

    const int aRow = tid >> 1;
    const int aCol = (tid & 1) << 2;
    const int bRow = tid >> 5;
    const int bCol = (tid & 31) << 2;
    const int trow = (tid >> 4) << 3;
    const int tcol = (tid & 15) << 3;

    float acc[8][8];
#pragma unroll
    for (int i = 0; i < 8; i++)
#pragma unroll
        for (int j = 0; j < 8; j++) acc[i][j] = 0.0f;

    for (int kt = 0; kt < K; kt += 8) {
        float4 av = make_float4(0.f, 0.f, 0.f, 0.f);
        if (block_row + aRow < M)
            av = *reinterpret_cast<const float4*>(&A[(size_t)(block_row + aRow) * K + kt + aCol]);
        As[aCol + 0][aRow] = av.x;
        As[aCol + 1][aRow] = av.y;
        As[aCol + 2][aRow] = av.z;
        As[aCol + 3][aRow] = av.w;

        float4 bv = *reinterpret_cast<const float4*>(&B[(size_t)(kt + bRow) * N + block_col + bCol]);
        *reinterpret_cast<float4*>(&Bs[bRow][bCol]) = bv;
        __syncthreads();

#pragma unroll
        for (int k = 0; k < 8; k++) {
            float ra[8], rb[8];
#pragma unroll
            for (int i = 0; i < 8; i++) ra[i] = As[k][trow + i];
#pragma unroll
            for (int j = 0; j < 8; j++) rb[j] = Bs[k][tcol + j];
#pragma unroll
            for (int i = 0; i < 8; i++)
#pragma unroll
                for (int j = 0; j < 8; j++)
                    acc[i][j] = fmaf(ra[i], rb[j], acc[i][j]);
        }
        __syncthreads();
    }

#pragma unroll
    for (int i = 0; i < 8; i++) {
        int r = block_row + trow + i;
        if (r < M) {
#pragma unroll
            for (int j = 0; j < 8; j += 4) {
                float4 v;
                v.x = acc[i][j + 0] + bias[block_col + tcol + j + 0];
                v.y = acc[i][j + 1] + bias[block_col + tcol + j + 1];
                v.z = acc[i][j + 2] + bias[block_col + tcol + j + 2];
                v.w = acc[i][j + 3] + bias[block_col + tcol + j + 3];
                if (doRelu) {
                    v.x = fmaxf(v.x, 0.f); v.y = fmaxf(v.y, 0.f);
                    v.z = fmaxf(v.z, 0.f); v.w = fmaxf(v.w, 0.f);
                }
                *reinterpret_cast<float4*>(&C[(size_t)r * N + block_col + tcol + j]) = v;
            }
        }
    }
}

// ============================ pooling + head ================================

__global__ void pool_kernel(const float* __restrict__ h,
                            const int* __restrict__ batch,
                            float* __restrict__ pooled,
                            float* __restrict__ counts) {
    int node = (blockIdx.x * blockDim.x + threadIdx.x) >> 5;
    int lane = threadIdx.x & 31;
    if (node >= N_NODES) return;
    int b = batch[node];
    const float* hs = h + (size_t)node * HID;
    float* pd = pooled + (size_t)b * HID;
#pragma unroll
    for (int j = 0; j < 8; j++)
        atomicAdd(pd + lane + 32 * j, hs[lane + 32 * j]);
    if (lane == 0) atomicAdd(&counts[b], 1.0f);
}

__global__ void pool_div(float* __restrict__ pooled,
                         const float* __restrict__ counts) {
    int i = blockIdx.x * blockDim.x + threadIdx.x;
    float c = counts[i >> 8];
    pooled[i] = pooled[i] / fmaxf(c, 1.0f);
}

__global__ void head_final(const float* __restrict__ hid,
                           const float* __restrict__ W,
                           const float* __restrict__ b,
                           float* __restrict__ out) {
    int m = blockIdx.x * blockDim.x + threadIdx.x;
    if (m >= N_GRAPHS) return;
    float a0 = b[0], a1 = b[1], a2 = b[2];
    const float* hs = hid + (size_t)m * 128;
#pragma unroll 8
    for (int k = 0; k < 128; k++) {
        float h = hs[k];
        a0 = fmaf(h, W[k * 3 + 0], a0);
        a1 = fmaf(h, W[k * 3 + 1], a1);
        a2 = fmaf(h, W[k * 3 + 2], a2);
    }
    out[m * 3 + 0] = a0;
    out[m * 3 + 1] = a1;
    out[m * 3 + 2] = a2;
}

// ============================ launch ========================================

extern "C" void kernel_launch(void* const* d_in, const int* in_sizes, int n_in,
                              void* d_out, int out_size) {
    const float* x     = (const float*)d_in[0];
    const int*   ei    = (const int*)d_in[1];
    const int*   batch = (const int*)d_in[2];

    const float* Wa[4], *ba[4], *Wb[4], *bb[4];
    for (int l = 0; l < 4; l++) {
        Wa[l] = (const float*)d_in[3 + 4 * l + 0];
        ba[l] = (const float*)d_in[3 + 4 * l + 1];
        Wb[l] = (const float*)d_in[3 + 4 * l + 2];
        bb[l] = (const float*)d_in[3 + 4 * l + 3];
    }
    const float* Wh1 = (const float*)d_in[19];
    const float* bh1 = (const float*)d_in[20];
    const float* Wh2 = (const float*)d_in[21];
    const float* bh2 = (const float*)d_in[22];
    float* out = (float*)d_out;

    __nv_bfloat16 *Ahi, *Alo, *A2hi, *A2lo, *Whi, *Wlo;
    float *bufB, *bufC, *agg7, *pooled, *counts, *hid;
    cudaGetSymbolAddress((void**)&Ahi,    g_Ahi);
    cudaGetSymbolAddress((void**)&Alo,    g_Alo);
    cudaGetSymbolAddress((void**)&A2hi,   g_A2hi);
    cudaGetSymbolAddress((void**)&A2lo,   g_A2lo);
    cudaGetSymbolAddress((void**)&Whi,    g_Whi);
    cudaGetSymbolAddress((void**)&Wlo,    g_Wlo);
    cudaGetSymbolAddress((void**)&bufB,   g_bufB);
    cudaGetSymbolAddress((void**)&bufC,   g_bufC);
    cudaGetSymbolAddress((void**)&agg7,   g_agg7);
    cudaGetSymbolAddress((void**)&pooled, g_pooled);
    cudaGetSymbolAddress((void**)&counts, g_counts);
    cudaGetSymbolAddress((void**)&hid,    g_hid);

    // weight conversion: slots 0=W1b, 1=W2a, 2=W2b, 3=W3a, 4=W3b, 5=W4a, 6=W4b
    const float* Wsrc[7] = { Wb[0], Wa[1], Wb[1], Wa[2], Wb[2], Wa[3], Wb[3] };
    for (int w = 0; w < 7; w++)
        convert_weight<<<HID, HID>>>(Wsrc[w], Whi + (size_t)w * HID * HID,
                                     Wlo + (size_t)w * HID * HID);

    dim3 mma_grid(2, (N_NODES + 127) / 128);
    const int CV_GRID = (N_NODES * HID / 4 + 255) / 256;

    // ---- layer 1 ----
    cudaMemcpyAsync(agg7, x, (size_t)N_NODES * 7 * sizeof(float),
                    cudaMemcpyDeviceToDevice);
    scatter_add_7<<<(N_EDGES + 255) / 256, 256>>>(x, ei, agg7);
    gemm_k7_relu_split<<<N_NODES, 256>>>(agg7, Wa[0], ba[0], A2hi, A2lo);
    mma_gemm_split<<<mma_grid, 256>>>(
        N_NODES, (const uint4*)A2hi, (const uint4*)A2lo,
        (const uint4*)(Whi + 0 * HID * HID), (const uint4*)(Wlo + 0 * HID * HID),
        bb[0], bufB, nullptr, nullptr, 0);

    // ---- layers 2..4 ----
    for (int l = 1; l < 4; l++) {
        cudaMemsetAsync(bufC, 0, (size_t)N_NODES * HID * sizeof(float));
        scatter_add_256<<<((size_t)N_EDGES * 32 + 255) / 256, 256>>>(bufB, ei, bufC);
        convert_add_split<<<CV_GRID, 256>>>((const float4*)bufC, (const float4*)bufB,
                                            (uint2*)Ahi, (uint2*)Alo);
        mma_gemm_split<<<mma_grid, 256>>>(
            N_NODES, (const uint4*)Ahi, (const uint4*)Alo,
            (const uint4*)(Whi + (size_t)(2 * l - 1) * HID * HID),
            (const uint4*)(Wlo + (size_t)(2 * l - 1) * HID * HID),
            ba[l], nullptr, A2hi, A2lo, 1);
        mma_gemm_split<<<mma_grid, 256>>>(
            N_NODES, (const uint4*)A2hi, (const uint4*)A2lo,
            (const uint4*)(Whi + (size_t)(2 * l) * HID * HID),
            (const uint4*)(Wlo + (size_t)(2 * l) * HID * HID),
            bb[l], bufB, nullptr, nullptr, 0);
    }

    // ---- mean pool ----
    cudaMemsetAsync(pooled, 0, (size_t)N_GRAPHS * HID * sizeof(float));
    cudaMemsetAsync(counts, 0, (size_t)N_GRAPHS * sizeof(float));
    pool_kernel<<<((size_t)N_NODES * 32 + 255) / 256, 256>>>(bufB, batch,
                                                             pooled, counts);
    pool_div<<<N_GRAPHS * HID / 256, 256>>>(pooled, counts);

    // ---- head ----
    dim3 head_grid(1, (N_GRAPHS + 127) / 128);
    sgemm_bias_relu<<<head_grid, 256>>>(N_GRAPHS, pooled, Wh1, bh1, hid,
                                        128, 256, 1);
    head_final<<<(N_GRAPHS + 255) / 256, 256>>>(hid, Wh2, bh2, out);
}

// round 5
// speedup vs baseline: 2.0998x; 1.1363x over previous
#include <cuda_runtime.h>
#include <cuda_bf16.h>
#include <cstdint>

#define N_NODES  150000
#define N_EDGES  300000
#define N_GRAPHS 6000
#define HID      256

// ============================ mma.sync helpers ==============================

__device__ __forceinline__ uint32_t smem_u32(const void* p) {
    uint32_t addr;
    asm("{ .reg .u64 tmp; cvta.to.shared.u64 tmp, %1; cvt.u32.u64 %0, tmp; }"
        : "=r"(addr) : "l"(p));
    return addr;
}

__device__ __forceinline__ void ldsm_x4(uint32_t addr, uint32_t* r) {
    asm volatile("ldmatrix.sync.aligned.m8n8.x4.shared.b16 {%0,%1,%2,%3}, [%4];"
                 : "=r"(r[0]), "=r"(r[1]), "=r"(r[2]), "=r"(r[3]) : "r"(addr));
}

__device__ __forceinline__ void mma16816(float* d, const uint32_t* a,
                                         uint32_t b0, uint32_t b1) {
    asm volatile(
        "mma.sync.aligned.m16n8k16.row.col.f32.bf16.bf16.f32 "
        "{%0,%1,%2,%3}, {%4,%5,%6,%7}, {%8,%9}, {%0,%1,%2,%3};"
        : "+f"(d[0]), "+f"(d[1]), "+f"(d[2]), "+f"(d[3])
        : "r"(a[0]), "r"(a[1]), "r"(a[2]), "r"(a[3]), "r"(b0), "r"(b1));
}

__device__ __forceinline__ void cp_async16(uint32_t smem_addr, const void* g) {
    asm volatile("cp.async.cg.shared.global [%0], [%1], 16;"
                 :: "r"(smem_addr), "l"(g));
}
#define CP_COMMIT() asm volatile("cp.async.commit_group;" ::: "memory")
#define CP_WAIT(n)  asm volatile("cp.async.wait_group %0;" :: "n"(n) : "memory")

// ============================ scratch buffers ===============================

__device__ __nv_bfloat16 g_Ahi[(size_t)N_NODES * HID];
__device__ __nv_bfloat16 g_Alo[(size_t)N_NODES * HID];
__device__ __nv_bfloat16 g_A2hi[(size_t)N_NODES * HID];
__device__ __nv_bfloat16 g_A2lo[(size_t)N_NODES * HID];
__device__ float g_bufB[(size_t)N_NODES * HID];   // layer output h (gather src)
__device__ float g_bufC[(size_t)N_NODES * HID];   // scatter accumulator (init h)
__device__ float g_agg7[N_NODES * 7];
__device__ __nv_bfloat16 g_Whi[7 * HID * HID];    // weights, [N][K] bf16 hi
__device__ __nv_bfloat16 g_Wlo[7 * HID * HID];    // weights, [N][K] bf16 lo
__device__ float g_pooled[N_GRAPHS * HID];
__device__ float g_counts[N_GRAPHS];
__device__ float g_hid[N_GRAPHS * 128];

// ============================ small kernels =================================

// all 7 weight matrices: fp32 [K][N] -> bf16 hi/lo [N][K] (transpose + split)
__global__ void convert_weight_all(const float* __restrict__ W0,
                                   const float* __restrict__ W1,
                                   const float* __restrict__ W2,
                                   const float* __restrict__ W3,
                                   const float* __restrict__ W4,
                                   const float* __restrict__ W5,
                                   const float* __restrict__ W6,
                                   __nv_bfloat16* __restrict__ Whi,
                                   __nv_bfloat16* __restrict__ Wlo) {
    int w = blockIdx.y;
    const float* W = (w == 0) ? W0 : (w == 1) ? W1 : (w == 2) ? W2 :
                     (w == 3) ? W3 : (w == 4) ? W4 : (w == 5) ? W5 : W6;
    int n = blockIdx.x;   // 256
    int k = threadIdx.x;  // 256
    float v = W[k * HID + n];
    __nv_bfloat16 h = __float2bfloat16(v);
    size_t o = (size_t)w * HID * HID + n * HID + k;
    Whi[o] = h;
    Wlo[o] = __float2bfloat16(v - __bfloat162float(h));
}

// hi/lo split (input already = agg + x)
__global__ void convert_split(const float4* __restrict__ in,
                              uint2* __restrict__ hi,
                              uint2* __restrict__ lo) {
    int i = blockIdx.x * blockDim.x + threadIdx.x;  // N_NODES*HID/4
    if (i >= N_NODES * HID / 4) return;
    float4 a = in[i];
    __nv_bfloat16 h0 = __float2bfloat16(a.x), h1 = __float2bfloat16(a.y);
    __nv_bfloat16 h2 = __float2bfloat16(a.z), h3 = __float2bfloat16(a.w);
    __nv_bfloat16 g0 = __float2bfloat16(a.x - __bfloat162float(h0));
    __nv_bfloat16 g1 = __float2bfloat16(a.y - __bfloat162float(h1));
    __nv_bfloat16 g2 = __float2bfloat16(a.z - __bfloat162float(h2));
    __nv_bfloat16 g3 = __float2bfloat16(a.w - __bfloat162float(h3));
    uint2 hp, lp;
    hp.x = ((uint32_t)__bfloat16_as_ushort(h1) << 16) | __bfloat16_as_ushort(h0);
    hp.y = ((uint32_t)__bfloat16_as_ushort(h3) << 16) | __bfloat16_as_ushort(h2);
    lp.x = ((uint32_t)__bfloat16_as_ushort(g1) << 16) | __bfloat16_as_ushort(g0);
    lp.y = ((uint32_t)__bfloat16_as_ushort(g3) << 16) | __bfloat16_as_ushort(g2);
    hi[i] = hp;
    lo[i] = lp;
}

// scatter-add for layer 1 (feature dim 7)
__global__ void scatter_add_7(const float* __restrict__ x,
                              const int* __restrict__ ei,
                              float* __restrict__ agg) {
    int e = blockIdx.x * blockDim.x + threadIdx.x;
    if (e >= N_EDGES) return;
    int s = ei[e];
    int d = ei[N_EDGES + e];
#pragma unroll
    for (int j = 0; j < 7; j++)
        atomicAdd(&agg[(size_t)d * 7 + j], x[(size_t)s * 7 + j]);
}

// scatter-add 256-dim: one warp per edge; agg pre-initialized with self term
__global__ void scatter_add_256(const float* __restrict__ x,
                                const int* __restrict__ ei,
                                float* __restrict__ agg) {
    int gw   = (blockIdx.x * blockDim.x + threadIdx.x) >> 5;
    int lane = threadIdx.x & 31;
    if (gw >= N_EDGES) return;
    int s = ei[gw];
    int d = ei[N_EDGES + gw];
    const float* xs = x + (size_t)s * HID;
    float* ad = agg + (size_t)d * HID;
#pragma unroll
    for (int j = 0; j < 8; j++)
        atomicAdd(ad + lane + 32 * j, xs[lane + 32 * j]);
}

// layer-1 first GEMM (K=7): writes relu result split into bf16 hi/lo
__global__ void gemm_k7_relu_split(const float* __restrict__ A,
                                   const float* __restrict__ W,
                                   const float* __restrict__ bias,
                                   __nv_bfloat16* __restrict__ Chi,
                                   __nv_bfloat16* __restrict__ Clo) {
    int m = blockIdx.x;
    int n = threadIdx.x;  // 256
    __shared__ float xs[7];
    if (n < 7) xs[n] = A[(size_t)m * 7 + n];
    __syncthreads();
    float acc = bias[n];
#pragma unroll
    for (int j = 0; j < 7; j++)
        acc = fmaf(xs[j], W[j * HID + n], acc);
    float v = fmaxf(acc, 0.0f);
    __nv_bfloat16 h = __float2bfloat16(v);
    Chi[(size_t)m * HID + n] = h;
    Clo[(size_t)m * HID + n] = __float2bfloat16(v - __bfloat162float(h));
}

// =================== bf16x3-split GEMM via mma.sync + cp.async ==============
// D[M,256] = relu( (Ahi+Alo)[M,256] @ (Bhi+Blo)^T + bias )
// mode 0: write fp32 to Cf (and Cc if non-null).
// mode 1: write bf16 hi/lo to Chi/Clo.
// Block tile 128(M) x 128(N), K-chunk 32, 2-stage cp.async pipeline.

#define ASTRIDE 40                     // bf16 per smem row (80B, 16B-aligned)
#define TILE_B  (128 * ASTRIDE * 2)    // 10240 bytes per tile
#define STAGE_B (4 * TILE_B)           // 40960 bytes per stage
#define GEMM_SMEM (2 * STAGE_B)        // 81920 bytes

__global__ __launch_bounds__(256, 2)
void mma_gemm_split(int M,
                    const uint4* __restrict__ Ahi4, const uint4* __restrict__ Alo4,
                    const uint4* __restrict__ Bhi4, const uint4* __restrict__ Blo4,
                    const float* __restrict__ bias,
                    float* __restrict__ Cf, float* __restrict__ Cc,
                    __nv_bfloat16* __restrict__ Chi,
                    __nv_bfloat16* __restrict__ Clo,
                    int mode) {
    extern __shared__ char smem[];
    const uint32_t sb = smem_u32(smem);

    const int tid  = threadIdx.x;
    const int wid  = tid >> 5;
    const int lane = tid & 31;
    const int wm   = wid & 1;        // M half (64 rows)
    const int wn   = wid >> 1;       // N quarter (32 cols)
    const int block_col = blockIdx.x * 128;
    const int block_row = blockIdx.y * 128;

    // ldmatrix lane addressing
    const int a_lrow = lane & 15;
    const int a_lcol = (lane >> 4) << 3;
    const int b_lrow = (lane & 7) + ((lane >> 4) & 1) * 8;
    const int b_lcol = ((lane >> 3) & 1) << 3;

    float acc[4][4][4];
#pragma unroll
    for (int i = 0; i < 4; i++)
#pragma unroll
        for (int j = 0; j < 4; j++)
#pragma unroll
            for (int c = 0; c < 4; c++) acc[i][j][c] = 0.0f;

    // gmem load mapping: per tile 512 uint4; each thread 2 (rows ldrow, +64)
    const int ldrow = tid >> 2;        // 0..63
    const int ldc   = tid & 3;         // 0..3

    // --- pipeline issue: load K-chunk kc into stage kc&1 ---
    auto issue = [&](int kc) {
        uint32_t sbase = sb + (uint32_t)(kc & 1) * STAGE_B;
#pragma unroll
        for (int h = 0; h < 2; h++) {
            int row = ldrow + h * 64;
            int rg = block_row + row;
            if (rg >= M) rg = M - 1;
            size_t gA = (size_t)rg * 32 + kc * 4 + ldc;
            size_t gB = (size_t)(block_col + row) * 32 + kc * 4 + ldc;
            uint32_t so = (uint32_t)(row * ASTRIDE + ldc * 8) * 2;
            cp_async16(sbase + 0 * TILE_B + so, Ahi4 + gA);
            cp_async16(sbase + 1 * TILE_B + so, Alo4 + gA);
            cp_async16(sbase + 2 * TILE_B + so, Bhi4 + gB);
            cp_async16(sbase + 3 * TILE_B + so, Blo4 + gB);
        }
        CP_COMMIT();
    };

    issue(0);

    for (int kc = 0; kc < 8; kc++) {
        if (kc < 7) { issue(kc + 1); CP_WAIT(1); }
        else        { CP_WAIT(0); }
        __syncthreads();

        uint32_t base = sb + (uint32_t)(kc & 1) * STAGE_B;
        uint32_t uAhi = base + 0 * TILE_B;
        uint32_t uAlo = base + 1 * TILE_B;
        uint32_t uBhi = base + 2 * TILE_B;
        uint32_t uBlo = base + 3 * TILE_B;

#pragma unroll
        for (int ks = 0; ks < 32; ks += 16) {
            uint32_t ah[4][4], al[4][4], bh[2][4], bl[2][4];
#pragma unroll
            for (int f = 0; f < 4; f++) {
                uint32_t off = (uint32_t)((wm * 64 + f * 16 + a_lrow) * ASTRIDE +
                                          ks + a_lcol) * 2;
                ldsm_x4(uAhi + off, ah[f]);
                ldsm_x4(uAlo + off, al[f]);
            }
#pragma unroll
            for (int p = 0; p < 2; p++) {
                uint32_t off = (uint32_t)((wn * 32 + p * 16 + b_lrow) * ASTRIDE +
                                          ks + b_lcol) * 2;
                ldsm_x4(uBhi + off, bh[p]);
                ldsm_x4(uBlo + off, bl[p]);
            }
#pragma unroll
            for (int mf = 0; mf < 4; mf++) {
#pragma unroll
                for (int nf = 0; nf < 4; nf++) {
                    int p = nf >> 1, q = (nf & 1) * 2;
                    mma16816(acc[mf][nf], ah[mf], bh[p][q], bh[p][q + 1]); // hi*hi
                    mma16816(acc[mf][nf], ah[mf], bl[p][q], bl[p][q + 1]); // hi*lo
                    mma16816(acc[mf][nf], al[mf], bh[p][q], bh[p][q + 1]); // lo*hi
                }
            }
        }
        __syncthreads();
    }

    // ---- epilogue ----
#pragma unroll
    for (int mf = 0; mf < 4; mf++) {
        int r0 = block_row + wm * 64 + mf * 16 + (lane >> 2);
        int r1 = r0 + 8;
#pragma unroll
        for (int nf = 0; nf < 4; nf++) {
            int col = block_col + wn * 32 + nf * 8 + (lane & 3) * 2;
            float b0 = bias[col], b1 = bias[col + 1];
            float v00 = fmaxf(acc[mf][nf][0] + b0, 0.f);
            float v01 = fmaxf(acc[mf][nf][1] + b1, 0.f);
            float v10 = fmaxf(acc[mf][nf][2] + b0, 0.f);
            float v11 = fmaxf(acc[mf][nf][3] + b1, 0.f);
            if (mode == 0) {
                if (r0 < M) {
                    *reinterpret_cast<float2*>(&Cf[(size_t)r0 * HID + col]) =
                        make_float2(v00, v01);
                    if (Cc)
                        *reinterpret_cast<float2*>(&Cc[(size_t)r0 * HID + col]) =
                            make_float2(v00, v01);
                }
                if (r1 < M) {
                    *reinterpret_cast<float2*>(&Cf[(size_t)r1 * HID + col]) =
                        make_float2(v10, v11);
                    if (Cc)
                        *reinterpret_cast<float2*>(&Cc[(size_t)r1 * HID + col]) =
                            make_float2(v10, v11);
                }
            } else {
                __nv_bfloat16 h0 = __float2bfloat16(v00);
                __nv_bfloat16 h1 = __float2bfloat16(v01);
                __nv_bfloat16 h2 = __float2bfloat16(v10);
                __nv_bfloat16 h3 = __float2bfloat16(v11);
                uint32_t hp0 = ((uint32_t)__bfloat16_as_ushort(h1) << 16) |
                               __bfloat16_as_ushort(h0);
                uint32_t hp1 = ((uint32_t)__bfloat16_as_ushort(h3) << 16) |
                               __bfloat16_as_ushort(h2);
                __nv_bfloat16 g0 = __float2bfloat16(v00 - __bfloat162float(h0));
                __nv_bfloat16 g1 = __float2bfloat16(v01 - __bfloat162float(h1));
                __nv_bfloat16 g2 = __float2bfloat16(v10 - __bfloat162float(h2));
                __nv_bfloat16 g3 = __float2bfloat16(v11 - __bfloat162float(h3));
                uint32_t lp0 = ((uint32_t)__bfloat16_as_ushort(g1) << 16) |
                               __bfloat16_as_ushort(g0);
                uint32_t lp1 = ((uint32_t)__bfloat16_as_ushort(g3) << 16) |
                               __bfloat16_as_ushort(g2);
                if (r0 < M) {
                    *reinterpret_cast<uint32_t*>(Chi + (size_t)r0 * HID + col) = hp0;
                    *reinterpret_cast<uint32_t*>(Clo + (size_t)r0 * HID + col) = lp0;
                }
                if (r1 < M) {
                    *reinterpret_cast<uint32_t*>(Chi + (size_t)r1 * HID + col) = hp1;
                    *reinterpret_cast<uint32_t*>(Clo + (size_t)r1 * HID + col) = lp1;
                }
            }
        }
    }
}

// =================== fp32 tiled SGEMM (small head GEMM) =====================

__global__ __launch_bounds__(256)
void sgemm_bias_relu(int M, const float* __restrict__ A,
                     const float* __restrict__ B,
                     const float* __restrict__ bias,
                     float* __restrict__ C,
                     int N, int K, int doRelu) {
    __shared__ float As[8][128];
    __shared__ float Bs[8][128];

    const int tid       = threadIdx.x;
    const int block_row = blockIdx.y * 128;
    const int block_col = blockIdx.x * 128;

    const int aRow = tid >> 1;
    const int aCol = (tid & 1) << 2;
    const int bRow = tid >> 5;
    const int bCol = (tid & 31) << 2;
    const int trow = (tid >> 4) << 3;
    const int tcol = (tid & 15) << 3;

    float acc[8][8];
#pragma unroll
    for (int i = 0; i < 8; i++)
#pragma unroll
        for (int j = 0; j < 8; j++) acc[i][j] = 0.0f;

    for (int kt = 0; kt < K; kt += 8) {
        float4 av = make_float4(0.f, 0.f, 0.f, 0.f);
        if (block_row + aRow < M)
            av = *reinterpret_cast<const float4*>(&A[(size_t)(block_row + aRow) * K + kt + aCol]);
        As[aCol + 0][aRow] = av.x;
        As[aCol + 1][aRow] = av.y;
        As[aCol + 2][aRow] = av.z;
        As[aCol + 3][aRow] = av.w;

        float4 bv = *reinterpret_cast<const float4*>(&B[(size_t)(kt + bRow) * N + block_col + bCol]);
        *reinterpret_cast<float4*>(&Bs[bRow][bCol]) = bv;
        __syncthreads();

#pragma unroll
        for (int k = 0; k < 8; k++) {
            float ra[8], rb[8];
#pragma unroll
            for (int i = 0; i < 8; i++) ra[i] = As[k][trow + i];
#pragma unroll
            for (int j = 0; j < 8; j++) rb[j] = Bs[k][tcol + j];
#pragma unroll
            for (int i = 0; i < 8; i++)
#pragma unroll
                for (int j = 0; j < 8; j++)
                    acc[i][j] = fmaf(ra[i], rb[j], acc[i][j]);
        }
        __syncthreads();
    }

#pragma unroll
    for (int i = 0; i < 8; i++) {
        int r = block_row + trow + i;
        if (r < M) {
#pragma unroll
            for (int j = 0; j < 8; j += 4) {
                float4 v;
                v.x = acc[i][j + 0] + bias[block_col + tcol + j + 0];
                v.y = acc[i][j + 1] + bias[block_col + tcol + j + 1];
                v.z = acc[i][j + 2] + bias[block_col + tcol + j + 2];
                v.w = acc[i][j + 3] + bias[block_col + tcol + j + 3];
                if (doRelu) {
                    v.x = fmaxf(v.x, 0.f); v.y = fmaxf(v.y, 0.f);
                    v.z = fmaxf(v.z, 0.f); v.w = fmaxf(v.w, 0.f);
                }
                *reinterpret_cast<float4*>(&C[(size_t)r * N + block_col + tcol + j]) = v;
            }
        }
    }
}

// ============================ pooling + head ================================

__global__ void pool_kernel(const float* __restrict__ h,
                            const int* __restrict__ batch,
                            float* __restrict__ pooled,
                            float* __restrict__ counts) {
    int node = (blockIdx.x * blockDim.x + threadIdx.x) >> 5;
    int lane = threadIdx.x & 31;
    if (node >= N_NODES) return;
    int b = batch[node];
    const float* hs = h + (size_t)node * HID;
    float* pd = pooled + (size_t)b * HID;
#pragma unroll
    for (int j = 0; j < 8; j++)
        atomicAdd(pd + lane + 32 * j, hs[lane + 32 * j]);
    if (lane == 0) atomicAdd(&counts[b], 1.0f);
}

__global__ void pool_div(float* __restrict__ pooled,
                         const float* __restrict__ counts) {
    int i = blockIdx.x * blockDim.x + threadIdx.x;
    float c = counts[i >> 8];
    pooled[i] = pooled[i] / fmaxf(c, 1.0f);
}

__global__ void head_final(const float* __restrict__ hid,
                           const float* __restrict__ W,
                           const float* __restrict__ b,
                           float* __restrict__ out) {
    int m = blockIdx.x * blockDim.x + threadIdx.x;
    if (m >= N_GRAPHS) return;
    float a0 = b[0], a1 = b[1], a2 = b[2];
    const float* hs = hid + (size_t)m * 128;
#pragma unroll 8
    for (int k = 0; k < 128; k++) {
        float h = hs[k];
        a0 = fmaf(h, W[k * 3 + 0], a0);
        a1 = fmaf(h, W[k * 3 + 1], a1);
        a2 = fmaf(h, W[k * 3 + 2], a2);
    }
    out[m * 3 + 0] = a0;
    out[m * 3 + 1] = a1;
    out[m * 3 + 2] = a2;
}

// ============================ launch ========================================

extern "C" void kernel_launch(void* const* d_in, const int* in_sizes, int n_in,
                              void* d_out, int out_size) {
    const float* x     = (const float*)d_in[0];
    const int*   ei    = (const int*)d_in[1];
    const int*   batch = (const int*)d_in[2];

    const float* Wa[4], *ba[4], *Wb[4], *bb[4];
    for (int l = 0; l < 4; l++) {
        Wa[l] = (const float*)d_in[3 + 4 * l + 0];
        ba[l] = (const float*)d_in[3 + 4 * l + 1];
        Wb[l] = (const float*)d_in[3 + 4 * l + 2];
        bb[l] = (const float*)d_in[3 + 4 * l + 3];
    }
    const float* Wh1 = (const float*)d_in[19];
    const float* bh1 = (const float*)d_in[20];
    const float* Wh2 = (const float*)d_in[21];
    const float* bh2 = (const float*)d_in[22];
    float* out = (float*)d_out;

    __nv_bfloat16 *Ahi, *Alo, *A2hi, *A2lo, *Whi, *Wlo;
    float *bufB, *bufC, *agg7, *pooled, *counts, *hid;
    cudaGetSymbolAddress((void**)&Ahi,    g_Ahi);
    cudaGetSymbolAddress((void**)&Alo,    g_Alo);
    cudaGetSymbolAddress((void**)&A2hi,   g_A2hi);
    cudaGetSymbolAddress((void**)&A2lo,   g_A2lo);
    cudaGetSymbolAddress((void**)&Whi,    g_Whi);
    cudaGetSymbolAddress((void**)&Wlo,    g_Wlo);
    cudaGetSymbolAddress((void**)&bufB,   g_bufB);
    cudaGetSymbolAddress((void**)&bufC,   g_bufC);
    cudaGetSymbolAddress((void**)&agg7,   g_agg7);
    cudaGetSymbolAddress((void**)&pooled, g_pooled);
    cudaGetSymbolAddress((void**)&counts, g_counts);
    cudaGetSymbolAddress((void**)&hid,    g_hid);

    cudaFuncSetAttribute(mma_gemm_split,
                         cudaFuncAttributeMaxDynamicSharedMemorySize, GEMM_SMEM);

    // weight conversion: slots 0=W1b, 1=W2a, 2=W2b, 3=W3a, 4=W3b, 5=W4a, 6=W4b
    dim3 cw_grid(HID, 7);
    convert_weight_all<<<cw_grid, HID>>>(Wb[0], Wa[1], Wb[1], Wa[2], Wb[2],
                                         Wa[3], Wb[3], Whi, Wlo);

    dim3 mma_grid(2, (N_NODES + 127) / 128);
    const int CV_GRID = (N_NODES * HID / 4 + 255) / 256;

    // ---- layer 1 ----
    cudaMemcpyAsync(agg7, x, (size_t)N_NODES * 7 * sizeof(float),
                    cudaMemcpyDeviceToDevice);
    scatter_add_7<<<(N_EDGES + 255) / 256, 256>>>(x, ei, agg7);
    gemm_k7_relu_split<<<N_NODES, 256>>>(agg7, Wa[0], ba[0], A2hi, A2lo);
    mma_gemm_split<<<mma_grid, 256, GEMM_SMEM>>>(
        N_NODES, (const uint4*)A2hi, (const uint4*)A2lo,
        (const uint4*)Whi, (const uint4*)Wlo,
        bb[0], bufB, bufC, nullptr, nullptr, 0);

    // ---- layers 2..4 ----
    for (int l = 1; l < 4; l++) {
        // bufC already holds h (self term); add neighbor terms
        scatter_add_256<<<((size_t)N_EDGES * 32 + 255) / 256, 256>>>(bufB, ei, bufC);
        convert_split<<<CV_GRID, 256>>>((const float4*)bufC,
                                        (uint2*)Ahi, (uint2*)Alo);
        mma_gemm_split<<<mma_grid, 256, GEMM_SMEM>>>(
            N_NODES, (const uint4*)Ahi, (const uint4*)Alo,
            (const uint4*)(Whi + (size_t)(2 * l - 1) * HID * HID),
            (const uint4*)(Wlo + (size_t)(2 * l - 1) * HID * HID),
            ba[l], nullptr, nullptr, A2hi, A2lo, 1);
        mma_gemm_split<<<mma_grid, 256, GEMM_SMEM>>>(
            N_NODES, (const uint4*)A2hi, (const uint4*)A2lo,
            (const uint4*)(Whi + (size_t)(2 * l) * HID * HID),
            (const uint4*)(Wlo + (size_t)(2 * l) * HID * HID),
            bb[l], bufB, (l < 3) ? bufC : nullptr, nullptr, nullptr, 0);
    }

    // ---- mean pool ----
    cudaMemsetAsync(pooled, 0, (size_t)N_GRAPHS * HID * sizeof(float));
    cudaMemsetAsync(counts, 0, (size_t)N_GRAPHS * sizeof(float));
    pool_kernel<<<((size_t)N_NODES * 32 + 255) / 256, 256>>>(bufB, batch,
                                                             pooled, counts);
    pool_div<<<N_GRAPHS * HID / 256, 256>>>(pooled, counts);

    // ---- head ----
    dim3 head_grid(1, (N_GRAPHS + 127) / 128);
    sgemm_bias_relu<<<head_grid, 256>>>(N_GRAPHS, pooled, Wh1, bh1, hid,
                                        128, 256, 1);
    head_final<<<(N_GRAPHS + 255) / 256, 256>>>(hid, Wh2, bh2, out);
}

// round 6
// speedup vs baseline: 2.1023x; 1.0012x over previous
#include <cuda_runtime.h>
#include <cuda_bf16.h>
#include <cstdint>

#define N_NODES  150000
#define N_EDGES  300000
#define N_GRAPHS 6000
#define HID      256

// ============================ mma.sync helpers ==============================

__device__ __forceinline__ uint32_t smem_u32(const void* p) {
    uint32_t addr;
    asm("{ .reg .u64 tmp; cvta.to.shared.u64 tmp, %1; cvt.u32.u64 %0, tmp; }"
        : "=r"(addr) : "l"(p));
    return addr;
}

__device__ __forceinline__ void ldsm_x4(uint32_t addr, uint32_t* r) {
    asm volatile("ldmatrix.sync.aligned.m8n8.x4.shared.b16 {%0,%1,%2,%3}, [%4];"
                 : "=r"(r[0]), "=r"(r[1]), "=r"(r[2]), "=r"(r[3]) : "r"(addr));
}

__device__ __forceinline__ void mma16816(float* d, const uint32_t* a,
                                         uint32_t b0, uint32_t b1) {
    asm volatile(
        "mma.sync.aligned.m16n8k16.row.col.f32.bf16.bf16.f32 "
        "{%0,%1,%2,%3}, {%4,%5,%6,%7}, {%8,%9}, {%0,%1,%2,%3};"
        : "+f"(d[0]), "+f"(d[1]), "+f"(d[2]), "+f"(d[3])
        : "r"(a[0]), "r"(a[1]), "r"(a[2]), "r"(a[3]), "r"(b0), "r"(b1));
}

__device__ __forceinline__ void cp_async16(uint32_t smem_addr, const void* g) {
    asm volatile("cp.async.cg.shared.global [%0], [%1], 16;"
                 :: "r"(smem_addr), "l"(g));
}
#define CP_COMMIT() asm volatile("cp.async.commit_group;" ::: "memory")
#define CP_WAIT(n)  asm volatile("cp.async.wait_group %0;" :: "n"(n) : "memory")

// ============================ scratch buffers ===============================

__device__ __nv_bfloat16 g_Ahi[(size_t)N_NODES * HID];
__device__ __nv_bfloat16 g_Alo[(size_t)N_NODES * HID];
__device__ __nv_bfloat16 g_A2hi[(size_t)N_NODES * HID];
__device__ __nv_bfloat16 g_A2lo[(size_t)N_NODES * HID];
__device__ float g_bufB[(size_t)N_NODES * HID];   // layer output h (gather src)
__device__ float g_bufC[(size_t)N_NODES * HID];   // scatter accumulator (init h)
__device__ float g_agg7[N_NODES * 7];
__device__ __nv_bfloat16 g_Whi[7 * HID * HID];    // weights, [N][K] bf16 hi
__device__ __nv_bfloat16 g_Wlo[7 * HID * HID];    // weights, [N][K] bf16 lo
__device__ float g_pooled[N_GRAPHS * HID];
__device__ float g_counts[N_GRAPHS];
__device__ float g_hid[N_GRAPHS * 128];

// ============================ small kernels =================================

__global__ void convert_weight_all(const float* __restrict__ W0,
                                   const float* __restrict__ W1,
                                   const float* __restrict__ W2,
                                   const float* __restrict__ W3,
                                   const float* __restrict__ W4,
                                   const float* __restrict__ W5,
                                   const float* __restrict__ W6,
                                   __nv_bfloat16* __restrict__ Whi,
                                   __nv_bfloat16* __restrict__ Wlo) {
    int w = blockIdx.y;
    const float* W = (w == 0) ? W0 : (w == 1) ? W1 : (w == 2) ? W2 :
                     (w == 3) ? W3 : (w == 4) ? W4 : (w == 5) ? W5 : W6;
    int n = blockIdx.x;   // 256
    int k = threadIdx.x;  // 256
    float v = W[k * HID + n];
    __nv_bfloat16 h = __float2bfloat16(v);
    size_t o = (size_t)w * HID * HID + n * HID + k;
    Whi[o] = h;
    Wlo[o] = __float2bfloat16(v - __bfloat162float(h));
}

__global__ void convert_split(const float4* __restrict__ in,
                              uint2* __restrict__ hi,
                              uint2* __restrict__ lo) {
    int i = blockIdx.x * blockDim.x + threadIdx.x;  // N_NODES*HID/4
    if (i >= N_NODES * HID / 4) return;
    float4 a = in[i];
    __nv_bfloat16 h0 = __float2bfloat16(a.x), h1 = __float2bfloat16(a.y);
    __nv_bfloat16 h2 = __float2bfloat16(a.z), h3 = __float2bfloat16(a.w);
    __nv_bfloat16 g0 = __float2bfloat16(a.x - __bfloat162float(h0));
    __nv_bfloat16 g1 = __float2bfloat16(a.y - __bfloat162float(h1));
    __nv_bfloat16 g2 = __float2bfloat16(a.z - __bfloat162float(h2));
    __nv_bfloat16 g3 = __float2bfloat16(a.w - __bfloat162float(h3));
    uint2 hp, lp;
    hp.x = ((uint32_t)__bfloat16_as_ushort(h1) << 16) | __bfloat16_as_ushort(h0);
    hp.y = ((uint32_t)__bfloat16_as_ushort(h3) << 16) | __bfloat16_as_ushort(h2);
    lp.x = ((uint32_t)__bfloat16_as_ushort(g1) << 16) | __bfloat16_as_ushort(g0);
    lp.y = ((uint32_t)__bfloat16_as_ushort(g3) << 16) | __bfloat16_as_ushort(g2);
    hi[i] = hp;
    lo[i] = lp;
}

__global__ void scatter_add_7(const float* __restrict__ x,
                              const int* __restrict__ ei,
                              float* __restrict__ agg) {
    int e = blockIdx.x * blockDim.x + threadIdx.x;
    if (e >= N_EDGES) return;
    int s = ei[e];
    int d = ei[N_EDGES + e];
#pragma unroll
    for (int j = 0; j < 7; j++)
        atomicAdd(&agg[(size_t)d * 7 + j], x[(size_t)s * 7 + j]);
}

__global__ void scatter_add_256(const float* __restrict__ x,
                                const int* __restrict__ ei,
                                float* __restrict__ agg) {
    int gw   = (blockIdx.x * blockDim.x + threadIdx.x) >> 5;
    int lane = threadIdx.x & 31;
    if (gw >= N_EDGES) return;
    int s = ei[gw];
    int d = ei[N_EDGES + gw];
    const float* xs = x + (size_t)s * HID;
    float* ad = agg + (size_t)d * HID;
#pragma unroll
    for (int j = 0; j < 8; j++)
        atomicAdd(ad + lane + 32 * j, xs[lane + 32 * j]);
}

__global__ void gemm_k7_relu_split(const float* __restrict__ A,
                                   const float* __restrict__ W,
                                   const float* __restrict__ bias,
                                   __nv_bfloat16* __restrict__ Chi,
                                   __nv_bfloat16* __restrict__ Clo) {
    int m = blockIdx.x;
    int n = threadIdx.x;  // 256
    __shared__ float xs[7];
    if (n < 7) xs[n] = A[(size_t)m * 7 + n];
    __syncthreads();
    float acc = bias[n];
#pragma unroll
    for (int j = 0; j < 7; j++)
        acc = fmaf(xs[j], W[j * HID + n], acc);
    float v = fmaxf(acc, 0.0f);
    __nv_bfloat16 h = __float2bfloat16(v);
    Chi[(size_t)m * HID + n] = h;
    Clo[(size_t)m * HID + n] = __float2bfloat16(v - __bfloat162float(h));
}

// =================== bf16x3-split GEMM via mma.sync + cp.async ==============
// Interleaved term scheduling: LDSM groups covered by in-flight HMMA blocks.

#define ASTRIDE 40                     // bf16 per smem row (80B, 16B-aligned)
#define TILE_B  (128 * ASTRIDE * 2)    // 10240 bytes per tile
#define STAGE_B (4 * TILE_B)           // 40960 bytes per stage
#define GEMM_SMEM (2 * STAGE_B)        // 81920 bytes

__global__ __launch_bounds__(256, 2)
void mma_gemm_split(int M,
                    const uint4* __restrict__ Ahi4, const uint4* __restrict__ Alo4,
                    const uint4* __restrict__ Bhi4, const uint4* __restrict__ Blo4,
                    const float* __restrict__ bias,
                    float* __restrict__ Cf, float* __restrict__ Cc,
                    __nv_bfloat16* __restrict__ Chi,
                    __nv_bfloat16* __restrict__ Clo,
                    int mode) {
    extern __shared__ char smem[];
    const uint32_t sb = smem_u32(smem);

    const int tid  = threadIdx.x;
    const int wid  = tid >> 5;
    const int lane = tid & 31;
    const int wm   = wid & 1;        // M half (64 rows)
    const int wn   = wid >> 1;       // N quarter (32 cols)
    const int block_col = blockIdx.x * 128;
    const int block_row = blockIdx.y * 128;

    // ldmatrix lane addressing
    const int a_lrow = lane & 15;
    const int a_lcol = (lane >> 4) << 3;
    const int b_lrow = (lane & 7) + ((lane >> 4) & 1) * 8;
    const int b_lcol = ((lane >> 3) & 1) << 3;

    float acc[4][4][4];
#pragma unroll
    for (int i = 0; i < 4; i++)
#pragma unroll
        for (int j = 0; j < 4; j++)
#pragma unroll
            for (int c = 0; c < 4; c++) acc[i][j][c] = 0.0f;

    const int ldrow = tid >> 2;        // 0..63
    const int ldc   = tid & 3;         // 0..3

    auto issue = [&](int kc) {
        uint32_t sbase = sb + (uint32_t)(kc & 1) * STAGE_B;
#pragma unroll
        for (int h = 0; h < 2; h++) {
            int row = ldrow + h * 64;
            int rg = block_row + row;
            if (rg >= M) rg = M - 1;
            size_t gA = (size_t)rg * 32 + kc * 4 + ldc;
            size_t gB = (size_t)(block_col + row) * 32 + kc * 4 + ldc;
            uint32_t so = (uint32_t)(row * ASTRIDE + ldc * 8) * 2;
            cp_async16(sbase + 0 * TILE_B + so, Ahi4 + gA);
            cp_async16(sbase + 1 * TILE_B + so, Alo4 + gA);
            cp_async16(sbase + 2 * TILE_B + so, Bhi4 + gB);
            cp_async16(sbase + 3 * TILE_B + so, Blo4 + gB);
        }
        CP_COMMIT();
    };

    issue(0);

    // smem offsets for this warp's frags
    const uint32_t a_base = (uint32_t)((wm * 64 + a_lrow) * ASTRIDE + a_lcol) * 2;
    const uint32_t b_base = (uint32_t)((wn * 32 + b_lrow) * ASTRIDE + b_lcol) * 2;

    for (int kc = 0; kc < 8; kc++) {
        if (kc < 7) { issue(kc + 1); CP_WAIT(1); }
        else        { CP_WAIT(0); }
        __syncthreads();

        uint32_t base = sb + (uint32_t)(kc & 1) * STAGE_B;
        uint32_t uAhi = base + 0 * TILE_B;
        uint32_t uAlo = base + 1 * TILE_B;
        uint32_t uBhi = base + 2 * TILE_B;
        uint32_t uBlo = base + 3 * TILE_B;

        uint32_t ah[4][4], al[4][4], bh[2][4], bl[2][4];

        // preload hi frags for ks=0
#pragma unroll
        for (int f = 0; f < 4; f++)
            ldsm_x4(uAhi + a_base + (uint32_t)(f * 16 * ASTRIDE) * 2, ah[f]);
#pragma unroll
        for (int p = 0; p < 2; p++)
            ldsm_x4(uBhi + b_base + (uint32_t)(p * 16 * ASTRIDE) * 2, bh[p]);

#pragma unroll
        for (int ks16 = 0; ks16 < 2; ks16++) {
            const uint32_t ko = (uint32_t)(ks16 * 16) * 2;
            // load lo frags for this kstep
#pragma unroll
            for (int p = 0; p < 2; p++)
                ldsm_x4(uBlo + b_base + (uint32_t)(p * 16 * ASTRIDE) * 2 + ko, bl[p]);
#pragma unroll
            for (int f = 0; f < 4; f++)
                ldsm_x4(uAlo + a_base + (uint32_t)(f * 16 * ASTRIDE) * 2 + ko, al[f]);

            // hi*hi  (covers bl/al LDSM latency)
#pragma unroll
            for (int mf = 0; mf < 4; mf++)
#pragma unroll
                for (int nf = 0; nf < 4; nf++) {
                    int p = nf >> 1, q = (nf & 1) * 2;
                    mma16816(acc[mf][nf], ah[mf], bh[p][q], bh[p][q + 1]);
                }
            // hi*lo
#pragma unroll
            for (int mf = 0; mf < 4; mf++)
#pragma unroll
                for (int nf = 0; nf < 4; nf++) {
                    int p = nf >> 1, q = (nf & 1) * 2;
                    mma16816(acc[mf][nf], ah[mf], bl[p][q], bl[p][q + 1]);
                }
            // prefetch ah for next kstep (ah now dead); covered by lo*hi below
            if (ks16 == 0) {
#pragma unroll
                for (int f = 0; f < 4; f++)
                    ldsm_x4(uAhi + a_base + (uint32_t)(f * 16 * ASTRIDE) * 2 + 32,
                            ah[f]);
            }
            // lo*hi
#pragma unroll
            for (int mf = 0; mf < 4; mf++)
#pragma unroll
                for (int nf = 0; nf < 4; nf++) {
                    int p = nf >> 1, q = (nf & 1) * 2;
                    mma16816(acc[mf][nf], al[mf], bh[p][q], bh[p][q + 1]);
                }
            // prefetch bh for next kstep (bh now dead)
            if (ks16 == 0) {
#pragma unroll
                for (int p = 0; p < 2; p++)
                    ldsm_x4(uBhi + b_base + (uint32_t)(p * 16 * ASTRIDE) * 2 + 32,
                            bh[p]);
            }
        }
        __syncthreads();
    }

    // ---- epilogue ----
#pragma unroll
    for (int mf = 0; mf < 4; mf++) {
        int r0 = block_row + wm * 64 + mf * 16 + (lane >> 2);
        int r1 = r0 + 8;
#pragma unroll
        for (int nf = 0; nf < 4; nf++) {
            int col = block_col + wn * 32 + nf * 8 + (lane & 3) * 2;
            float b0 = bias[col], b1 = bias[col + 1];
            float v00 = fmaxf(acc[mf][nf][0] + b0, 0.f);
            float v01 = fmaxf(acc[mf][nf][1] + b1, 0.f);
            float v10 = fmaxf(acc[mf][nf][2] + b0, 0.f);
            float v11 = fmaxf(acc[mf][nf][3] + b1, 0.f);
            if (mode == 0) {
                if (r0 < M) {
                    *reinterpret_cast<float2*>(&Cf[(size_t)r0 * HID + col]) =
                        make_float2(v00, v01);
                    if (Cc)
                        *reinterpret_cast<float2*>(&Cc[(size_t)r0 * HID + col]) =
                            make_float2(v00, v01);
                }
                if (r1 < M) {
                    *reinterpret_cast<float2*>(&Cf[(size_t)r1 * HID + col]) =
                        make_float2(v10, v11);
                    if (Cc)
                        *reinterpret_cast<float2*>(&Cc[(size_t)r1 * HID + col]) =
                            make_float2(v10, v11);
                }
            } else {
                __nv_bfloat16 h0 = __float2bfloat16(v00);
                __nv_bfloat16 h1 = __float2bfloat16(v01);
                __nv_bfloat16 h2 = __float2bfloat16(v10);
                __nv_bfloat16 h3 = __float2bfloat16(v11);
                uint32_t hp0 = ((uint32_t)__bfloat16_as_ushort(h1) << 16) |
                               __bfloat16_as_ushort(h0);
                uint32_t hp1 = ((uint32_t)__bfloat16_as_ushort(h3) << 16) |
                               __bfloat16_as_ushort(h2);
                __nv_bfloat16 g0 = __float2bfloat16(v00 - __bfloat162float(h0));
                __nv_bfloat16 g1 = __float2bfloat16(v01 - __bfloat162float(h1));
                __nv_bfloat16 g2 = __float2bfloat16(v10 - __bfloat162float(h2));
                __nv_bfloat16 g3 = __float2bfloat16(v11 - __bfloat162float(h3));
                uint32_t lp0 = ((uint32_t)__bfloat16_as_ushort(g1) << 16) |
                               __bfloat16_as_ushort(g0);
                uint32_t lp1 = ((uint32_t)__bfloat16_as_ushort(g3) << 16) |
                               __bfloat16_as_ushort(g2);
                if (r0 < M) {
                    *reinterpret_cast<uint32_t*>(Chi + (size_t)r0 * HID + col) = hp0;
                    *reinterpret_cast<uint32_t*>(Clo + (size_t)r0 * HID + col) = lp0;
                }
                if (r1 < M) {
                    *reinterpret_cast<uint32_t*>(Chi + (size_t)r1 * HID + col) = hp1;
                    *reinterpret_cast<uint32_t*>(Clo + (size_t)r1 * HID + col) = lp1;
                }
            }
        }
    }
}

// =================== fp32 tiled SGEMM (small head GEMM) =====================

__global__ __launch_bounds__(256)
void sgemm_bias_relu(int M, const float* __restrict__ A,
                     const float* __restrict__ B,
                     const float* __restrict__ bias,
                     float* __restrict__ C,
                     int N, int K, int doRelu) {
    __shared__ float As[8][128];
    __shared__ float Bs[8][128];

    const int tid       = threadIdx.x;
    const int block_row = blockIdx.y * 128;
    const int block_col = blockIdx.x * 128;

    const int aRow = tid >> 1;
    const int aCol = (tid & 1) << 2;
    const int bRow = tid >> 5;
    const int bCol = (tid & 31) << 2;
    const int trow = (tid >> 4) << 3;
    const int tcol = (tid & 15) << 3;

    float acc[8][8];
#pragma unroll
    for (int i = 0; i < 8; i++)
#pragma unroll
        for (int j = 0; j < 8; j++) acc[i][j] = 0.0f;

    for (int kt = 0; kt < K; kt += 8) {
        float4 av = make_float4(0.f, 0.f, 0.f, 0.f);
        if (block_row + aRow < M)
            av = *reinterpret_cast<const float4*>(&A[(size_t)(block_row + aRow) * K + kt + aCol]);
        As[aCol + 0][aRow] = av.x;
        As[aCol + 1][aRow] = av.y;
        As[aCol + 2][aRow] = av.z;
        As[aCol + 3][aRow] = av.w;

        float4 bv = *reinterpret_cast<const float4*>(&B[(size_t)(kt + bRow) * N + block_col + bCol]);
        *reinterpret_cast<float4*>(&Bs[bRow][bCol]) = bv;
        __syncthreads();

#pragma unroll
        for (int k = 0; k < 8; k++) {
            float ra[8], rb[8];
#pragma unroll
            for (int i = 0; i < 8; i++) ra[i] = As[k][trow + i];
#pragma unroll
            for (int j = 0; j < 8; j++) rb[j] = Bs[k][tcol + j];
#pragma unroll
            for (int i = 0; i < 8; i++)
#pragma unroll
                for (int j = 0; j < 8; j++)
                    acc[i][j] = fmaf(ra[i], rb[j], acc[i][j]);
        }
        __syncthreads();
    }

#pragma unroll
    for (int i = 0; i < 8; i++) {
        int r = block_row + trow + i;
        if (r < M) {
#pragma unroll
            for (int j = 0; j < 8; j += 4) {
                float4 v;
                v.x = acc[i][j + 0] + bias[block_col + tcol + j + 0];
                v.y = acc[i][j + 1] + bias[block_col + tcol + j + 1];
                v.z = acc[i][j + 2] + bias[block_col + tcol + j + 2];
                v.w = acc[i][j + 3] + bias[block_col + tcol + j + 3];
                if (doRelu) {
                    v.x = fmaxf(v.x, 0.f); v.y = fmaxf(v.y, 0.f);
                    v.z = fmaxf(v.z, 0.f); v.w = fmaxf(v.w, 0.f);
                }
                *reinterpret_cast<float4*>(&C[(size_t)r * N + block_col + tcol + j]) = v;
            }
        }
    }
}

// ============================ pooling + head ================================

__global__ void pool_kernel(const float* __restrict__ h,
                            const int* __restrict__ batch,
                            float* __restrict__ pooled,
                            float* __restrict__ counts) {
    int node = (blockIdx.x * blockDim.x + threadIdx.x) >> 5;
    int lane = threadIdx.x & 31;
    if (node >= N_NODES) return;
    int b = batch[node];
    const float* hs = h + (size_t)node * HID;
    float* pd = pooled + (size_t)b * HID;
#pragma unroll
    for (int j = 0; j < 8; j++)
        atomicAdd(pd + lane + 32 * j, hs[lane + 32 * j]);
    if (lane == 0) atomicAdd(&counts[b], 1.0f);
}

__global__ void pool_div(float* __restrict__ pooled,
                         const float* __restrict__ counts) {
    int i = blockIdx.x * blockDim.x + threadIdx.x;
    float c = counts[i >> 8];
    pooled[i] = pooled[i] / fmaxf(c, 1.0f);
}

__global__ void head_final(const float* __restrict__ hid,
                           const float* __restrict__ W,
                           const float* __restrict__ b,
                           float* __restrict__ out) {
    int m = blockIdx.x * blockDim.x + threadIdx.x;
    if (m >= N_GRAPHS) return;
    float a0 = b[0], a1 = b[1], a2 = b[2];
    const float* hs = hid + (size_t)m * 128;
#pragma unroll 8
    for (int k = 0; k < 128; k++) {
        float h = hs[k];
        a0 = fmaf(h, W[k * 3 + 0], a0);
        a1 = fmaf(h, W[k * 3 + 1], a1);
        a2 = fmaf(h, W[k * 3 + 2], a2);
    }
    out[m * 3 + 0] = a0;
    out[m * 3 + 1] = a1;
    out[m * 3 + 2] = a2;
}

// ============================ launch ========================================

extern "C" void kernel_launch(void* const* d_in, const int* in_sizes, int n_in,
                              void* d_out, int out_size) {
    const float* x     = (const float*)d_in[0];
    const int*   ei    = (const int*)d_in[1];
    const int*   batch = (const int*)d_in[2];

    const float* Wa[4], *ba[4], *Wb[4], *bb[4];
    for (int l = 0; l < 4; l++) {
        Wa[l] = (const float*)d_in[3 + 4 * l + 0];
        ba[l] = (const float*)d_in[3 + 4 * l + 1];
        Wb[l] = (const float*)d_in[3 + 4 * l + 2];
        bb[l] = (const float*)d_in[3 + 4 * l + 3];
    }
    const float* Wh1 = (const float*)d_in[19];
    const float* bh1 = (const float*)d_in[20];
    const float* Wh2 = (const float*)d_in[21];
    const float* bh2 = (const float*)d_in[22];
    float* out = (float*)d_out;

    __nv_bfloat16 *Ahi, *Alo, *A2hi, *A2lo, *Whi, *Wlo;
    float *bufB, *bufC, *agg7, *pooled, *counts, *hid;
    cudaGetSymbolAddress((void**)&Ahi,    g_Ahi);
    cudaGetSymbolAddress((void**)&Alo,    g_Alo);
    cudaGetSymbolAddress((void**)&A2hi,   g_A2hi);
    cudaGetSymbolAddress((void**)&A2lo,   g_A2lo);
    cudaGetSymbolAddress((void**)&Whi,    g_Whi);
    cudaGetSymbolAddress((void**)&Wlo,    g_Wlo);
    cudaGetSymbolAddress((void**)&bufB,   g_bufB);
    cudaGetSymbolAddress((void**)&bufC,   g_bufC);
    cudaGetSymbolAddress((void**)&agg7,   g_agg7);
    cudaGetSymbolAddress((void**)&pooled, g_pooled);
    cudaGetSymbolAddress((void**)&counts, g_counts);
    cudaGetSymbolAddress((void**)&hid,    g_hid);

    cudaFuncSetAttribute(mma_gemm_split,
                         cudaFuncAttributeMaxDynamicSharedMemorySize, GEMM_SMEM);

    // weight conversion: slots 0=W1b, 1=W2a, 2=W2b, 3=W3a, 4=W3b, 5=W4a, 6=W4b
    dim3 cw_grid(HID, 7);
    convert_weight_all<<<cw_grid, HID>>>(Wb[0], Wa[1], Wb[1], Wa[2], Wb[2],
                                         Wa[3], Wb[3], Whi, Wlo);

    dim3 mma_grid(2, (N_NODES + 127) / 128);
    const int CV_GRID = (N_NODES * HID / 4 + 255) / 256;

    // ---- layer 1 ----
    cudaMemcpyAsync(agg7, x, (size_t)N_NODES * 7 * sizeof(float),
                    cudaMemcpyDeviceToDevice);
    scatter_add_7<<<(N_EDGES + 255) / 256, 256>>>(x, ei, agg7);
    gemm_k7_relu_split<<<N_NODES, 256>>>(agg7, Wa[0], ba[0], A2hi, A2lo);
    mma_gemm_split<<<mma_grid, 256, GEMM_SMEM>>>(
        N_NODES, (const uint4*)A2hi, (const uint4*)A2lo,
        (const uint4*)Whi, (const uint4*)Wlo,
        bb[0], bufB, bufC, nullptr, nullptr, 0);

    // ---- layers 2..4 ----
    for (int l = 1; l < 4; l++) {
        // bufC already holds h (self term); add neighbor terms
        scatter_add_256<<<((size_t)N_EDGES * 32 + 255) / 256, 256>>>(bufB, ei, bufC);
        convert_split<<<CV_GRID, 256>>>((const float4*)bufC,
                                        (uint2*)Ahi, (uint2*)Alo);
        mma_gemm_split<<<mma_grid, 256, GEMM_SMEM>>>(
            N_NODES, (const uint4*)Ahi, (const uint4*)Alo,
            (const uint4*)(Whi + (size_t)(2 * l - 1) * HID * HID),
            (const uint4*)(Wlo + (size_t)(2 * l - 1) * HID * HID),
            ba[l], nullptr, nullptr, A2hi, A2lo, 1);
        mma_gemm_split<<<mma_grid, 256, GEMM_SMEM>>>(
            N_NODES, (const uint4*)A2hi, (const uint4*)A2lo,
            (const uint4*)(Whi + (size_t)(2 * l) * HID * HID),
            (const uint4*)(Wlo + (size_t)(2 * l) * HID * HID),
            bb[l], bufB, (l < 3) ? bufC : nullptr, nullptr, nullptr, 0);
    }

    // ---- mean pool ----
    cudaMemsetAsync(pooled, 0, (size_t)N_GRAPHS * HID * sizeof(float));
    cudaMemsetAsync(counts, 0, (size_t)N_GRAPHS * sizeof(float));
    pool_kernel<<<((size_t)N_NODES * 32 + 255) / 256, 256>>>(bufB, batch,
                                                             pooled, counts);
    pool_div<<<N_GRAPHS * HID / 256, 256>>>(pooled, counts);

    // ---- head ----
    dim3 head_grid(1, (N_GRAPHS + 127) / 128);
    sgemm_bias_relu<<<head_grid, 256>>>(N_GRAPHS, pooled, Wh1, bh1, hid,
                                        128, 256, 1);
    head_final<<<(N_GRAPHS + 255) / 256, 256>>>(hid, Wh2, bh2, out);
}

// round 7
// speedup vs baseline: 2.2707x; 1.0801x over previous
#include <cuda_runtime.h>
#include <cuda_bf16.h>
#include <cstdint>

#define N_NODES  150000
#define N_EDGES  300000
#define N_GRAPHS 6000
#define HID      256

// ============================ mma.sync helpers ==============================

__device__ __forceinline__ uint32_t smem_u32(const void* p) {
    uint32_t addr;
    asm("{ .reg .u64 tmp; cvta.to.shared.u64 tmp, %1; cvt.u32.u64 %0, tmp; }"
        : "=r"(addr) : "l"(p));
    return addr;
}

__device__ __forceinline__ void ldsm_x4(uint32_t addr, uint32_t* r) {
    asm volatile("ldmatrix.sync.aligned.m8n8.x4.shared.b16 {%0,%1,%2,%3}, [%4];"
                 : "=r"(r[0]), "=r"(r[1]), "=r"(r[2]), "=r"(r[3]) : "r"(addr));
}

__device__ __forceinline__ void mma16816(float* d, const uint32_t* a,
                                         uint32_t b0, uint32_t b1) {
    asm volatile(
        "mma.sync.aligned.m16n8k16.row.col.f32.bf16.bf16.f32 "
        "{%0,%1,%2,%3}, {%4,%5,%6,%7}, {%8,%9}, {%0,%1,%2,%3};"
        : "+f"(d[0]), "+f"(d[1]), "+f"(d[2]), "+f"(d[3])
        : "r"(a[0]), "r"(a[1]), "r"(a[2]), "r"(a[3]), "r"(b0), "r"(b1));
}

__device__ __forceinline__ void cp_async16(uint32_t smem_addr, const void* g) {
    asm volatile("cp.async.cg.shared.global [%0], [%1], 16;"
                 :: "r"(smem_addr), "l"(g));
}
#define CP_COMMIT() asm volatile("cp.async.commit_group;" ::: "memory")
#define CP_WAIT(n)  asm volatile("cp.async.wait_group %0;" :: "n"(n) : "memory")

__device__ __forceinline__ uint32_t pack_bf16x2(float a, float b) {
    __nv_bfloat16 ha = __float2bfloat16(a);
    __nv_bfloat16 hb = __float2bfloat16(b);
    return ((uint32_t)__bfloat16_as_ushort(hb) << 16) | __bfloat16_as_ushort(ha);
}

// ============================ scratch buffers ===============================

__device__ __nv_bfloat16 g_A2hi[(size_t)N_NODES * HID];
__device__ __nv_bfloat16 g_A2lo[(size_t)N_NODES * HID];
__device__ float g_bufB[(size_t)N_NODES * HID];   // layer output h (gather src)
__device__ float g_bufC[(size_t)N_NODES * HID];   // scatter accumulator (init h)
__device__ float g_agg7[N_NODES * 7];
__device__ __nv_bfloat16 g_Whi[7 * HID * HID];    // weights, [N][K] bf16 hi
__device__ __nv_bfloat16 g_Wlo[7 * HID * HID];    // weights, [N][K] bf16 lo
__device__ float g_pooled[N_GRAPHS * HID];
__device__ float g_counts[N_GRAPHS];
__device__ float g_hid[N_GRAPHS * 128];

// ============================ small kernels =================================

__global__ void convert_weight_all(const float* __restrict__ W0,
                                   const float* __restrict__ W1,
                                   const float* __restrict__ W2,
                                   const float* __restrict__ W3,
                                   const float* __restrict__ W4,
                                   const float* __restrict__ W5,
                                   const float* __restrict__ W6,
                                   __nv_bfloat16* __restrict__ Whi,
                                   __nv_bfloat16* __restrict__ Wlo) {
    int w = blockIdx.y;
    const float* W = (w == 0) ? W0 : (w == 1) ? W1 : (w == 2) ? W2 :
                     (w == 3) ? W3 : (w == 4) ? W4 : (w == 5) ? W5 : W6;
    int n = blockIdx.x;   // 256
    int k = threadIdx.x;  // 256
    float v = W[k * HID + n];
    __nv_bfloat16 h = __float2bfloat16(v);
    size_t o = (size_t)w * HID * HID + n * HID + k;
    Whi[o] = h;
    Wlo[o] = __float2bfloat16(v - __bfloat162float(h));
}

__global__ void scatter_add_7(const float* __restrict__ x,
                              const int* __restrict__ ei,
                              float* __restrict__ agg) {
    int e = blockIdx.x * blockDim.x + threadIdx.x;
    if (e >= N_EDGES) return;
    int s = ei[e];
    int d = ei[N_EDGES + e];
#pragma unroll
    for (int j = 0; j < 7; j++)
        atomicAdd(&agg[(size_t)d * 7 + j], x[(size_t)s * 7 + j]);
}

__global__ void scatter_add_256(const float* __restrict__ x,
                                const int* __restrict__ ei,
                                float* __restrict__ agg) {
    int gw   = (blockIdx.x * blockDim.x + threadIdx.x) >> 5;
    int lane = threadIdx.x & 31;
    if (gw >= N_EDGES) return;
    int s = ei[gw];
    int d = ei[N_EDGES + gw];
    const float* xs = x + (size_t)s * HID;
    float* ad = agg + (size_t)d * HID;
#pragma unroll
    for (int j = 0; j < 8; j++)
        atomicAdd(ad + lane + 32 * j, xs[lane + 32 * j]);
}

__global__ void gemm_k7_relu_split(const float* __restrict__ A,
                                   const float* __restrict__ W,
                                   const float* __restrict__ bias,
                                   __nv_bfloat16* __restrict__ Chi,
                                   __nv_bfloat16* __restrict__ Clo) {
    int m = blockIdx.x;
    int n = threadIdx.x;  // 256
    __shared__ float xs[7];
    if (n < 7) xs[n] = A[(size_t)m * 7 + n];
    __syncthreads();
    float acc = bias[n];
#pragma unroll
    for (int j = 0; j < 7; j++)
        acc = fmaf(xs[j], W[j * HID + n], acc);
    float v = fmaxf(acc, 0.0f);
    __nv_bfloat16 h = __float2bfloat16(v);
    Chi[(size_t)m * HID + n] = h;
    Clo[(size_t)m * HID + n] = __float2bfloat16(v - __bfloat162float(h));
}

// =================== shared GEMM compute macros =============================

#define ASTRIDE 40                     // bf16 per smem row (80B, 16B-aligned)
#define TILE_B  (128 * ASTRIDE * 2)    // 10240 bytes per tile

// mainloop compute on tiles (uAhi,uAlo,uBhi,uBlo) for one 32-wide K chunk
#define GEMM_CHUNK_COMPUTE()                                                   \
    do {                                                                       \
        uint32_t ah[4][4], al[4][4], bh[2][4], bl[2][4];                       \
        _Pragma("unroll")                                                      \
        for (int ks16 = 0; ks16 < 2; ks16++) {                                 \
            const uint32_t ko = (uint32_t)(ks16 * 16) * 2;                     \
            _Pragma("unroll")                                                  \
            for (int f = 0; f < 4; f++) {                                      \
                uint32_t off = a_base + (uint32_t)(f * 16 * ASTRIDE) * 2 + ko; \
                ldsm_x4(uAhi + off, ah[f]);                                    \
                ldsm_x4(uAlo + off, al[f]);                                    \
            }                                                                  \
            _Pragma("unroll")                                                  \
            for (int p = 0; p < 2; p++) {                                      \
                uint32_t off = b_base + (uint32_t)(p * 16 * ASTRIDE) * 2 + ko; \
                ldsm_x4(uBhi + off, bh[p]);                                    \
                ldsm_x4(uBlo + off, bl[p]);                                    \
            }                                                                  \
            _Pragma("unroll")                                                  \
            for (int mf = 0; mf < 4; mf++)                                     \
                _Pragma("unroll")                                              \
                for (int nf = 0; nf < 4; nf++) {                               \
                    int p = nf >> 1, q = (nf & 1) * 2;                         \
                    mma16816(acc[mf][nf], ah[mf], bh[p][q], bh[p][q + 1]);     \
                    mma16816(acc[mf][nf], ah[mf], bl[p][q], bl[p][q + 1]);     \
                    mma16816(acc[mf][nf], al[mf], bh[p][q], bh[p][q + 1]);     \
                }                                                              \
        }                                                                      \
    } while (0)

// =================== GEMM variant 1: bf16 A (modes 0/1) =====================
// mode 0: Cf (+Cc) fp32 out.  mode 1: Chi/Clo bf16 split out.

#define STAGE_B (4 * TILE_B)           // 40960 bytes per stage
#define GEMM_SMEM (2 * STAGE_B)        // 81920 bytes

__global__ __launch_bounds__(256, 2)
void mma_gemm_split(int M,
                    const uint4* __restrict__ Ahi4, const uint4* __restrict__ Alo4,
                    const uint4* __restrict__ Bhi4, const uint4* __restrict__ Blo4,
                    const float* __restrict__ bias,
                    float* __restrict__ Cf, float* __restrict__ Cc,
                    __nv_bfloat16* __restrict__ Chi,
                    __nv_bfloat16* __restrict__ Clo,
                    int mode) {
    extern __shared__ char smem[];
    const uint32_t sb = smem_u32(smem);

    const int tid  = threadIdx.x;
    const int wid  = tid >> 5;
    const int lane = tid & 31;
    const int wm   = wid & 1;
    const int wn   = wid >> 1;
    const int block_col = blockIdx.x * 128;
    const int block_row = blockIdx.y * 128;

    const int a_lrow = lane & 15;
    const int a_lcol = (lane >> 4) << 3;
    const int b_lrow = (lane & 7) + ((lane >> 4) & 1) * 8;
    const int b_lcol = ((lane >> 3) & 1) << 3;
    const uint32_t a_base = (uint32_t)((wm * 64 + a_lrow) * ASTRIDE + a_lcol) * 2;
    const uint32_t b_base = (uint32_t)((wn * 32 + b_lrow) * ASTRIDE + b_lcol) * 2;

    float acc[4][4][4];
#pragma unroll
    for (int i = 0; i < 4; i++)
#pragma unroll
        for (int j = 0; j < 4; j++)
#pragma unroll
            for (int c = 0; c < 4; c++) acc[i][j][c] = 0.0f;

    const int ldrow = tid >> 2;
    const int ldc   = tid & 3;

    auto issue = [&](int kc) {
        uint32_t sbase = sb + (uint32_t)(kc & 1) * STAGE_B;
#pragma unroll
        for (int h = 0; h < 2; h++) {
            int row = ldrow + h * 64;
            int rg = block_row + row;
            if (rg >= M) rg = M - 1;
            size_t gA = (size_t)rg * 32 + kc * 4 + ldc;
            size_t gB = (size_t)(block_col + row) * 32 + kc * 4 + ldc;
            uint32_t so = (uint32_t)(row * ASTRIDE + ldc * 8) * 2;
            cp_async16(sbase + 0 * TILE_B + so, Ahi4 + gA);
            cp_async16(sbase + 1 * TILE_B + so, Alo4 + gA);
            cp_async16(sbase + 2 * TILE_B + so, Bhi4 + gB);
            cp_async16(sbase + 3 * TILE_B + so, Blo4 + gB);
        }
        CP_COMMIT();
    };

    issue(0);

    for (int kc = 0; kc < 8; kc++) {
        CP_WAIT(0);
        __syncthreads();
        if (kc < 7) issue(kc + 1);

        uint32_t base = sb + (uint32_t)(kc & 1) * STAGE_B;
        uint32_t uAhi = base + 0 * TILE_B;
        uint32_t uAlo = base + 1 * TILE_B;
        uint32_t uBhi = base + 2 * TILE_B;
        uint32_t uBlo = base + 3 * TILE_B;
        GEMM_CHUNK_COMPUTE();
    }

    // ---- epilogue ----
#pragma unroll
    for (int mf = 0; mf < 4; mf++) {
        int r0 = block_row + wm * 64 + mf * 16 + (lane >> 2);
        int r1 = r0 + 8;
#pragma unroll
        for (int nf = 0; nf < 4; nf++) {
            int col = block_col + wn * 32 + nf * 8 + (lane & 3) * 2;
            float b0 = bias[col], b1 = bias[col + 1];
            float v00 = fmaxf(acc[mf][nf][0] + b0, 0.f);
            float v01 = fmaxf(acc[mf][nf][1] + b1, 0.f);
            float v10 = fmaxf(acc[mf][nf][2] + b0, 0.f);
            float v11 = fmaxf(acc[mf][nf][3] + b1, 0.f);
            if (mode == 0) {
                if (r0 < M) {
                    *reinterpret_cast<float2*>(&Cf[(size_t)r0 * HID + col]) =
                        make_float2(v00, v01);
                    if (Cc)
                        *reinterpret_cast<float2*>(&Cc[(size_t)r0 * HID + col]) =
                            make_float2(v00, v01);
                }
                if (r1 < M) {
                    *reinterpret_cast<float2*>(&Cf[(size_t)r1 * HID + col]) =
                        make_float2(v10, v11);
                    if (Cc)
                        *reinterpret_cast<float2*>(&Cc[(size_t)r1 * HID + col]) =
                            make_float2(v10, v11);
                }
            } else {
                uint32_t hp0 = pack_bf16x2(v00, v01);
                uint32_t hp1 = pack_bf16x2(v10, v11);
                float w00 = v00 - __bfloat162float(__float2bfloat16(v00));
                float w01 = v01 - __bfloat162float(__float2bfloat16(v01));
                float w10 = v10 - __bfloat162float(__float2bfloat16(v10));
                float w11 = v11 - __bfloat162float(__float2bfloat16(v11));
                uint32_t lp0 = pack_bf16x2(w00, w01);
                uint32_t lp1 = pack_bf16x2(w10, w11);
                if (r0 < M) {
                    *reinterpret_cast<uint32_t*>(Chi + (size_t)r0 * HID + col) = hp0;
                    *reinterpret_cast<uint32_t*>(Clo + (size_t)r0 * HID + col) = lp0;
                }
                if (r1 < M) {
                    *reinterpret_cast<uint32_t*>(Chi + (size_t)r1 * HID + col) = hp1;
                    *reinterpret_cast<uint32_t*>(Clo + (size_t)r1 * HID + col) = lp1;
                }
            }
        }
    }
}

// =================== GEMM variant 2: fp32 A, in-kernel split ================
// A is fp32 [M][256]; split into bf16 hi/lo tiles in smem. Output: bf16 split.

#define F_AF32_SZ (128 * 144)              // fp32 A stage: 144B/row padded
#define F_B       (2 * F_AF32_SZ)          // 36864
#define F_BSTG    (2 * TILE_B)             // 20480
#define F_AHI     (F_B + 2 * F_BSTG)       // 77824
#define F_ALO     (F_AHI + TILE_B)         // 88064
#define F_SMEM    (F_ALO + TILE_B)         // 98304

__global__ __launch_bounds__(256, 2)
void mma_gemm_split_f32a(int M,
                         const float* __restrict__ Af,
                         const uint4* __restrict__ Bhi4,
                         const uint4* __restrict__ Blo4,
                         const float* __restrict__ bias,
                         __nv_bfloat16* __restrict__ Chi,
                         __nv_bfloat16* __restrict__ Clo) {
    extern __shared__ char smem[];
    const uint32_t sb = smem_u32(smem);

    const int tid  = threadIdx.x;
    const int wid  = tid >> 5;
    const int lane = tid & 31;
    const int wm   = wid & 1;
    const int wn   = wid >> 1;
    const int block_col = blockIdx.x * 128;
    const int block_row = blockIdx.y * 128;

    const int a_lrow = lane & 15;
    const int a_lcol = (lane >> 4) << 3;
    const int b_lrow = (lane & 7) + ((lane >> 4) & 1) * 8;
    const int b_lcol = ((lane >> 3) & 1) << 3;
    const uint32_t a_base = (uint32_t)((wm * 64 + a_lrow) * ASTRIDE + a_lcol) * 2;
    const uint32_t b_base = (uint32_t)((wn * 32 + b_lrow) * ASTRIDE + b_lcol) * 2;

    float acc[4][4][4];
#pragma unroll
    for (int i = 0; i < 4; i++)
#pragma unroll
        for (int j = 0; j < 4; j++)
#pragma unroll
            for (int c = 0; c < 4; c++) acc[i][j][c] = 0.0f;

    const int ldrow = tid >> 2;
    const int ldc   = tid & 3;
    // convert mapping
    const int crow  = tid >> 1;        // 0..127
    const int chalf = tid & 1;         // 0..1

    auto issue = [&](int kc) {
        int s = kc & 1;
        // A fp32: 1024 uint4 -> 4 per thread
#pragma unroll
        for (int i = 0; i < 4; i++) {
            int idx = tid + i * 256;
            int row = idx >> 3, c = idx & 7;
            int rg = block_row + row;
            if (rg >= M) rg = M - 1;
            const float* g = Af + (size_t)rg * 256 + kc * 32 + c * 4;
            cp_async16(sb + (uint32_t)(s * F_AF32_SZ + row * 144 + c * 16), g);
        }
        // B hi/lo
        uint32_t bbase = sb + F_B + (uint32_t)s * F_BSTG;
#pragma unroll
        for (int h = 0; h < 2; h++) {
            int row = ldrow + h * 64;
            size_t gB = (size_t)(block_col + row) * 32 + kc * 4 + ldc;
            uint32_t so = (uint32_t)(row * ASTRIDE + ldc * 8) * 2;
            cp_async16(bbase + so, Bhi4 + gB);
            cp_async16(bbase + TILE_B + so, Blo4 + gB);
        }
        CP_COMMIT();
    };

    issue(0);

    for (int kc = 0; kc < 8; kc++) {
        CP_WAIT(0);
        __syncthreads();
        if (kc < 7) issue(kc + 1);

        // convert fp32 stage -> bf16 hi/lo tiles (16 floats per thread)
        {
            int s = kc & 1;
            const char* af = smem + s * F_AF32_SZ + crow * 144 + chalf * 64;
            float4 v0 = *reinterpret_cast<const float4*>(af + 0);
            float4 v1 = *reinterpret_cast<const float4*>(af + 16);
            float4 v2 = *reinterpret_cast<const float4*>(af + 32);
            float4 v3 = *reinterpret_cast<const float4*>(af + 48);
            uint4 H0, H1, L0, L1;
            H0.x = pack_bf16x2(v0.x, v0.y); H0.y = pack_bf16x2(v0.z, v0.w);
            H0.z = pack_bf16x2(v1.x, v1.y); H0.w = pack_bf16x2(v1.z, v1.w);
            H1.x = pack_bf16x2(v2.x, v2.y); H1.y = pack_bf16x2(v2.z, v2.w);
            H1.z = pack_bf16x2(v3.x, v3.y); H1.w = pack_bf16x2(v3.z, v3.w);
            L0.x = pack_bf16x2(v0.x - __bfloat162float(__float2bfloat16(v0.x)),
                               v0.y - __bfloat162float(__float2bfloat16(v0.y)));
            L0.y = pack_bf16x2(v0.z - __bfloat162float(__float2bfloat16(v0.z)),
                               v0.w - __bfloat162float(__float2bfloat16(v0.w)));
            L0.z = pack_bf16x2(v1.x - __bfloat162float(__float2bfloat16(v1.x)),
                               v1.y - __bfloat162float(__float2bfloat16(v1.y)));
            L0.w = pack_bf16x2(v1.z - __bfloat162float(__float2bfloat16(v1.z)),
                               v1.w - __bfloat162float(__float2bfloat16(v1.w)));
            L1.x = pack_bf16x2(v2.x - __bfloat162float(__float2bfloat16(v2.x)),
                               v2.y - __bfloat162float(__float2bfloat16(v2.y)));
            L1.y = pack_bf16x2(v2.z - __bfloat162float(__float2bfloat16(v2.z)),
                               v2.w - __bfloat162float(__float2bfloat16(v2.w)));
            L1.z = pack_bf16x2(v3.x - __bfloat162float(__float2bfloat16(v3.x)),
                               v3.y - __bfloat162float(__float2bfloat16(v3.y)));
            L1.w = pack_bf16x2(v3.z - __bfloat162float(__float2bfloat16(v3.z)),
                               v3.w - __bfloat162float(__float2bfloat16(v3.w)));
            char* ah = smem + F_AHI + (crow * ASTRIDE + chalf * 16) * 2;
            char* al = smem + F_ALO + (crow * ASTRIDE + chalf * 16) * 2;
            *reinterpret_cast<uint4*>(ah + 0)  = H0;
            *reinterpret_cast<uint4*>(ah + 16) = H1;
            *reinterpret_cast<uint4*>(al + 0)  = L0;
            *reinterpret_cast<uint4*>(al + 16) = L1;
        }
        __syncthreads();

        uint32_t uAhi = sb + F_AHI;
        uint32_t uAlo = sb + F_ALO;
        uint32_t uBhi = sb + F_B + (uint32_t)(kc & 1) * F_BSTG;
        uint32_t uBlo = uBhi + TILE_B;
        GEMM_CHUNK_COMPUTE();
    }

    // ---- epilogue (bf16 split out) ----
#pragma unroll
    for (int mf = 0; mf < 4; mf++) {
        int r0 = block_row + wm * 64 + mf * 16 + (lane >> 2);
        int r1 = r0 + 8;
#pragma unroll
        for (int nf = 0; nf < 4; nf++) {
            int col = block_col + wn * 32 + nf * 8 + (lane & 3) * 2;
            float b0 = bias[col], b1 = bias[col + 1];
            float v00 = fmaxf(acc[mf][nf][0] + b0, 0.f);
            float v01 = fmaxf(acc[mf][nf][1] + b1, 0.f);
            float v10 = fmaxf(acc[mf][nf][2] + b0, 0.f);
            float v11 = fmaxf(acc[mf][nf][3] + b1, 0.f);
            uint32_t hp0 = pack_bf16x2(v00, v01);
            uint32_t hp1 = pack_bf16x2(v10, v11);
            float w00 = v00 - __bfloat162float(__float2bfloat16(v00));
            float w01 = v01 - __bfloat162float(__float2bfloat16(v01));
            float w10 = v10 - __bfloat162float(__float2bfloat16(v10));
            float w11 = v11 - __bfloat162float(__float2bfloat16(v11));
            uint32_t lp0 = pack_bf16x2(w00, w01);
            uint32_t lp1 = pack_bf16x2(w10, w11);
            if (r0 < M) {
                *reinterpret_cast<uint32_t*>(Chi + (size_t)r0 * HID + col) = hp0;
                *reinterpret_cast<uint32_t*>(Clo + (size_t)r0 * HID + col) = lp0;
            }
            if (r1 < M) {
                *reinterpret_cast<uint32_t*>(Chi + (size_t)r1 * HID + col) = hp1;
                *reinterpret_cast<uint32_t*>(Clo + (size_t)r1 * HID + col) = lp1;
            }
        }
    }
}

// =================== fp32 tiled SGEMM (small head GEMM) =====================

__global__ __launch_bounds__(256)
void sgemm_bias_relu(int M, const float* __restrict__ A,
                     const float* __restrict__ B,
                     const float* __restrict__ bias,
                     float* __restrict__ C,
                     int N, int K, int doRelu) {
    __shared__ float As[8][128];
    __shared__ float Bs[8][128];

    const int tid       = threadIdx.x;
    const int block_row = blockIdx.y * 128;
    const int block_col = blockIdx.x * 128;

    const int aRow = tid >> 1;
    const int aCol = (tid & 1) << 2;
    const int bRow = tid >> 5;
    const int bCol = (tid & 31) << 2;
    const int trow = (tid >> 4) << 3;
    const int tcol = (tid & 15) << 3;

    float acc[8][8];
#pragma unroll
    for (int i = 0; i < 8; i++)
#pragma unroll
        for (int j = 0; j < 8; j++) acc[i][j] = 0.0f;

    for (int kt = 0; kt < K; kt += 8) {
        float4 av = make_float4(0.f, 0.f, 0.f, 0.f);
        if (block_row + aRow < M)
            av = *reinterpret_cast<const float4*>(&A[(size_t)(block_row + aRow) * K + kt + aCol]);
        As[aCol + 0][aRow] = av.x;
        As[aCol + 1][aRow] = av.y;
        As[aCol + 2][aRow] = av.z;
        As[aCol + 3][aRow] = av.w;

        float4 bv = *reinterpret_cast<const float4*>(&B[(size_t)(kt + bRow) * N + block_col + bCol]);
        *reinterpret_cast<float4*>(&Bs[bRow][bCol]) = bv;
        __syncthreads();

#pragma unroll
        for (int k = 0; k < 8; k++) {
            float ra[8], rb[8];
#pragma unroll
            for (int i = 0; i < 8; i++) ra[i] = As[k][trow + i];
#pragma unroll
            for (int j = 0; j < 8; j++) rb[j] = Bs[k][tcol + j];
#pragma unroll
            for (int i = 0; i < 8; i++)
#pragma unroll
                for (int j = 0; j < 8; j++)
                    acc[i][j] = fmaf(ra[i], rb[j], acc[i][j]);
        }
        __syncthreads();
    }

#pragma unroll
    for (int i = 0; i < 8; i++) {
        int r = block_row + trow + i;
        if (r < M) {
#pragma unroll
            for (int j = 0; j < 8; j += 4) {
                float4 v;
                v.x = acc[i][j + 0] + bias[block_col + tcol + j + 0];
                v.y = acc[i][j + 1] + bias[block_col + tcol + j + 1];
                v.z = acc[i][j + 2] + bias[block_col + tcol + j + 2];
                v.w = acc[i][j + 3] + bias[block_col + tcol + j + 3];
                if (doRelu) {
                    v.x = fmaxf(v.x, 0.f); v.y = fmaxf(v.y, 0.f);
                    v.z = fmaxf(v.z, 0.f); v.w = fmaxf(v.w, 0.f);
                }
                *reinterpret_cast<float4*>(&C[(size_t)r * N + block_col + tcol + j]) = v;
            }
        }
    }
}

// ============================ pooling + head ================================

__global__ void pool_kernel(const float* __restrict__ h,
                            const int* __restrict__ batch,
                            float* __restrict__ pooled,
                            float* __restrict__ counts) {
    int node = (blockIdx.x * blockDim.x + threadIdx.x) >> 5;
    int lane = threadIdx.x & 31;
    if (node >= N_NODES) return;
    int b = batch[node];
    const float* hs = h + (size_t)node * HID;
    float* pd = pooled + (size_t)b * HID;
#pragma unroll
    for (int j = 0; j < 8; j++)
        atomicAdd(pd + lane + 32 * j, hs[lane + 32 * j]);
    if (lane == 0) atomicAdd(&counts[b], 1.0f);
}

__global__ void pool_div(float* __restrict__ pooled,
                         const float* __restrict__ counts) {
    int i = blockIdx.x * blockDim.x + threadIdx.x;
    float c = counts[i >> 8];
    pooled[i] = pooled[i] / fmaxf(c, 1.0f);
}

__global__ void head_final(const float* __restrict__ hid,
                           const float* __restrict__ W,
                           const float* __restrict__ b,
                           float* __restrict__ out) {
    int m = blockIdx.x * blockDim.x + threadIdx.x;
    if (m >= N_GRAPHS) return;
    float a0 = b[0], a1 = b[1], a2 = b[2];
    const float* hs = hid + (size_t)m * 128;
#pragma unroll 8
    for (int k = 0; k < 128; k++) {
        float h = hs[k];
        a0 = fmaf(h, W[k * 3 + 0], a0);
        a1 = fmaf(h, W[k * 3 + 1], a1);
        a2 = fmaf(h, W[k * 3 + 2], a2);
    }
    out[m * 3 + 0] = a0;
    out[m * 3 + 1] = a1;
    out[m * 3 + 2] = a2;
}

// ============================ launch ========================================

extern "C" void kernel_launch(void* const* d_in, const int* in_sizes, int n_in,
                              void* d_out, int out_size) {
    const float* x     = (const float*)d_in[0];
    const int*   ei    = (const int*)d_in[1];
    const int*   batch = (const int*)d_in[2];

    const float* Wa[4], *ba[4], *Wb[4], *bb[4];
    for (int l = 0; l < 4; l++) {
        Wa[l] = (const float*)d_in[3 + 4 * l + 0];
        ba[l] = (const float*)d_in[3 + 4 * l + 1];
        Wb[l] = (const float*)d_in[3 + 4 * l + 2];
        bb[l] = (const float*)d_in[3 + 4 * l + 3];
    }
    const float* Wh1 = (const float*)d_in[19];
    const float* bh1 = (const float*)d_in[20];
    const float* Wh2 = (const float*)d_in[21];
    const float* bh2 = (const float*)d_in[22];
    float* out = (float*)d_out;

    __nv_bfloat16 *A2hi, *A2lo, *Whi, *Wlo;
    float *bufB, *bufC, *agg7, *pooled, *counts, *hid;
    cudaGetSymbolAddress((void**)&A2hi,   g_A2hi);
    cudaGetSymbolAddress((void**)&A2lo,   g_A2lo);
    cudaGetSymbolAddress((void**)&Whi,    g_Whi);
    cudaGetSymbolAddress((void**)&Wlo,    g_Wlo);
    cudaGetSymbolAddress((void**)&bufB,   g_bufB);
    cudaGetSymbolAddress((void**)&bufC,   g_bufC);
    cudaGetSymbolAddress((void**)&agg7,   g_agg7);
    cudaGetSymbolAddress((void**)&pooled, g_pooled);
    cudaGetSymbolAddress((void**)&counts, g_counts);
    cudaGetSymbolAddress((void**)&hid,    g_hid);

    cudaFuncSetAttribute(mma_gemm_split,
                         cudaFuncAttributeMaxDynamicSharedMemorySize, GEMM_SMEM);
    cudaFuncSetAttribute(mma_gemm_split_f32a,
                         cudaFuncAttributeMaxDynamicSharedMemorySize, F_SMEM);

    // weight conversion: slots 0=W1b, 1=W2a, 2=W2b, 3=W3a, 4=W3b, 5=W4a, 6=W4b
    dim3 cw_grid(HID, 7);
    convert_weight_all<<<cw_grid, HID>>>(Wb[0], Wa[1], Wb[1], Wa[2], Wb[2],
                                         Wa[3], Wb[3], Whi, Wlo);

    dim3 mma_grid(2, (N_NODES + 127) / 128);

    // ---- layer 1 ----
    cudaMemcpyAsync(agg7, x, (size_t)N_NODES * 7 * sizeof(float),
                    cudaMemcpyDeviceToDevice);
    scatter_add_7<<<(N_EDGES + 255) / 256, 256>>>(x, ei, agg7);
    gemm_k7_relu_split<<<N_NODES, 256>>>(agg7, Wa[0], ba[0], A2hi, A2lo);
    mma_gemm_split<<<mma_grid, 256, GEMM_SMEM>>>(
        N_NODES, (const uint4*)A2hi, (const uint4*)A2lo,
        (const uint4*)Whi, (const uint4*)Wlo,
        bb[0], bufB, bufC, nullptr, nullptr, 0);

    // ---- layers 2..4 ----
    for (int l = 1; l < 4; l++) {
        // bufC holds h (self term); add neighbor terms
        scatter_add_256<<<((size_t)N_EDGES * 32 + 255) / 256, 256>>>(bufB, ei, bufC);
        // GEMM-a: fp32 A (bufC), in-kernel split; bf16 split out
        mma_gemm_split_f32a<<<mma_grid, 256, F_SMEM>>>(
            N_NODES, bufC,
            (const uint4*)(Whi + (size_t)(2 * l - 1) * HID * HID),
            (const uint4*)(Wlo + (size_t)(2 * l - 1) * HID * HID),
            ba[l], A2hi, A2lo);
        // GEMM-b: bf16 A; fp32 out (+bufC self-term for next layer)
        mma_gemm_split<<<mma_grid, 256, GEMM_SMEM>>>(
            N_NODES, (const uint4*)A2hi, (const uint4*)A2lo,
            (const uint4*)(Whi + (size_t)(2 * l) * HID * HID),
            (const uint4*)(Wlo + (size_t)(2 * l) * HID * HID),
            bb[l], bufB, (l < 3) ? bufC : nullptr, nullptr, nullptr, 0);
    }

    // ---- mean pool ----
    cudaMemsetAsync(pooled, 0, (size_t)N_GRAPHS * HID * sizeof(float));
    cudaMemsetAsync(counts, 0, (size_t)N_GRAPHS * sizeof(float));
    pool_kernel<<<((size_t)N_NODES * 32 + 255) / 256, 256>>>(bufB, batch,
                                                             pooled, counts);
    pool_div<<<N_GRAPHS * HID / 256, 256>>>(pooled, counts);

    // ---- head ----
    dim3 head_grid(1, (N_GRAPHS + 127) / 128);
    sgemm_bias_relu<<<head_grid, 256>>>(N_GRAPHS, pooled, Wh1, bh1, hid,
                                        128, 256, 1);
    head_final<<<(N_GRAPHS + 255) / 256, 256>>>(hid, Wh2, bh2, out);
}

// round 8
// speedup vs baseline: 2.3756x; 1.0462x over previous
#include <cuda_runtime.h>
#include <cuda_bf16.h>
#include <cstdint>

#define N_NODES  150000
#define N_EDGES  300000
#define N_GRAPHS 6000
#define HID      256

// ============================ mma.sync helpers ==============================

__device__ __forceinline__ uint32_t smem_u32(const void* p) {
    uint32_t addr;
    asm("{ .reg .u64 tmp; cvta.to.shared.u64 tmp, %1; cvt.u32.u64 %0, tmp; }"
        : "=r"(addr) : "l"(p));
    return addr;
}

__device__ __forceinline__ void ldsm_x4(uint32_t addr, uint32_t* r) {
    asm volatile("ldmatrix.sync.aligned.m8n8.x4.shared.b16 {%0,%1,%2,%3}, [%4];"
                 : "=r"(r[0]), "=r"(r[1]), "=r"(r[2]), "=r"(r[3]) : "r"(addr));
}

__device__ __forceinline__ void mma16816(float* d, const uint32_t* a,
                                         uint32_t b0, uint32_t b1) {
    asm volatile(
        "mma.sync.aligned.m16n8k16.row.col.f32.bf16.bf16.f32 "
        "{%0,%1,%2,%3}, {%4,%5,%6,%7}, {%8,%9}, {%0,%1,%2,%3};"
        : "+f"(d[0]), "+f"(d[1]), "+f"(d[2]), "+f"(d[3])
        : "r"(a[0]), "r"(a[1]), "r"(a[2]), "r"(a[3]), "r"(b0), "r"(b1));
}

__device__ __forceinline__ void cp_async16(uint32_t smem_addr, const void* g) {
    asm volatile("cp.async.cg.shared.global [%0], [%1], 16;"
                 :: "r"(smem_addr), "l"(g));
}
#define CP_COMMIT() asm volatile("cp.async.commit_group;" ::: "memory")
#define CP_WAIT(n)  asm volatile("cp.async.wait_group %0;" :: "n"(n) : "memory")

__device__ __forceinline__ uint32_t pack_bf16x2(float a, float b) {
    __nv_bfloat16 ha = __float2bfloat16(a);
    __nv_bfloat16 hb = __float2bfloat16(b);
    return ((uint32_t)__bfloat16_as_ushort(hb) << 16) | __bfloat16_as_ushort(ha);
}

// ============================ scratch buffers ===============================

__device__ __nv_bfloat16 g_A2hi[(size_t)N_NODES * HID];
__device__ __nv_bfloat16 g_A2lo[(size_t)N_NODES * HID];
__device__ float g_bufB[(size_t)N_NODES * HID];   // layer output h (gather src)
__device__ float g_bufC[(size_t)N_NODES * HID];   // scatter accumulator (init h)
__device__ float g_agg7[N_NODES * 7];
__device__ __nv_bfloat16 g_Whi[7 * HID * HID];    // weights, [N][K] bf16 hi
__device__ __nv_bfloat16 g_Wlo[7 * HID * HID];    // weights, [N][K] bf16 lo
__device__ float g_pooled[N_GRAPHS * HID];
__device__ float g_counts[N_GRAPHS];
__device__ float g_hid[N_GRAPHS * 128];

// ============================ small kernels =================================

__global__ void convert_weight_all(const float* __restrict__ W0,
                                   const float* __restrict__ W1,
                                   const float* __restrict__ W2,
                                   const float* __restrict__ W3,
                                   const float* __restrict__ W4,
                                   const float* __restrict__ W5,
                                   const float* __restrict__ W6,
                                   __nv_bfloat16* __restrict__ Whi,
                                   __nv_bfloat16* __restrict__ Wlo) {
    int w = blockIdx.y;
    const float* W = (w == 0) ? W0 : (w == 1) ? W1 : (w == 2) ? W2 :
                     (w == 3) ? W3 : (w == 4) ? W4 : (w == 5) ? W5 : W6;
    int n = blockIdx.x;   // 256
    int k = threadIdx.x;  // 256
    float v = W[k * HID + n];
    __nv_bfloat16 h = __float2bfloat16(v);
    size_t o = (size_t)w * HID * HID + n * HID + k;
    Whi[o] = h;
    Wlo[o] = __float2bfloat16(v - __bfloat162float(h));
}

__global__ void scatter_add_7(const float* __restrict__ x,
                              const int* __restrict__ ei,
                              float* __restrict__ agg) {
    int e = blockIdx.x * blockDim.x + threadIdx.x;
    if (e >= N_EDGES) return;
    int s = ei[e];
    int d = ei[N_EDGES + e];
#pragma unroll
    for (int j = 0; j < 7; j++)
        atomicAdd(&agg[(size_t)d * 7 + j], x[(size_t)s * 7 + j]);
}

__global__ void scatter_add_256(const float* __restrict__ x,
                                const int* __restrict__ ei,
                                float* __restrict__ agg) {
    int gw   = (blockIdx.x * blockDim.x + threadIdx.x) >> 5;
    int lane = threadIdx.x & 31;
    if (gw >= N_EDGES) return;
    int s = ei[gw];
    int d = ei[N_EDGES + gw];
    const float* xs = x + (size_t)s * HID;
    float* ad = agg + (size_t)d * HID;
#pragma unroll
    for (int j = 0; j < 8; j++)
        atomicAdd(ad + lane + 32 * j, xs[lane + 32 * j]);
}

__global__ void gemm_k7_relu_split(const float* __restrict__ A,
                                   const float* __restrict__ W,
                                   const float* __restrict__ bias,
                                   __nv_bfloat16* __restrict__ Chi,
                                   __nv_bfloat16* __restrict__ Clo) {
    int m = blockIdx.x;
    int n = threadIdx.x;  // 256
    __shared__ float xs[7];
    if (n < 7) xs[n] = A[(size_t)m * 7 + n];
    __syncthreads();
    float acc = bias[n];
#pragma unroll
    for (int j = 0; j < 7; j++)
        acc = fmaf(xs[j], W[j * HID + n], acc);
    float v = fmaxf(acc, 0.0f);
    __nv_bfloat16 h = __float2bfloat16(v);
    Chi[(size_t)m * HID + n] = h;
    Clo[(size_t)m * HID + n] = __float2bfloat16(v - __bfloat162float(h));
}

// =================== shared GEMM compute (padded layout, f32a) ==============

#define ASTRIDE 40                     // bf16 per smem row (80B, 16B-aligned)
#define TILE_B  (128 * ASTRIDE * 2)    // 10240 bytes per tile (padded)

#define GEMM_CHUNK_COMPUTE()                                                   \
    do {                                                                       \
        uint32_t ah[4][4], al[4][4], bh[2][4], bl[2][4];                       \
        _Pragma("unroll")                                                      \
        for (int ks16 = 0; ks16 < 2; ks16++) {                                 \
            const uint32_t ko = (uint32_t)(ks16 * 16) * 2;                     \
            _Pragma("unroll")                                                  \
            for (int f = 0; f < 4; f++) {                                      \
                uint32_t off = a_base + (uint32_t)(f * 16 * ASTRIDE) * 2 + ko; \
                ldsm_x4(uAhi + off, ah[f]);                                    \
                ldsm_x4(uAlo + off, al[f]);                                    \
            }                                                                  \
            _Pragma("unroll")                                                  \
            for (int p = 0; p < 2; p++) {                                      \
                uint32_t off = b_base + (uint32_t)(p * 16 * ASTRIDE) * 2 + ko; \
                ldsm_x4(uBhi + off, bh[p]);                                    \
                ldsm_x4(uBlo + off, bl[p]);                                    \
            }                                                                  \
            _Pragma("unroll")                                                  \
            for (int mf = 0; mf < 4; mf++)                                     \
                _Pragma("unroll")                                              \
                for (int nf = 0; nf < 4; nf++) {                               \
                    int p = nf >> 1, q = (nf & 1) * 2;                         \
                    mma16816(acc[mf][nf], ah[mf], bh[p][q], bh[p][q + 1]);     \
                    mma16816(acc[mf][nf], ah[mf], bl[p][q], bl[p][q + 1]);     \
                    mma16816(acc[mf][nf], al[mf], bh[p][q], bh[p][q + 1]);     \
                }                                                              \
        }                                                                      \
    } while (0)

// =================== GEMM variant 1: bf16 A, swizzled 3-stage ===============
// Tile = 128 rows x 64B (32 bf16), no pad. Swizzle:
//   offset(row, kcol16) = row*64 + ((kcol16 ^ ((row>>1)&3)) << 4)
// LDSM.x4 (8 consecutive rows, fixed kcol16) -> 8 distinct granule phases.

#define TILE_SW  8192                   // 128 * 64 bytes
#define STAGE_SW (4 * TILE_SW)          // 32768 per stage (Ahi,Alo,Bhi,Blo)
#define GEMM_SMEM (3 * STAGE_SW)        // 98304 bytes, 3 stages

__device__ __forceinline__ uint32_t swz(int row, uint32_t kcol) {
    return (uint32_t)(row * 64) + (((kcol ^ ((uint32_t)(row >> 1) & 3u)) << 4));
}

__global__ __launch_bounds__(256, 2)
void mma_gemm_split(int M,
                    const uint4* __restrict__ Ahi4, const uint4* __restrict__ Alo4,
                    const uint4* __restrict__ Bhi4, const uint4* __restrict__ Blo4,
                    const float* __restrict__ bias,
                    float* __restrict__ Cf, float* __restrict__ Cc,
                    __nv_bfloat16* __restrict__ Chi,
                    __nv_bfloat16* __restrict__ Clo,
                    int mode) {
    extern __shared__ char smem[];
    const uint32_t sb = smem_u32(smem);

    const int tid  = threadIdx.x;
    const int wid  = tid >> 5;
    const int lane = tid & 31;
    const int wm   = wid & 1;
    const int wn   = wid >> 1;
    const int block_col = blockIdx.x * 128;
    const int block_row = blockIdx.y * 128;

    const int a_lrow = lane & 15;
    const int a_lcol = (lane >> 4) << 3;       // 0 or 8 bf16
    const int b_lrow = (lane & 7) + ((lane >> 4) & 1) * 8;
    const int b_lcol = ((lane >> 3) & 1) << 3;
    const uint32_t a_k0 = (uint32_t)(a_lcol >> 3);  // 16B col: 0/1
    const uint32_t b_k0 = (uint32_t)(b_lcol >> 3);

    // per-lane swizzle precompute
    uint32_t a_rowoff[4], b_rowoff[2];
    uint32_t a_s[4], b_s[2];
#pragma unroll
    for (int f = 0; f < 4; f++) {
        int r = wm * 64 + f * 16 + a_lrow;
        a_rowoff[f] = (uint32_t)(r * 64);
        a_s[f] = (uint32_t)(r >> 1) & 3u;
    }
#pragma unroll
    for (int p = 0; p < 2; p++) {
        int r = wn * 32 + p * 16 + b_lrow;
        b_rowoff[p] = (uint32_t)(r * 64);
        b_s[p] = (uint32_t)(r >> 1) & 3u;
    }

    float acc[4][4][4];
#pragma unroll
    for (int i = 0; i < 4; i++)
#pragma unroll
        for (int j = 0; j < 4; j++)
#pragma unroll
            for (int c = 0; c < 4; c++) acc[i][j][c] = 0.0f;

    const int ldrow = tid >> 2;
    const int ldc   = tid & 3;

    auto issue = [&](int kc) {
        uint32_t sbase = sb + (uint32_t)(kc % 3) * STAGE_SW;
#pragma unroll
        for (int h = 0; h < 2; h++) {
            int row = ldrow + h * 64;
            int rg = block_row + row;
            if (rg >= M) rg = M - 1;
            size_t gA = (size_t)rg * 32 + kc * 4 + ldc;
            size_t gB = (size_t)(block_col + row) * 32 + kc * 4 + ldc;
            uint32_t so = swz(row, (uint32_t)ldc);
            cp_async16(sbase + 0 * TILE_SW + so, Ahi4 + gA);
            cp_async16(sbase + 1 * TILE_SW + so, Alo4 + gA);
            cp_async16(sbase + 2 * TILE_SW + so, Bhi4 + gB);
            cp_async16(sbase + 3 * TILE_SW + so, Blo4 + gB);
        }
        CP_COMMIT();
    };

    issue(0);
    issue(1);

    for (int kc = 0; kc < 8; kc++) {
        CP_WAIT(1);            // group kc fully arrived (kc+1 may be in flight)
        __syncthreads();       // also protects stage (kc+2)%3 reuse
        if (kc < 6) issue(kc + 2);

        uint32_t base = sb + (uint32_t)(kc % 3) * STAGE_SW;
        uint32_t uAhi = base + 0 * TILE_SW;
        uint32_t uAlo = base + 1 * TILE_SW;
        uint32_t uBhi = base + 2 * TILE_SW;
        uint32_t uBlo = base + 3 * TILE_SW;

        uint32_t ah[4][4], al[4][4], bh[2][4], bl[2][4];
#pragma unroll
        for (int ks16 = 0; ks16 < 2; ks16++) {
            const uint32_t kb = (uint32_t)(ks16 * 2);
#pragma unroll
            for (int f = 0; f < 4; f++) {
                uint32_t off = a_rowoff[f] + (((a_k0 + kb) ^ a_s[f]) << 4);
                ldsm_x4(uAhi + off, ah[f]);
                ldsm_x4(uAlo + off, al[f]);
            }
#pragma unroll
            for (int p = 0; p < 2; p++) {
                uint32_t off = b_rowoff[p] + (((b_k0 + kb) ^ b_s[p]) << 4);
                ldsm_x4(uBhi + off, bh[p]);
                ldsm_x4(uBlo + off, bl[p]);
            }
#pragma unroll
            for (int mf = 0; mf < 4; mf++)
#pragma unroll
                for (int nf = 0; nf < 4; nf++) {
                    int p = nf >> 1, q = (nf & 1) * 2;
                    mma16816(acc[mf][nf], ah[mf], bh[p][q], bh[p][q + 1]);
                    mma16816(acc[mf][nf], ah[mf], bl[p][q], bl[p][q + 1]);
                    mma16816(acc[mf][nf], al[mf], bh[p][q], bh[p][q + 1]);
                }
        }
    }

    // ---- epilogue ----
#pragma unroll
    for (int mf = 0; mf < 4; mf++) {
        int r0 = block_row + wm * 64 + mf * 16 + (lane >> 2);
        int r1 = r0 + 8;
#pragma unroll
        for (int nf = 0; nf < 4; nf++) {
            int col = block_col + wn * 32 + nf * 8 + (lane & 3) * 2;
            float b0 = bias[col], b1 = bias[col + 1];
            float v00 = fmaxf(acc[mf][nf][0] + b0, 0.f);
            float v01 = fmaxf(acc[mf][nf][1] + b1, 0.f);
            float v10 = fmaxf(acc[mf][nf][2] + b0, 0.f);
            float v11 = fmaxf(acc[mf][nf][3] + b1, 0.f);
            if (mode == 0) {
                if (r0 < M) {
                    *reinterpret_cast<float2*>(&Cf[(size_t)r0 * HID + col]) =
                        make_float2(v00, v01);
                    if (Cc)
                        *reinterpret_cast<float2*>(&Cc[(size_t)r0 * HID + col]) =
                            make_float2(v00, v01);
                }
                if (r1 < M) {
                    *reinterpret_cast<float2*>(&Cf[(size_t)r1 * HID + col]) =
                        make_float2(v10, v11);
                    if (Cc)
                        *reinterpret_cast<float2*>(&Cc[(size_t)r1 * HID + col]) =
                            make_float2(v10, v11);
                }
            } else {
                uint32_t hp0 = pack_bf16x2(v00, v01);
                uint32_t hp1 = pack_bf16x2(v10, v11);
                float w00 = v00 - __bfloat162float(__float2bfloat16(v00));
                float w01 = v01 - __bfloat162float(__float2bfloat16(v01));
                float w10 = v10 - __bfloat162float(__float2bfloat16(v10));
                float w11 = v11 - __bfloat162float(__float2bfloat16(v11));
                uint32_t lp0 = pack_bf16x2(w00, w01);
                uint32_t lp1 = pack_bf16x2(w10, w11);
                if (r0 < M) {
                    *reinterpret_cast<uint32_t*>(Chi + (size_t)r0 * HID + col) = hp0;
                    *reinterpret_cast<uint32_t*>(Clo + (size_t)r0 * HID + col) = lp0;
                }
                if (r1 < M) {
                    *reinterpret_cast<uint32_t*>(Chi + (size_t)r1 * HID + col) = hp1;
                    *reinterpret_cast<uint32_t*>(Clo + (size_t)r1 * HID + col) = lp1;
                }
            }
        }
    }
}

// =================== GEMM variant 2: fp32 A, in-kernel split ================
// (unchanged from R7; padded layout, 2-stage)

#define F_AF32_SZ (128 * 144)
#define F_B       (2 * F_AF32_SZ)
#define F_BSTG    (2 * TILE_B)
#define F_AHI     (F_B + 2 * F_BSTG)
#define F_ALO     (F_AHI + TILE_B)
#define F_SMEM    (F_ALO + TILE_B)

__global__ __launch_bounds__(256, 2)
void mma_gemm_split_f32a(int M,
                         const float* __restrict__ Af,
                         const uint4* __restrict__ Bhi4,
                         const uint4* __restrict__ Blo4,
                         const float* __restrict__ bias,
                         __nv_bfloat16* __restrict__ Chi,
                         __nv_bfloat16* __restrict__ Clo) {
    extern __shared__ char smem[];
    const uint32_t sb = smem_u32(smem);

    const int tid  = threadIdx.x;
    const int wid  = tid >> 5;
    const int lane = tid & 31;
    const int wm   = wid & 1;
    const int wn   = wid >> 1;
    const int block_col = blockIdx.x * 128;
    const int block_row = blockIdx.y * 128;

    const int a_lrow = lane & 15;
    const int a_lcol = (lane >> 4) << 3;
    const int b_lrow = (lane & 7) + ((lane >> 4) & 1) * 8;
    const int b_lcol = ((lane >> 3) & 1) << 3;
    const uint32_t a_base = (uint32_t)((wm * 64 + a_lrow) * ASTRIDE + a_lcol) * 2;
    const uint32_t b_base = (uint32_t)((wn * 32 + b_lrow) * ASTRIDE + b_lcol) * 2;

    float acc[4][4][4];
#pragma unroll
    for (int i = 0; i < 4; i++)
#pragma unroll
        for (int j = 0; j < 4; j++)
#pragma unroll
            for (int c = 0; c < 4; c++) acc[i][j][c] = 0.0f;

    const int ldrow = tid >> 2;
    const int ldc   = tid & 3;
    const int crow  = tid >> 1;
    const int chalf = tid & 1;

    auto issue = [&](int kc) {
        int s = kc & 1;
#pragma unroll
        for (int i = 0; i < 4; i++) {
            int idx = tid + i * 256;
            int row = idx >> 3, c = idx & 7;
            int rg = block_row + row;
            if (rg >= M) rg = M - 1;
            const float* g = Af + (size_t)rg * 256 + kc * 32 + c * 4;
            cp_async16(sb + (uint32_t)(s * F_AF32_SZ + row * 144 + c * 16), g);
        }
        uint32_t bbase = sb + F_B + (uint32_t)s * F_BSTG;
#pragma unroll
        for (int h = 0; h < 2; h++) {
            int row = ldrow + h * 64;
            size_t gB = (size_t)(block_col + row) * 32 + kc * 4 + ldc;
            uint32_t so = (uint32_t)(row * ASTRIDE + ldc * 8) * 2;
            cp_async16(bbase + so, Bhi4 + gB);
            cp_async16(bbase + TILE_B + so, Blo4 + gB);
        }
        CP_COMMIT();
    };

    issue(0);

    for (int kc = 0; kc < 8; kc++) {
        CP_WAIT(0);
        __syncthreads();
        if (kc < 7) issue(kc + 1);

        {
            int s = kc & 1;
            const char* af = smem + s * F_AF32_SZ + crow * 144 + chalf * 64;
            float4 v0 = *reinterpret_cast<const float4*>(af + 0);
            float4 v1 = *reinterpret_cast<const float4*>(af + 16);
            float4 v2 = *reinterpret_cast<const float4*>(af + 32);
            float4 v3 = *reinterpret_cast<const float4*>(af + 48);
            uint4 H0, H1, L0, L1;
            H0.x = pack_bf16x2(v0.x, v0.y); H0.y = pack_bf16x2(v0.z, v0.w);
            H0.z = pack_bf16x2(v1.x, v1.y); H0.w = pack_bf16x2(v1.z, v1.w);
            H1.x = pack_bf16x2(v2.x, v2.y); H1.y = pack_bf16x2(v2.z, v2.w);
            H1.z = pack_bf16x2(v3.x, v3.y); H1.w = pack_bf16x2(v3.z, v3.w);
            L0.x = pack_bf16x2(v0.x - __bfloat162float(__float2bfloat16(v0.x)),
                               v0.y - __bfloat162float(__float2bfloat16(v0.y)));
            L0.y = pack_bf16x2(v0.z - __bfloat162float(__float2bfloat16(v0.z)),
                               v0.w - __bfloat162float(__float2bfloat16(v0.w)));
            L0.z = pack_bf16x2(v1.x - __bfloat162float(__float2bfloat16(v1.x)),
                               v1.y - __bfloat162float(__float2bfloat16(v1.y)));
            L0.w = pack_bf16x2(v1.z - __bfloat162float(__float2bfloat16(v1.z)),
                               v1.w - __bfloat162float(__float2bfloat16(v1.w)));
            L1.x = pack_bf16x2(v2.x - __bfloat162float(__float2bfloat16(v2.x)),
                               v2.y - __bfloat162float(__float2bfloat16(v2.y)));
            L1.y = pack_bf16x2(v2.z - __bfloat162float(__float2bfloat16(v2.z)),
                               v2.w - __bfloat162float(__float2bfloat16(v2.w)));
            L1.z = pack_bf16x2(v3.x - __bfloat162float(__float2bfloat16(v3.x)),
                               v3.y - __bfloat162float(__float2bfloat16(v3.y)));
            L1.w = pack_bf16x2(v3.z - __bfloat162float(__float2bfloat16(v3.z)),
                               v3.w - __bfloat162float(__float2bfloat16(v3.w)));
            char* ah = smem + F_AHI + (crow * ASTRIDE + chalf * 16) * 2;
            char* al = smem + F_ALO + (crow * ASTRIDE + chalf * 16) * 2;
            *reinterpret_cast<uint4*>(ah + 0)  = H0;
            *reinterpret_cast<uint4*>(ah + 16) = H1;
            *reinterpret_cast<uint4*>(al + 0)  = L0;
            *reinterpret_cast<uint4*>(al + 16) = L1;
        }
        __syncthreads();

        uint32_t uAhi = sb + F_AHI;
        uint32_t uAlo = sb + F_ALO;
        uint32_t uBhi = sb + F_B + (uint32_t)(kc & 1) * F_BSTG;
        uint32_t uBlo = uBhi + TILE_B;
        GEMM_CHUNK_COMPUTE();
    }

#pragma unroll
    for (int mf = 0; mf < 4; mf++) {
        int r0 = block_row + wm * 64 + mf * 16 + (lane >> 2);
        int r1 = r0 + 8;
#pragma unroll
        for (int nf = 0; nf < 4; nf++) {
            int col = block_col + wn * 32 + nf * 8 + (lane & 3) * 2;
            float b0 = bias[col], b1 = bias[col + 1];
            float v00 = fmaxf(acc[mf][nf][0] + b0, 0.f);
            float v01 = fmaxf(acc[mf][nf][1] + b1, 0.f);
            float v10 = fmaxf(acc[mf][nf][2] + b0, 0.f);
            float v11 = fmaxf(acc[mf][nf][3] + b1, 0.f);
            uint32_t hp0 = pack_bf16x2(v00, v01);
            uint32_t hp1 = pack_bf16x2(v10, v11);
            float w00 = v00 - __bfloat162float(__float2bfloat16(v00));
            float w01 = v01 - __bfloat162float(__float2bfloat16(v01));
            float w10 = v10 - __bfloat162float(__float2bfloat16(v10));
            float w11 = v11 - __bfloat162float(__float2bfloat16(v11));
            uint32_t lp0 = pack_bf16x2(w00, w01);
            uint32_t lp1 = pack_bf16x2(w10, w11);
            if (r0 < M) {
                *reinterpret_cast<uint32_t*>(Chi + (size_t)r0 * HID + col) = hp0;
                *reinterpret_cast<uint32_t*>(Clo + (size_t)r0 * HID + col) = lp0;
            }
            if (r1 < M) {
                *reinterpret_cast<uint32_t*>(Chi + (size_t)r1 * HID + col) = hp1;
                *reinterpret_cast<uint32_t*>(Clo + (size_t)r1 * HID + col) = lp1;
            }
        }
    }
}

// =================== fp32 tiled SGEMM (small head GEMM) =====================

__global__ __launch_bounds__(256)
void sgemm_bias_relu(int M, const float* __restrict__ A,
                     const float* __restrict__ B,
                     const float* __restrict__ bias,
                     float* __restrict__ C,
                     int N, int K, int doRelu) {
    __shared__ float As[8][128];
    __shared__ float Bs[8][128];

    const int tid       = threadIdx.x;
    const int block_row = blockIdx.y * 128;
    const int block_col = blockIdx.x * 128;

    const int aRow = tid >> 1;
    const int aCol = (tid & 1) << 2;
    const int bRow = tid >> 5;
    const int bCol = (tid & 31) << 2;
    const int trow = (tid >> 4) << 3;
    const int tcol = (tid & 15) << 3;

    float acc[8][8];
#pragma unroll
    for (int i = 0; i < 8; i++)
#pragma unroll
        for (int j = 0; j < 8; j++) acc[i][j] = 0.0f;

    for (int kt = 0; kt < K; kt += 8) {
        float4 av = make_float4(0.f, 0.f, 0.f, 0.f);
        if (block_row + aRow < M)
            av = *reinterpret_cast<const float4*>(&A[(size_t)(block_row + aRow) * K + kt + aCol]);
        As[aCol + 0][aRow] = av.x;
        As[aCol + 1][aRow] = av.y;
        As[aCol + 2][aRow] = av.z;
        As[aCol + 3][aRow] = av.w;

        float4 bv = *reinterpret_cast<const float4*>(&B[(size_t)(kt + bRow) * N + block_col + bCol]);
        *reinterpret_cast<float4*>(&Bs[bRow][bCol]) = bv;
        __syncthreads();

#pragma unroll
        for (int k = 0; k < 8; k++) {
            float ra[8], rb[8];
#pragma unroll
            for (int i = 0; i < 8; i++) ra[i] = As[k][trow + i];
#pragma unroll
            for (int j = 0; j < 8; j++) rb[j] = Bs[k][tcol + j];
#pragma unroll
            for (int i = 0; i < 8; i++)
#pragma unroll
                for (int j = 0; j < 8; j++)
                    acc[i][j] = fmaf(ra[i], rb[j], acc[i][j]);
        }
        __syncthreads();
    }

#pragma unroll
    for (int i = 0; i < 8; i++) {
        int r = block_row + trow + i;
        if (r < M) {
#pragma unroll
            for (int j = 0; j < 8; j += 4) {
                float4 v;
                v.x = acc[i][j + 0] + bias[block_col + tcol + j + 0];
                v.y = acc[i][j + 1] + bias[block_col + tcol + j + 1];
                v.z = acc[i][j + 2] + bias[block_col + tcol + j + 2];
                v.w = acc[i][j + 3] + bias[block_col + tcol + j + 3];
                if (doRelu) {
                    v.x = fmaxf(v.x, 0.f); v.y = fmaxf(v.y, 0.f);
                    v.z = fmaxf(v.z, 0.f); v.w = fmaxf(v.w, 0.f);
                }
                *reinterpret_cast<float4*>(&C[(size_t)r * N + block_col + tcol + j]) = v;
            }
        }
    }
}

// ============================ pooling + head ================================

__global__ void pool_kernel(const float* __restrict__ h,
                            const int* __restrict__ batch,
                            float* __restrict__ pooled,
                            float* __restrict__ counts) {
    int node = (blockIdx.x * blockDim.x + threadIdx.x) >> 5;
    int lane = threadIdx.x & 31;
    if (node >= N_NODES) return;
    int b = batch[node];
    const float* hs = h + (size_t)node * HID;
    float* pd = pooled + (size_t)b * HID;
#pragma unroll
    for (int j = 0; j < 8; j++)
        atomicAdd(pd + lane + 32 * j, hs[lane + 32 * j]);
    if (lane == 0) atomicAdd(&counts[b], 1.0f);
}

__global__ void pool_div(float* __restrict__ pooled,
                         const float* __restrict__ counts) {
    int i = blockIdx.x * blockDim.x + threadIdx.x;
    float c = counts[i >> 8];
    pooled[i] = pooled[i] / fmaxf(c, 1.0f);
}

__global__ void head_final(const float* __restrict__ hid,
                           const float* __restrict__ W,
                           const float* __restrict__ b,
                           float* __restrict__ out) {
    int m = blockIdx.x * blockDim.x + threadIdx.x;
    if (m >= N_GRAPHS) return;
    float a0 = b[0], a1 = b[1], a2 = b[2];
    const float* hs = hid + (size_t)m * 128;
#pragma unroll 8
    for (int k = 0; k < 128; k++) {
        float h = hs[k];
        a0 = fmaf(h, W[k * 3 + 0], a0);
        a1 = fmaf(h, W[k * 3 + 1], a1);
        a2 = fmaf(h, W[k * 3 + 2], a2);
    }
    out[m * 3 + 0] = a0;
    out[m * 3 + 1] = a1;
    out[m * 3 + 2] = a2;
}

// ============================ launch ========================================

extern "C" void kernel_launch(void* const* d_in, const int* in_sizes, int n_in,
                              void* d_out, int out_size) {
    const float* x     = (const float*)d_in[0];
    const int*   ei    = (const int*)d_in[1];
    const int*   batch = (const int*)d_in[2];

    const float* Wa[4], *ba[4], *Wb[4], *bb[4];
    for (int l = 0; l < 4; l++) {
        Wa[l] = (const float*)d_in[3 + 4 * l + 0];
        ba[l] = (const float*)d_in[3 + 4 * l + 1];
        Wb[l] = (const float*)d_in[3 + 4 * l + 2];
        bb[l] = (const float*)d_in[3 + 4 * l + 3];
    }
    const float* Wh1 = (const float*)d_in[19];
    const float* bh1 = (const float*)d_in[20];
    const float* Wh2 = (const float*)d_in[21];
    const float* bh2 = (const float*)d_in[22];
    float* out = (float*)d_out;

    __nv_bfloat16 *A2hi, *A2lo, *Whi, *Wlo;
    float *bufB, *bufC, *agg7, *pooled, *counts, *hid;
    cudaGetSymbolAddress((void**)&A2hi,   g_A2hi);
    cudaGetSymbolAddress((void**)&A2lo,   g_A2lo);
    cudaGetSymbolAddress((void**)&Whi,    g_Whi);
    cudaGetSymbolAddress((void**)&Wlo,    g_Wlo);
    cudaGetSymbolAddress((void**)&bufB,   g_bufB);
    cudaGetSymbolAddress((void**)&bufC,   g_bufC);
    cudaGetSymbolAddress((void**)&agg7,   g_agg7);
    cudaGetSymbolAddress((void**)&pooled, g_pooled);
    cudaGetSymbolAddress((void**)&counts, g_counts);
    cudaGetSymbolAddress((void**)&hid,    g_hid);

    cudaFuncSetAttribute(mma_gemm_split,
                         cudaFuncAttributeMaxDynamicSharedMemorySize, GEMM_SMEM);
    cudaFuncSetAttribute(mma_gemm_split_f32a,
                         cudaFuncAttributeMaxDynamicSharedMemorySize, F_SMEM);

    // weight conversion: slots 0=W1b, 1=W2a, 2=W2b, 3=W3a, 4=W3b, 5=W4a, 6=W4b
    dim3 cw_grid(HID, 7);
    convert_weight_all<<<cw_grid, HID>>>(Wb[0], Wa[1], Wb[1], Wa[2], Wb[2],
                                         Wa[3], Wb[3], Whi, Wlo);

    dim3 mma_grid(2, (N_NODES + 127) / 128);

    // ---- layer 1 ----
    cudaMemcpyAsync(agg7, x, (size_t)N_NODES * 7 * sizeof(float),
                    cudaMemcpyDeviceToDevice);
    scatter_add_7<<<(N_EDGES + 255) / 256, 256>>>(x, ei, agg7);
    gemm_k7_relu_split<<<N_NODES, 256>>>(agg7, Wa[0], ba[0], A2hi, A2lo);
    mma_gemm_split<<<mma_grid, 256, GEMM_SMEM>>>(
        N_NODES, (const uint4*)A2hi, (const uint4*)A2lo,
        (const uint4*)Whi, (const uint4*)Wlo,
        bb[0], bufB, bufC, nullptr, nullptr, 0);

    // ---- layers 2..4 ----
    for (int l = 1; l < 4; l++) {
        scatter_add_256<<<((size_t)N_EDGES * 32 + 255) / 256, 256>>>(bufB, ei, bufC);
        mma_gemm_split_f32a<<<mma_grid, 256, F_SMEM>>>(
            N_NODES, bufC,
            (const uint4*)(Whi + (size_t)(2 * l - 1) * HID * HID),
            (const uint4*)(Wlo + (size_t)(2 * l - 1) * HID * HID),
            ba[l], A2hi, A2lo);
        mma_gemm_split<<<mma_grid, 256, GEMM_SMEM>>>(
            N_NODES, (const uint4*)A2hi, (const uint4*)A2lo,
            (const uint4*)(Whi + (size_t)(2 * l) * HID * HID),
            (const uint4*)(Wlo + (size_t)(2 * l) * HID * HID),
            bb[l], bufB, (l < 3) ? bufC : nullptr, nullptr, nullptr, 0);
    }

    // ---- mean pool ----
    cudaMemsetAsync(pooled, 0, (size_t)N_GRAPHS * HID * sizeof(float));
    cudaMemsetAsync(counts, 0, (size_t)N_GRAPHS * sizeof(float));
    pool_kernel<<<((size_t)N_NODES * 32 + 255) / 256, 256>>>(bufB, batch,
                                                             pooled, counts);
    pool_div<<<N_GRAPHS * HID / 256, 256>>>(pooled, counts);

    // ---- head ----
    dim3 head_grid(1, (N_GRAPHS + 127) / 128);
    sgemm_bias_relu<<<head_grid, 256>>>(N_GRAPHS, pooled, Wh1, bh1, hid,
                                        128, 256, 1);
    head_final<<<(N_GRAPHS + 255) / 256, 256>>>(hid, Wh2, bh2, out);
}

// round 9
// speedup vs baseline: 2.4540x; 1.0330x over previous
#include <cuda_runtime.h>
#include <cuda_bf16.h>
#include <cstdint>

#define N_NODES  150000
#define N_EDGES  300000
#define N_GRAPHS 6000
#define HID      256

// ============================ mma.sync helpers ==============================

__device__ __forceinline__ uint32_t smem_u32(const void* p) {
    uint32_t addr;
    asm("{ .reg .u64 tmp; cvta.to.shared.u64 tmp, %1; cvt.u32.u64 %0, tmp; }"
        : "=r"(addr) : "l"(p));
    return addr;
}

__device__ __forceinline__ void ldsm_x4(uint32_t addr, uint32_t* r) {
    asm volatile("ldmatrix.sync.aligned.m8n8.x4.shared.b16 {%0,%1,%2,%3}, [%4];"
                 : "=r"(r[0]), "=r"(r[1]), "=r"(r[2]), "=r"(r[3]) : "r"(addr));
}

__device__ __forceinline__ void mma16816(float* d, const uint32_t* a,
                                         uint32_t b0, uint32_t b1) {
    asm volatile(
        "mma.sync.aligned.m16n8k16.row.col.f32.bf16.bf16.f32 "
        "{%0,%1,%2,%3}, {%4,%5,%6,%7}, {%8,%9}, {%0,%1,%2,%3};"
        : "+f"(d[0]), "+f"(d[1]), "+f"(d[2]), "+f"(d[3])
        : "r"(a[0]), "r"(a[1]), "r"(a[2]), "r"(a[3]), "r"(b0), "r"(b1));
}

__device__ __forceinline__ void cp_async16(uint32_t smem_addr, const void* g) {
    asm volatile("cp.async.cg.shared.global [%0], [%1], 16;"
                 :: "r"(smem_addr), "l"(g));
}
#define CP_COMMIT() asm volatile("cp.async.commit_group;" ::: "memory")
#define CP_WAIT(n)  asm volatile("cp.async.wait_group %0;" :: "n"(n) : "memory")

__device__ __forceinline__ uint32_t pack_bf16x2(float a, float b) {
    __nv_bfloat16 ha = __float2bfloat16(a);
    __nv_bfloat16 hb = __float2bfloat16(b);
    return ((uint32_t)__bfloat16_as_ushort(hb) << 16) | __bfloat16_as_ushort(ha);
}

// ============================ scratch buffers ===============================

__device__ __nv_bfloat16 g_A2hi[(size_t)N_NODES * HID];
__device__ __nv_bfloat16 g_A2lo[(size_t)N_NODES * HID];
__device__ float g_bufB[(size_t)N_NODES * HID];   // layer output h (gather src)
__device__ float g_bufC[(size_t)N_NODES * HID];   // scatter accumulator (init h)
__device__ float g_agg7[N_NODES * 7];
__device__ __nv_bfloat16 g_Whi[7 * HID * HID];    // weights, [N][K] bf16 hi
__device__ __nv_bfloat16 g_Wlo[7 * HID * HID];    // weights, [N][K] bf16 lo
__device__ float g_pooled[N_GRAPHS * HID];
__device__ float g_counts[N_GRAPHS];
__device__ float g_hid[N_GRAPHS * 128];

// ============================ small kernels =================================

__global__ void convert_weight_all(const float* __restrict__ W0,
                                   const float* __restrict__ W1,
                                   const float* __restrict__ W2,
                                   const float* __restrict__ W3,
                                   const float* __restrict__ W4,
                                   const float* __restrict__ W5,
                                   const float* __restrict__ W6,
                                   __nv_bfloat16* __restrict__ Whi,
                                   __nv_bfloat16* __restrict__ Wlo) {
    int w = blockIdx.y;
    const float* W = (w == 0) ? W0 : (w == 1) ? W1 : (w == 2) ? W2 :
                     (w == 3) ? W3 : (w == 4) ? W4 : (w == 5) ? W5 : W6;
    int n = blockIdx.x;   // 256
    int k = threadIdx.x;  // 256
    float v = W[k * HID + n];
    __nv_bfloat16 h = __float2bfloat16(v);
    size_t o = (size_t)w * HID * HID + n * HID + k;
    Whi[o] = h;
    Wlo[o] = __float2bfloat16(v - __bfloat162float(h));
}

__global__ void scatter_add_7(const float* __restrict__ x,
                              const int* __restrict__ ei,
                              float* __restrict__ agg) {
    int e = blockIdx.x * blockDim.x + threadIdx.x;
    if (e >= N_EDGES) return;
    int s = ei[e];
    int d = ei[N_EDGES + e];
#pragma unroll
    for (int j = 0; j < 7; j++)
        atomicAdd(&agg[(size_t)d * 7 + j], x[(size_t)s * 7 + j]);
}

__global__ void scatter_add_256(const float* __restrict__ x,
                                const int* __restrict__ ei,
                                float* __restrict__ agg) {
    int gw   = (blockIdx.x * blockDim.x + threadIdx.x) >> 5;
    int lane = threadIdx.x & 31;
    if (gw >= N_EDGES) return;
    int s = ei[gw];
    int d = ei[N_EDGES + gw];
    const float* xs = x + (size_t)s * HID;
    float* ad = agg + (size_t)d * HID;
#pragma unroll
    for (int j = 0; j < 8; j++)
        atomicAdd(ad + lane + 32 * j, xs[lane + 32 * j]);
}

__global__ void gemm_k7_relu_split(const float* __restrict__ A,
                                   const float* __restrict__ W,
                                   const float* __restrict__ bias,
                                   __nv_bfloat16* __restrict__ Chi,
                                   __nv_bfloat16* __restrict__ Clo) {
    int m = blockIdx.x;
    int n = threadIdx.x;  // 256
    __shared__ float xs[7];
    if (n < 7) xs[n] = A[(size_t)m * 7 + n];
    __syncthreads();
    float acc = bias[n];
#pragma unroll
    for (int j = 0; j < 7; j++)
        acc = fmaf(xs[j], W[j * HID + n], acc);
    float v = fmaxf(acc, 0.0f);
    __nv_bfloat16 h = __float2bfloat16(v);
    Chi[(size_t)m * HID + n] = h;
    Clo[(size_t)m * HID + n] = __float2bfloat16(v - __bfloat162float(h));
}

// =================== GEMM variant 1: bf16 A, swizzled 3-stage ===============
// Tile = 128 rows x 64B (32 bf16), no pad. Swizzle:
//   offset(row, kcol16) = row*64 + ((kcol16 ^ ((row>>1)&3)) << 4)

#define TILE_SW  8192                   // 128 * 64 bytes
#define STAGE_SW (4 * TILE_SW)          // 32768 per stage (Ahi,Alo,Bhi,Blo)
#define GEMM_SMEM (3 * STAGE_SW)        // 98304 bytes, 3 stages

__device__ __forceinline__ uint32_t swz(int row, uint32_t kcol) {
    return (uint32_t)(row * 64) + (((kcol ^ ((uint32_t)(row >> 1) & 3u)) << 4));
}

__global__ __launch_bounds__(256, 2)
void mma_gemm_split(int M,
                    const uint4* __restrict__ Ahi4, const uint4* __restrict__ Alo4,
                    const uint4* __restrict__ Bhi4, const uint4* __restrict__ Blo4,
                    const float* __restrict__ bias,
                    float* __restrict__ Cf, float* __restrict__ Cc,
                    __nv_bfloat16* __restrict__ Chi,
                    __nv_bfloat16* __restrict__ Clo,
                    int mode) {
    extern __shared__ char smem[];
    const uint32_t sb = smem_u32(smem);

    const int tid  = threadIdx.x;
    const int wid  = tid >> 5;
    const int lane = tid & 31;
    const int wm   = wid & 1;
    const int wn   = wid >> 1;
    const int block_col = blockIdx.x * 128;
    const int block_row = blockIdx.y * 128;

    const int a_lrow = lane & 15;
    const int a_lcol = (lane >> 4) << 3;
    const int b_lrow = (lane & 7) + ((lane >> 4) & 1) * 8;
    const int b_lcol = ((lane >> 3) & 1) << 3;
    const uint32_t a_k0 = (uint32_t)(a_lcol >> 3);
    const uint32_t b_k0 = (uint32_t)(b_lcol >> 3);

    uint32_t a_rowoff[4], b_rowoff[2];
    uint32_t a_s[4], b_s[2];
#pragma unroll
    for (int f = 0; f < 4; f++) {
        int r = wm * 64 + f * 16 + a_lrow;
        a_rowoff[f] = (uint32_t)(r * 64);
        a_s[f] = (uint32_t)(r >> 1) & 3u;
    }
#pragma unroll
    for (int p = 0; p < 2; p++) {
        int r = wn * 32 + p * 16 + b_lrow;
        b_rowoff[p] = (uint32_t)(r * 64);
        b_s[p] = (uint32_t)(r >> 1) & 3u;
    }

    float acc[4][4][4];
#pragma unroll
    for (int i = 0; i < 4; i++)
#pragma unroll
        for (int j = 0; j < 4; j++)
#pragma unroll
            for (int c = 0; c < 4; c++) acc[i][j][c] = 0.0f;

    const int ldrow = tid >> 2;
    const int ldc   = tid & 3;

    auto issue = [&](int kc) {
        uint32_t sbase = sb + (uint32_t)(kc % 3) * STAGE_SW;
#pragma unroll
        for (int h = 0; h < 2; h++) {
            int row = ldrow + h * 64;
            int rg = block_row + row;
            if (rg >= M) rg = M - 1;
            size_t gA = (size_t)rg * 32 + kc * 4 + ldc;
            size_t gB = (size_t)(block_col + row) * 32 + kc * 4 + ldc;
            uint32_t so = swz(row, (uint32_t)ldc);
            cp_async16(sbase + 0 * TILE_SW + so, Ahi4 + gA);
            cp_async16(sbase + 1 * TILE_SW + so, Alo4 + gA);
            cp_async16(sbase + 2 * TILE_SW + so, Bhi4 + gB);
            cp_async16(sbase + 3 * TILE_SW + so, Blo4 + gB);
        }
        CP_COMMIT();
    };

    issue(0);
    issue(1);

    for (int kc = 0; kc < 8; kc++) {
        CP_WAIT(1);
        __syncthreads();
        if (kc < 6) issue(kc + 2);

        uint32_t base = sb + (uint32_t)(kc % 3) * STAGE_SW;
        uint32_t uAhi = base + 0 * TILE_SW;
        uint32_t uAlo = base + 1 * TILE_SW;
        uint32_t uBhi = base + 2 * TILE_SW;
        uint32_t uBlo = base + 3 * TILE_SW;

        uint32_t ah[4][4], al[4][4], bh[2][4], bl[2][4];
#pragma unroll
        for (int ks16 = 0; ks16 < 2; ks16++) {
            const uint32_t kb = (uint32_t)(ks16 * 2);
#pragma unroll
            for (int f = 0; f < 4; f++) {
                uint32_t off = a_rowoff[f] + (((a_k0 + kb) ^ a_s[f]) << 4);
                ldsm_x4(uAhi + off, ah[f]);
                ldsm_x4(uAlo + off, al[f]);
            }
#pragma unroll
            for (int p = 0; p < 2; p++) {
                uint32_t off = b_rowoff[p] + (((b_k0 + kb) ^ b_s[p]) << 4);
                ldsm_x4(uBhi + off, bh[p]);
                ldsm_x4(uBlo + off, bl[p]);
            }
#pragma unroll
            for (int mf = 0; mf < 4; mf++)
#pragma unroll
                for (int nf = 0; nf < 4; nf++) {
                    int p = nf >> 1, q = (nf & 1) * 2;
                    mma16816(acc[mf][nf], ah[mf], bh[p][q], bh[p][q + 1]);
                    mma16816(acc[mf][nf], ah[mf], bl[p][q], bl[p][q + 1]);
                    mma16816(acc[mf][nf], al[mf], bh[p][q], bh[p][q + 1]);
                }
        }
    }

    // ---- epilogue ----
#pragma unroll
    for (int mf = 0; mf < 4; mf++) {
        int r0 = block_row + wm * 64 + mf * 16 + (lane >> 2);
        int r1 = r0 + 8;
#pragma unroll
        for (int nf = 0; nf < 4; nf++) {
            int col = block_col + wn * 32 + nf * 8 + (lane & 3) * 2;
            float b0 = bias[col], b1 = bias[col + 1];
            float v00 = fmaxf(acc[mf][nf][0] + b0, 0.f);
            float v01 = fmaxf(acc[mf][nf][1] + b1, 0.f);
            float v10 = fmaxf(acc[mf][nf][2] + b0, 0.f);
            float v11 = fmaxf(acc[mf][nf][3] + b1, 0.f);
            if (mode == 0) {
                if (r0 < M) {
                    *reinterpret_cast<float2*>(&Cf[(size_t)r0 * HID + col]) =
                        make_float2(v00, v01);
                    if (Cc)
                        *reinterpret_cast<float2*>(&Cc[(size_t)r0 * HID + col]) =
                            make_float2(v00, v01);
                }
                if (r1 < M) {
                    *reinterpret_cast<float2*>(&Cf[(size_t)r1 * HID + col]) =
                        make_float2(v10, v11);
                    if (Cc)
                        *reinterpret_cast<float2*>(&Cc[(size_t)r1 * HID + col]) =
                            make_float2(v10, v11);
                }
            } else {
                uint32_t hp0 = pack_bf16x2(v00, v01);
                uint32_t hp1 = pack_bf16x2(v10, v11);
                float w00 = v00 - __bfloat162float(__float2bfloat16(v00));
                float w01 = v01 - __bfloat162float(__float2bfloat16(v01));
                float w10 = v10 - __bfloat162float(__float2bfloat16(v10));
                float w11 = v11 - __bfloat162float(__float2bfloat16(v11));
                uint32_t lp0 = pack_bf16x2(w00, w01);
                uint32_t lp1 = pack_bf16x2(w10, w11);
                if (r0 < M) {
                    *reinterpret_cast<uint32_t*>(Chi + (size_t)r0 * HID + col) = hp0;
                    *reinterpret_cast<uint32_t*>(Clo + (size_t)r0 * HID + col) = lp0;
                }
                if (r1 < M) {
                    *reinterpret_cast<uint32_t*>(Chi + (size_t)r1 * HID + col) = hp1;
                    *reinterpret_cast<uint32_t*>(Clo + (size_t)r1 * HID + col) = lp1;
                }
            }
        }
    }
}

// =================== GEMM variant 2: fp32 A, in-kernel split, 3-stage =======
// A fp32 stage: 128 rows x 128B, swizzle granule = (c ^ (row&7)).
// B hi/lo: swizzled 64B tiles like variant 1. Converted A: single 2x8KB buf.
// Total smem = 3*16K (Af32) + 3*16K (B) + 16K (conv) = 112 KB.

#define F_A32_STG 16384
#define F_B_OFF   (3 * F_A32_STG)          // 49152
#define F_B_STG   (2 * TILE_SW)            // 16384
#define F_AHI     (F_B_OFF + 3 * F_B_STG)  // 98304
#define F_ALO     (F_AHI + TILE_SW)        // 106496
#define F_SMEM    (F_ALO + TILE_SW)        // 114688 (112 KB)

__global__ __launch_bounds__(256, 2)
void mma_gemm_split_f32a(int M,
                         const float* __restrict__ Af,
                         const uint4* __restrict__ Bhi4,
                         const uint4* __restrict__ Blo4,
                         const float* __restrict__ bias,
                         __nv_bfloat16* __restrict__ Chi,
                         __nv_bfloat16* __restrict__ Clo) {
    extern __shared__ char smem[];
    const uint32_t sb = smem_u32(smem);

    const int tid  = threadIdx.x;
    const int wid  = tid >> 5;
    const int lane = tid & 31;
    const int wm   = wid & 1;
    const int wn   = wid >> 1;
    const int block_col = blockIdx.x * 128;
    const int block_row = blockIdx.y * 128;

    const int a_lrow = lane & 15;
    const int a_lcol = (lane >> 4) << 3;
    const int b_lrow = (lane & 7) + ((lane >> 4) & 1) * 8;
    const int b_lcol = ((lane >> 3) & 1) << 3;
    const uint32_t a_k0 = (uint32_t)(a_lcol >> 3);
    const uint32_t b_k0 = (uint32_t)(b_lcol >> 3);

    uint32_t a_rowoff[4], b_rowoff[2];
    uint32_t a_s[4], b_s[2];
#pragma unroll
    for (int f = 0; f < 4; f++) {
        int r = wm * 64 + f * 16 + a_lrow;
        a_rowoff[f] = (uint32_t)(r * 64);
        a_s[f] = (uint32_t)(r >> 1) & 3u;
    }
#pragma unroll
    for (int p = 0; p < 2; p++) {
        int r = wn * 32 + p * 16 + b_lrow;
        b_rowoff[p] = (uint32_t)(r * 64);
        b_s[p] = (uint32_t)(r >> 1) & 3u;
    }

    float acc[4][4][4];
#pragma unroll
    for (int i = 0; i < 4; i++)
#pragma unroll
        for (int j = 0; j < 4; j++)
#pragma unroll
            for (int c = 0; c < 4; c++) acc[i][j][c] = 0.0f;

    const int ldrow = tid >> 2;
    const int ldc   = tid & 3;
    const int crow  = tid >> 1;
    const int chalf = tid & 1;

    auto issue = [&](int kc) {
        int s = kc % 3;
        // A fp32: 1024 granules of 16B, swizzled
#pragma unroll
        for (int i = 0; i < 4; i++) {
            int idx = tid + i * 256;
            int row = idx >> 3, c = idx & 7;
            int rg = block_row + row;
            if (rg >= M) rg = M - 1;
            const float* g = Af + (size_t)rg * 256 + kc * 32 + c * 4;
            uint32_t so = (uint32_t)(row * 128) +
                          (((uint32_t)(c ^ (row & 7))) << 4);
            cp_async16(sb + (uint32_t)(s * F_A32_STG) + so, g);
        }
        // B hi/lo swizzled
        uint32_t bbase = sb + F_B_OFF + (uint32_t)s * F_B_STG;
#pragma unroll
        for (int h = 0; h < 2; h++) {
            int row = ldrow + h * 64;
            size_t gB = (size_t)(block_col + row) * 32 + kc * 4 + ldc;
            uint32_t so = swz(row, (uint32_t)ldc);
            cp_async16(bbase + so, Bhi4 + gB);
            cp_async16(bbase + TILE_SW + so, Blo4 + gB);
        }
        CP_COMMIT();
    };

    issue(0);
    issue(1);

    for (int kc = 0; kc < 8; kc++) {
        CP_WAIT(1);
        __syncthreads();           // stage (kc+2)%3 free; conv buffer free
        if (kc < 6) issue(kc + 2);

        // convert fp32 stage -> bf16 hi/lo swizzled tiles (16 floats/thread)
        {
            const char* afb = smem + (kc % 3) * F_A32_STG + crow * 128;
            uint32_t rs = (uint32_t)(crow & 7);
            float4 v0 = *reinterpret_cast<const float4*>(
                afb + (((uint32_t)(chalf * 4 + 0) ^ rs) << 4));
            float4 v1 = *reinterpret_cast<const float4*>(
                afb + (((uint32_t)(chalf * 4 + 1) ^ rs) << 4));
            float4 v2 = *reinterpret_cast<const float4*>(
                afb + (((uint32_t)(chalf * 4 + 2) ^ rs) << 4));
            float4 v3 = *reinterpret_cast<const float4*>(
                afb + (((uint32_t)(chalf * 4 + 3) ^ rs) << 4));
            uint4 H0, H1, L0, L1;
            H0.x = pack_bf16x2(v0.x, v0.y); H0.y = pack_bf16x2(v0.z, v0.w);
            H0.z = pack_bf16x2(v1.x, v1.y); H0.w = pack_bf16x2(v1.z, v1.w);
            H1.x = pack_bf16x2(v2.x, v2.y); H1.y = pack_bf16x2(v2.z, v2.w);
            H1.z = pack_bf16x2(v3.x, v3.y); H1.w = pack_bf16x2(v3.z, v3.w);
            L0.x = pack_bf16x2(v0.x - __bfloat162float(__float2bfloat16(v0.x)),
                               v0.y - __bfloat162float(__float2bfloat16(v0.y)));
            L0.y = pack_bf16x2(v0.z - __bfloat162float(__float2bfloat16(v0.z)),
                               v0.w - __bfloat162float(__float2bfloat16(v0.w)));
            L0.z = pack_bf16x2(v1.x - __bfloat162float(__float2bfloat16(v1.x)),
                               v1.y - __bfloat162float(__float2bfloat16(v1.y)));
            L0.w = pack_bf16x2(v1.z - __bfloat162float(__float2bfloat16(v1.z)),
                               v1.w - __bfloat162float(__float2bfloat16(v1.w)));
            L1.x = pack_bf16x2(v2.x - __bfloat162float(__float2bfloat16(v2.x)),
                               v2.y - __bfloat162float(__float2bfloat16(v2.y)));
            L1.y = pack_bf16x2(v2.z - __bfloat162float(__float2bfloat16(v2.z)),
                               v2.w - __bfloat162float(__float2bfloat16(v2.w)));
            L1.z = pack_bf16x2(v3.x - __bfloat162float(__float2bfloat16(v3.x)),
                               v3.y - __bfloat162float(__float2bfloat16(v3.y)));
            L1.w = pack_bf16x2(v3.z - __bfloat162float(__float2bfloat16(v3.z)),
                               v3.w - __bfloat162float(__float2bfloat16(v3.w)));
            // converted tile: 64B/row, granules chalf*2, chalf*2+1 (swizzled)
            uint32_t cs = (uint32_t)(crow >> 1) & 3u;
            uint32_t g0 = ((uint32_t)(chalf * 2 + 0) ^ cs) << 4;
            uint32_t g1 = ((uint32_t)(chalf * 2 + 1) ^ cs) << 4;
            char* ah = smem + F_AHI + crow * 64;
            char* al = smem + F_ALO + crow * 64;
            *reinterpret_cast<uint4*>(ah + g0) = H0;
            *reinterpret_cast<uint4*>(ah + g1) = H1;
            *reinterpret_cast<uint4*>(al + g0) = L0;
            *reinterpret_cast<uint4*>(al + g1) = L1;
        }
        __syncthreads();

        uint32_t uAhi = sb + F_AHI;
        uint32_t uAlo = sb + F_ALO;
        uint32_t uBhi = sb + F_B_OFF + (uint32_t)(kc % 3) * F_B_STG;
        uint32_t uBlo = uBhi + TILE_SW;

        uint32_t ah[4][4], al[4][4], bh[2][4], bl[2][4];
#pragma unroll
        for (int ks16 = 0; ks16 < 2; ks16++) {
            const uint32_t kb = (uint32_t)(ks16 * 2);
#pragma unroll
            for (int f = 0; f < 4; f++) {
                uint32_t off = a_rowoff[f] + (((a_k0 + kb) ^ a_s[f]) << 4);
                ldsm_x4(uAhi + off, ah[f]);
                ldsm_x4(uAlo + off, al[f]);
            }
#pragma unroll
            for (int p = 0; p < 2; p++) {
                uint32_t off = b_rowoff[p] + (((b_k0 + kb) ^ b_s[p]) << 4);
                ldsm_x4(uBhi + off, bh[p]);
                ldsm_x4(uBlo + off, bl[p]);
            }
#pragma unroll
            for (int mf = 0; mf < 4; mf++)
#pragma unroll
                for (int nf = 0; nf < 4; nf++) {
                    int p = nf >> 1, q = (nf & 1) * 2;
                    mma16816(acc[mf][nf], ah[mf], bh[p][q], bh[p][q + 1]);
                    mma16816(acc[mf][nf], ah[mf], bl[p][q], bl[p][q + 1]);
                    mma16816(acc[mf][nf], al[mf], bh[p][q], bh[p][q + 1]);
                }
        }
    }

    // ---- epilogue (bf16 split out) ----
#pragma unroll
    for (int mf = 0; mf < 4; mf++) {
        int r0 = block_row + wm * 64 + mf * 16 + (lane >> 2);
        int r1 = r0 + 8;
#pragma unroll
        for (int nf = 0; nf < 4; nf++) {
            int col = block_col + wn * 32 + nf * 8 + (lane & 3) * 2;
            float b0 = bias[col], b1 = bias[col + 1];
            float v00 = fmaxf(acc[mf][nf][0] + b0, 0.f);
            float v01 = fmaxf(acc[mf][nf][1] + b1, 0.f);
            float v10 = fmaxf(acc[mf][nf][2] + b0, 0.f);
            float v11 = fmaxf(acc[mf][nf][3] + b1, 0.f);
            uint32_t hp0 = pack_bf16x2(v00, v01);
            uint32_t hp1 = pack_bf16x2(v10, v11);
            float w00 = v00 - __bfloat162float(__float2bfloat16(v00));
            float w01 = v01 - __bfloat162float(__float2bfloat16(v01));
            float w10 = v10 - __bfloat162float(__float2bfloat16(v10));
            float w11 = v11 - __bfloat162float(__float2bfloat16(v11));
            uint32_t lp0 = pack_bf16x2(w00, w01);
            uint32_t lp1 = pack_bf16x2(w10, w11);
            if (r0 < M) {
                *reinterpret_cast<uint32_t*>(Chi + (size_t)r0 * HID + col) = hp0;
                *reinterpret_cast<uint32_t*>(Clo + (size_t)r0 * HID + col) = lp0;
            }
            if (r1 < M) {
                *reinterpret_cast<uint32_t*>(Chi + (size_t)r1 * HID + col) = hp1;
                *reinterpret_cast<uint32_t*>(Clo + (size_t)r1 * HID + col) = lp1;
            }
        }
    }
}

// =================== fp32 tiled SGEMM (small head GEMM) =====================

__global__ __launch_bounds__(256)
void sgemm_bias_relu(int M, const float* __restrict__ A,
                     const float* __restrict__ B,
                     const float* __restrict__ bias,
                     float* __restrict__ C,
                     int N, int K, int doRelu) {
    __shared__ float As[8][128];
    __shared__ float Bs[8][128];

    const int tid       = threadIdx.x;
    const int block_row = blockIdx.y * 128;
    const int block_col = blockIdx.x * 128;

    const int aRow = tid >> 1;
    const int aCol = (tid & 1) << 2;
    const int bRow = tid >> 5;
    const int bCol = (tid & 31) << 2;
    const int trow = (tid >> 4) << 3;
    const int tcol = (tid & 15) << 3;

    float acc[8][8];
#pragma unroll
    for (int i = 0; i < 8; i++)
#pragma unroll
        for (int j = 0; j < 8; j++) acc[i][j] = 0.0f;

    for (int kt = 0; kt < K; kt += 8) {
        float4 av = make_float4(0.f, 0.f, 0.f, 0.f);
        if (block_row + aRow < M)
            av = *reinterpret_cast<const float4*>(&A[(size_t)(block_row + aRow) * K + kt + aCol]);
        As[aCol + 0][aRow] = av.x;
        As[aCol + 1][aRow] = av.y;
        As[aCol + 2][aRow] = av.z;
        As[aCol + 3][aRow] = av.w;

        float4 bv = *reinterpret_cast<const float4*>(&B[(size_t)(kt + bRow) * N + block_col + bCol]);
        *reinterpret_cast<float4*>(&Bs[bRow][bCol]) = bv;
        __syncthreads();

#pragma unroll
        for (int k = 0; k < 8; k++) {
            float ra[8], rb[8];
#pragma unroll
            for (int i = 0; i < 8; i++) ra[i] = As[k][trow + i];
#pragma unroll
            for (int j = 0; j < 8; j++) rb[j] = Bs[k][tcol + j];
#pragma unroll
            for (int i = 0; i < 8; i++)
#pragma unroll
                for (int j = 0; j < 8; j++)
                    acc[i][j] = fmaf(ra[i], rb[j], acc[i][j]);
        }
        __syncthreads();
    }

#pragma unroll
    for (int i = 0; i < 8; i++) {
        int r = block_row + trow + i;
        if (r < M) {
#pragma unroll
            for (int j = 0; j < 8; j += 4) {
                float4 v;
                v.x = acc[i][j + 0] + bias[block_col + tcol + j + 0];
                v.y = acc[i][j + 1] + bias[block_col + tcol + j + 1];
                v.z = acc[i][j + 2] + bias[block_col + tcol + j + 2];
                v.w = acc[i][j + 3] + bias[block_col + tcol + j + 3];
                if (doRelu) {
                    v.x = fmaxf(v.x, 0.f); v.y = fmaxf(v.y, 0.f);
                    v.z = fmaxf(v.z, 0.f); v.w = fmaxf(v.w, 0.f);
                }
                *reinterpret_cast<float4*>(&C[(size_t)r * N + block_col + tcol + j]) = v;
            }
        }
    }
}

// ============================ pooling + head ================================

__global__ void pool_kernel(const float* __restrict__ h,
                            const int* __restrict__ batch,
                            float* __restrict__ pooled,
                            float* __restrict__ counts) {
    int node = (blockIdx.x * blockDim.x + threadIdx.x) >> 5;
    int lane = threadIdx.x & 31;
    if (node >= N_NODES) return;
    int b = batch[node];
    const float* hs = h + (size_t)node * HID;
    float* pd = pooled + (size_t)b * HID;
#pragma unroll
    for (int j = 0; j < 8; j++)
        atomicAdd(pd + lane + 32 * j, hs[lane + 32 * j]);
    if (lane == 0) atomicAdd(&counts[b], 1.0f);
}

__global__ void pool_div(float* __restrict__ pooled,
                         const float* __restrict__ counts) {
    int i = blockIdx.x * blockDim.x + threadIdx.x;
    float c = counts[i >> 8];
    pooled[i] = pooled[i] / fmaxf(c, 1.0f);
}

__global__ void head_final(const float* __restrict__ hid,
                           const float* __restrict__ W,
                           const float* __restrict__ b,
                           float* __restrict__ out) {
    int m = blockIdx.x * blockDim.x + threadIdx.x;
    if (m >= N_GRAPHS) return;
    float a0 = b[0], a1 = b[1], a2 = b[2];
    const float* hs = hid + (size_t)m * 128;
#pragma unroll 8
    for (int k = 0; k < 128; k++) {
        float h = hs[k];
        a0 = fmaf(h, W[k * 3 + 0], a0);
        a1 = fmaf(h, W[k * 3 + 1], a1);
        a2 = fmaf(h, W[k * 3 + 2], a2);
    }
    out[m * 3 + 0] = a0;
    out[m * 3 + 1] = a1;
    out[m * 3 + 2] = a2;
}

// ============================ launch ========================================

extern "C" void kernel_launch(void* const* d_in, const int* in_sizes, int n_in,
                              void* d_out, int out_size) {
    const float* x     = (const float*)d_in[0];
    const int*   ei    = (const int*)d_in[1];
    const int*   batch = (const int*)d_in[2];

    const float* Wa[4], *ba[4], *Wb[4], *bb[4];
    for (int l = 0; l < 4; l++) {
        Wa[l] = (const float*)d_in[3 + 4 * l + 0];
        ba[l] = (const float*)d_in[3 + 4 * l + 1];
        Wb[l] = (const float*)d_in[3 + 4 * l + 2];
        bb[l] = (const float*)d_in[3 + 4 * l + 3];
    }
    const float* Wh1 = (const float*)d_in[19];
    const float* bh1 = (const float*)d_in[20];
    const float* Wh2 = (const float*)d_in[21];
    const float* bh2 = (const float*)d_in[22];
    float* out = (float*)d_out;

    __nv_bfloat16 *A2hi, *A2lo, *Whi, *Wlo;
    float *bufB, *bufC, *agg7, *pooled, *counts, *hid;
    cudaGetSymbolAddress((void**)&A2hi,   g_A2hi);
    cudaGetSymbolAddress((void**)&A2lo,   g_A2lo);
    cudaGetSymbolAddress((void**)&Whi,    g_Whi);
    cudaGetSymbolAddress((void**)&Wlo,    g_Wlo);
    cudaGetSymbolAddress((void**)&bufB,   g_bufB);
    cudaGetSymbolAddress((void**)&bufC,   g_bufC);
    cudaGetSymbolAddress((void**)&agg7,   g_agg7);
    cudaGetSymbolAddress((void**)&pooled, g_pooled);
    cudaGetSymbolAddress((void**)&counts, g_counts);
    cudaGetSymbolAddress((void**)&hid,    g_hid);

    cudaFuncSetAttribute(mma_gemm_split,
                         cudaFuncAttributeMaxDynamicSharedMemorySize, GEMM_SMEM);
    cudaFuncSetAttribute(mma_gemm_split_f32a,
                         cudaFuncAttributeMaxDynamicSharedMemorySize, F_SMEM);

    // weight conversion: slots 0=W1b, 1=W2a, 2=W2b, 3=W3a, 4=W3b, 5=W4a, 6=W4b
    dim3 cw_grid(HID, 7);
    convert_weight_all<<<cw_grid, HID>>>(Wb[0], Wa[1], Wb[1], Wa[2], Wb[2],
                                         Wa[3], Wb[3], Whi, Wlo);

    dim3 mma_grid(2, (N_NODES + 127) / 128);

    // ---- layer 1 ----
    cudaMemcpyAsync(agg7, x, (size_t)N_NODES * 7 * sizeof(float),
                    cudaMemcpyDeviceToDevice);
    scatter_add_7<<<(N_EDGES + 255) / 256, 256>>>(x, ei, agg7);
    gemm_k7_relu_split<<<N_NODES, 256>>>(agg7, Wa[0], ba[0], A2hi, A2lo);
    mma_gemm_split<<<mma_grid, 256, GEMM_SMEM>>>(
        N_NODES, (const uint4*)A2hi, (const uint4*)A2lo,
        (const uint4*)Whi, (const uint4*)Wlo,
        bb[0], bufB, bufC, nullptr, nullptr, 0);

    // ---- layers 2..4 ----
    for (int l = 1; l < 4; l++) {
        scatter_add_256<<<((size_t)N_EDGES * 32 + 255) / 256, 256>>>(bufB, ei, bufC);
        mma_gemm_split_f32a<<<mma_grid, 256, F_SMEM>>>(
            N_NODES, bufC,
            (const uint4*)(Whi + (size_t)(2 * l - 1) * HID * HID),
            (const uint4*)(Wlo + (size_t)(2 * l - 1) * HID * HID),
            ba[l], A2hi, A2lo);
        mma_gemm_split<<<mma_grid, 256, GEMM_SMEM>>>(
            N_NODES, (const uint4*)A2hi, (const uint4*)A2lo,
            (const uint4*)(Whi + (size_t)(2 * l) * HID * HID),
            (const uint4*)(Wlo + (size_t)(2 * l) * HID * HID),
            bb[l], bufB, (l < 3) ? bufC : nullptr, nullptr, nullptr, 0);
    }

    // ---- mean pool ----
    cudaMemsetAsync(pooled, 0, (size_t)N_GRAPHS * HID * sizeof(float));
    cudaMemsetAsync(counts, 0, (size_t)N_GRAPHS * sizeof(float));
    pool_kernel<<<((size_t)N_NODES * 32 + 255) / 256, 256>>>(bufB, batch,
                                                             pooled, counts);
    pool_div<<<N_GRAPHS * HID / 256, 256>>>(pooled, counts);

    // ---- head ----
    dim3 head_grid(1, (N_GRAPHS + 127) / 128);
    sgemm_bias_relu<<<head_grid, 256>>>(N_GRAPHS, pooled, Wh1, bh1, hid,
                                        128, 256, 1);
    head_final<<<(N_GRAPHS + 255) / 256, 256>>>(hid, Wh2, bh2, out);
}

// round 10
// speedup vs baseline: 2.5171x; 1.0257x over previous
#include <cuda_runtime.h>
#include <cuda_bf16.h>
#include <cstdint>

#define N_NODES  150000
#define N_EDGES  300000
#define N_GRAPHS 6000
#define HID      256

// ============================ mma.sync helpers ==============================

__device__ __forceinline__ uint32_t smem_u32(const void* p) {
    uint32_t addr;
    asm("{ .reg .u64 tmp; cvta.to.shared.u64 tmp, %1; cvt.u32.u64 %0, tmp; }"
        : "=r"(addr) : "l"(p));
    return addr;
}

__device__ __forceinline__ void ldsm_x4(uint32_t addr, uint32_t* r) {
    asm volatile("ldmatrix.sync.aligned.m8n8.x4.shared.b16 {%0,%1,%2,%3}, [%4];"
                 : "=r"(r[0]), "=r"(r[1]), "=r"(r[2]), "=r"(r[3]) : "r"(addr));
}

__device__ __forceinline__ void mma16816(float* d, const uint32_t* a,
                                         uint32_t b0, uint32_t b1) {
    asm volatile(
        "mma.sync.aligned.m16n8k16.row.col.f32.bf16.bf16.f32 "
        "{%0,%1,%2,%3}, {%4,%5,%6,%7}, {%8,%9}, {%0,%1,%2,%3};"
        : "+f"(d[0]), "+f"(d[1]), "+f"(d[2]), "+f"(d[3])
        : "r"(a[0]), "r"(a[1]), "r"(a[2]), "r"(a[3]), "r"(b0), "r"(b1));
}

__device__ __forceinline__ void cp_async16(uint32_t smem_addr, const void* g) {
    asm volatile("cp.async.cg.shared.global [%0], [%1], 16;"
                 :: "r"(smem_addr), "l"(g));
}
#define CP_COMMIT() asm volatile("cp.async.commit_group;" ::: "memory")
#define CP_WAIT(n)  asm volatile("cp.async.wait_group %0;" :: "n"(n) : "memory")

__device__ __forceinline__ uint32_t pack_bf16x2(float a, float b) {
    __nv_bfloat16 ha = __float2bfloat16(a);
    __nv_bfloat16 hb = __float2bfloat16(b);
    return ((uint32_t)__bfloat16_as_ushort(hb) << 16) | __bfloat16_as_ushort(ha);
}

// ============================ scratch buffers ===============================

__device__ __nv_bfloat16 g_A2hi[(size_t)N_NODES * HID];
__device__ __nv_bfloat16 g_A2lo[(size_t)N_NODES * HID];
__device__ float g_bufB[(size_t)N_NODES * HID];   // layer output h (gather src)
__device__ float g_bufC[(size_t)N_NODES * HID];   // scatter accumulator (init h)
__device__ float g_agg7[N_NODES * 7];
__device__ __nv_bfloat16 g_Whi[7 * HID * HID];    // weights, [N][K] bf16 hi
__device__ __nv_bfloat16 g_Wlo[7 * HID * HID];    // weights, [N][K] bf16 lo
__device__ float g_pooled[N_GRAPHS * HID];
__device__ float g_counts[N_GRAPHS];
__device__ float g_hid[N_GRAPHS * 128];

// ============================ small kernels =================================

__global__ void convert_weight_all(const float* __restrict__ W0,
                                   const float* __restrict__ W1,
                                   const float* __restrict__ W2,
                                   const float* __restrict__ W3,
                                   const float* __restrict__ W4,
                                   const float* __restrict__ W5,
                                   const float* __restrict__ W6,
                                   __nv_bfloat16* __restrict__ Whi,
                                   __nv_bfloat16* __restrict__ Wlo) {
    int w = blockIdx.y;
    const float* W = (w == 0) ? W0 : (w == 1) ? W1 : (w == 2) ? W2 :
                     (w == 3) ? W3 : (w == 4) ? W4 : (w == 5) ? W5 : W6;
    int n = blockIdx.x;   // 256
    int k = threadIdx.x;  // 256
    float v = W[k * HID + n];
    __nv_bfloat16 h = __float2bfloat16(v);
    size_t o = (size_t)w * HID * HID + n * HID + k;
    Whi[o] = h;
    Wlo[o] = __float2bfloat16(v - __bfloat162float(h));
}

__global__ void count_kernel(const int* __restrict__ batch,
                             float* __restrict__ counts) {
    int i = blockIdx.x * blockDim.x + threadIdx.x;
    if (i >= N_NODES) return;
    atomicAdd(&counts[batch[i]], 1.0f);
}

__global__ void scatter_add_7(const float* __restrict__ x,
                              const int* __restrict__ ei,
                              float* __restrict__ agg) {
    int e = blockIdx.x * blockDim.x + threadIdx.x;
    if (e >= N_EDGES) return;
    int s = ei[e];
    int d = ei[N_EDGES + e];
#pragma unroll
    for (int j = 0; j < 7; j++)
        atomicAdd(&agg[(size_t)d * 7 + j], x[(size_t)s * 7 + j]);
}

__global__ void scatter_add_256(const float* __restrict__ x,
                                const int* __restrict__ ei,
                                float* __restrict__ agg) {
    int gw   = (blockIdx.x * blockDim.x + threadIdx.x) >> 5;
    int lane = threadIdx.x & 31;
    if (gw >= N_EDGES) return;
    int s = ei[gw];
    int d = ei[N_EDGES + gw];
    const float* xs = x + (size_t)s * HID;
    float* ad = agg + (size_t)d * HID;
#pragma unroll
    for (int j = 0; j < 8; j++)
        atomicAdd(ad + lane + 32 * j, xs[lane + 32 * j]);
}

// layer-1 first GEMM (K=7), grid-stride, weights hoisted to registers
#define K7_BLOCKS 1184
__global__ void gemm_k7_relu_split(const float* __restrict__ A,
                                   const float* __restrict__ W,
                                   const float* __restrict__ bias,
                                   __nv_bfloat16* __restrict__ Chi,
                                   __nv_bfloat16* __restrict__ Clo) {
    int n = threadIdx.x;  // 256
    float w0 = W[0 * HID + n], w1 = W[1 * HID + n], w2 = W[2 * HID + n];
    float w3 = W[3 * HID + n], w4 = W[4 * HID + n], w5 = W[5 * HID + n];
    float w6 = W[6 * HID + n];
    float bi = bias[n];
    for (int m = blockIdx.x; m < N_NODES; m += K7_BLOCKS) {
        const float* xr = A + (size_t)m * 7;
        float acc = bi;
        acc = fmaf(xr[0], w0, acc);
        acc = fmaf(xr[1], w1, acc);
        acc = fmaf(xr[2], w2, acc);
        acc = fmaf(xr[3], w3, acc);
        acc = fmaf(xr[4], w4, acc);
        acc = fmaf(xr[5], w5, acc);
        acc = fmaf(xr[6], w6, acc);
        float v = fmaxf(acc, 0.0f);
        __nv_bfloat16 h = __float2bfloat16(v);
        Chi[(size_t)m * HID + n] = h;
        Clo[(size_t)m * HID + n] = __float2bfloat16(v - __bfloat162float(h));
    }
}

// =================== GEMM variant 1: bf16 A, swizzled 3-stage ===============
// mode 0: Cf (+Cc) fp32 out.  mode 1: Chi/Clo bf16 split out.
// mode 2: atomic mean-pool accumulate into pooled[batch[r]*256+col].

#define TILE_SW  8192                   // 128 * 64 bytes
#define STAGE_SW (4 * TILE_SW)          // 32768 per stage (Ahi,Alo,Bhi,Blo)
#define GEMM_SMEM (3 * STAGE_SW)        // 98304 bytes, 3 stages

__device__ __forceinline__ uint32_t swz(int row, uint32_t kcol) {
    return (uint32_t)(row * 64) + (((kcol ^ ((uint32_t)(row >> 1) & 3u)) << 4));
}

__global__ __launch_bounds__(256, 2)
void mma_gemm_split(int M,
                    const uint4* __restrict__ Ahi4, const uint4* __restrict__ Alo4,
                    const uint4* __restrict__ Bhi4, const uint4* __restrict__ Blo4,
                    const float* __restrict__ bias,
                    float* __restrict__ Cf, float* __restrict__ Cc,
                    __nv_bfloat16* __restrict__ Chi,
                    __nv_bfloat16* __restrict__ Clo,
                    const int* __restrict__ batch,
                    float* __restrict__ pooled,
                    int mode) {
    extern __shared__ char smem[];
    const uint32_t sb = smem_u32(smem);

    const int tid  = threadIdx.x;
    const int wid  = tid >> 5;
    const int lane = tid & 31;
    const int wm   = wid & 1;
    const int wn   = wid >> 1;
    const int block_col = blockIdx.x * 128;
    const int block_row = blockIdx.y * 128;

    const int a_lrow = lane & 15;
    const int a_lcol = (lane >> 4) << 3;
    const int b_lrow = (lane & 7) + ((lane >> 4) & 1) * 8;
    const int b_lcol = ((lane >> 3) & 1) << 3;
    const uint32_t a_k0 = (uint32_t)(a_lcol >> 3);
    const uint32_t b_k0 = (uint32_t)(b_lcol >> 3);

    uint32_t a_rowoff[4], b_rowoff[2];
    uint32_t a_s[4], b_s[2];
#pragma unroll
    for (int f = 0; f < 4; f++) {
        int r = wm * 64 + f * 16 + a_lrow;
        a_rowoff[f] = (uint32_t)(r * 64);
        a_s[f] = (uint32_t)(r >> 1) & 3u;
    }
#pragma unroll
    for (int p = 0; p < 2; p++) {
        int r = wn * 32 + p * 16 + b_lrow;
        b_rowoff[p] = (uint32_t)(r * 64);
        b_s[p] = (uint32_t)(r >> 1) & 3u;
    }

    float acc[4][4][4];
#pragma unroll
    for (int i = 0; i < 4; i++)
#pragma unroll
        for (int j = 0; j < 4; j++)
#pragma unroll
            for (int c = 0; c < 4; c++) acc[i][j][c] = 0.0f;

    const int ldrow = tid >> 2;
    const int ldc   = tid & 3;

    auto issue = [&](int kc) {
        uint32_t sbase = sb + (uint32_t)(kc % 3) * STAGE_SW;
#pragma unroll
        for (int h = 0; h < 2; h++) {
            int row = ldrow + h * 64;
            int rg = block_row + row;
            if (rg >= M) rg = M - 1;
            size_t gA = (size_t)rg * 32 + kc * 4 + ldc;
            size_t gB = (size_t)(block_col + row) * 32 + kc * 4 + ldc;
            uint32_t so = swz(row, (uint32_t)ldc);
            cp_async16(sbase + 0 * TILE_SW + so, Ahi4 + gA);
            cp_async16(sbase + 1 * TILE_SW + so, Alo4 + gA);
            cp_async16(sbase + 2 * TILE_SW + so, Bhi4 + gB);
            cp_async16(sbase + 3 * TILE_SW + so, Blo4 + gB);
        }
        CP_COMMIT();
    };

    issue(0);
    issue(1);

    for (int kc = 0; kc < 8; kc++) {
        CP_WAIT(1);
        __syncthreads();
        if (kc < 6) issue(kc + 2);

        uint32_t base = sb + (uint32_t)(kc % 3) * STAGE_SW;
        uint32_t uAhi = base + 0 * TILE_SW;
        uint32_t uAlo = base + 1 * TILE_SW;
        uint32_t uBhi = base + 2 * TILE_SW;
        uint32_t uBlo = base + 3 * TILE_SW;

        uint32_t ah[4][4], al[4][4], bh[2][4], bl[2][4];
#pragma unroll
        for (int ks16 = 0; ks16 < 2; ks16++) {
            const uint32_t kb = (uint32_t)(ks16 * 2);
#pragma unroll
            for (int f = 0; f < 4; f++) {
                uint32_t off = a_rowoff[f] + (((a_k0 + kb) ^ a_s[f]) << 4);
                ldsm_x4(uAhi + off, ah[f]);
                ldsm_x4(uAlo + off, al[f]);
            }
#pragma unroll
            for (int p = 0; p < 2; p++) {
                uint32_t off = b_rowoff[p] + (((b_k0 + kb) ^ b_s[p]) << 4);
                ldsm_x4(uBhi + off, bh[p]);
                ldsm_x4(uBlo + off, bl[p]);
            }
#pragma unroll
            for (int mf = 0; mf < 4; mf++)
#pragma unroll
                for (int nf = 0; nf < 4; nf++) {
                    int p = nf >> 1, q = (nf & 1) * 2;
                    mma16816(acc[mf][nf], ah[mf], bh[p][q], bh[p][q + 1]);
                    mma16816(acc[mf][nf], ah[mf], bl[p][q], bl[p][q + 1]);
                    mma16816(acc[mf][nf], al[mf], bh[p][q], bh[p][q + 1]);
                }
        }
    }

    // ---- epilogue ----
#pragma unroll
    for (int mf = 0; mf < 4; mf++) {
        int r0 = block_row + wm * 64 + mf * 16 + (lane >> 2);
        int r1 = r0 + 8;
#pragma unroll
        for (int nf = 0; nf < 4; nf++) {
            int col = block_col + wn * 32 + nf * 8 + (lane & 3) * 2;
            float b0 = bias[col], b1 = bias[col + 1];
            float v00 = fmaxf(acc[mf][nf][0] + b0, 0.f);
            float v01 = fmaxf(acc[mf][nf][1] + b1, 0.f);
            float v10 = fmaxf(acc[mf][nf][2] + b0, 0.f);
            float v11 = fmaxf(acc[mf][nf][3] + b1, 0.f);
            if (mode == 0) {
                if (r0 < M) {
                    *reinterpret_cast<float2*>(&Cf[(size_t)r0 * HID + col]) =
                        make_float2(v00, v01);
                    *reinterpret_cast<float2*>(&Cc[(size_t)r0 * HID + col]) =
                        make_float2(v00, v01);
                }
                if (r1 < M) {
                    *reinterpret_cast<float2*>(&Cf[(size_t)r1 * HID + col]) =
                        make_float2(v10, v11);
                    *reinterpret_cast<float2*>(&Cc[(size_t)r1 * HID + col]) =
                        make_float2(v10, v11);
                }
            } else if (mode == 1) {
                uint32_t hp0 = pack_bf16x2(v00, v01);
                uint32_t hp1 = pack_bf16x2(v10, v11);
                float w00 = v00 - __bfloat162float(__float2bfloat16(v00));
                float w01 = v01 - __bfloat162float(__float2bfloat16(v01));
                float w10 = v10 - __bfloat162float(__float2bfloat16(v10));
                float w11 = v11 - __bfloat162float(__float2bfloat16(v11));
                uint32_t lp0 = pack_bf16x2(w00, w01);
                uint32_t lp1 = pack_bf16x2(w10, w11);
                if (r0 < M) {
                    *reinterpret_cast<uint32_t*>(Chi + (size_t)r0 * HID + col) = hp0;
                    *reinterpret_cast<uint32_t*>(Clo + (size_t)r0 * HID + col) = lp0;
                }
                if (r1 < M) {
                    *reinterpret_cast<uint32_t*>(Chi + (size_t)r1 * HID + col) = hp1;
                    *reinterpret_cast<uint32_t*>(Clo + (size_t)r1 * HID + col) = lp1;
                }
            } else {
                // mode 2: mean-pool accumulate
                if (r0 < M) {
                    float* pd = pooled + (size_t)batch[r0] * HID + col;
                    atomicAdd(pd + 0, v00);
                    atomicAdd(pd + 1, v01);
                }
                if (r1 < M) {
                    float* pd = pooled + (size_t)batch[r1] * HID + col;
                    atomicAdd(pd + 0, v10);
                    atomicAdd(pd + 1, v11);
                }
            }
        }
    }
}

// =================== GEMM variant 2: fp32 A, in-kernel split, 3-stage =======

#define F_A32_STG 16384
#define F_B_OFF   (3 * F_A32_STG)
#define F_B_STG   (2 * TILE_SW)
#define F_AHI     (F_B_OFF + 3 * F_B_STG)
#define F_ALO     (F_AHI + TILE_SW)
#define F_SMEM    (F_ALO + TILE_SW)

__global__ __launch_bounds__(256, 2)
void mma_gemm_split_f32a(int M,
                         const float* __restrict__ Af,
                         const uint4* __restrict__ Bhi4,
                         const uint4* __restrict__ Blo4,
                         const float* __restrict__ bias,
                         __nv_bfloat16* __restrict__ Chi,
                         __nv_bfloat16* __restrict__ Clo) {
    extern __shared__ char smem[];
    const uint32_t sb = smem_u32(smem);

    const int tid  = threadIdx.x;
    const int wid  = tid >> 5;
    const int lane = tid & 31;
    const int wm   = wid & 1;
    const int wn   = wid >> 1;
    const int block_col = blockIdx.x * 128;
    const int block_row = blockIdx.y * 128;

    const int a_lrow = lane & 15;
    const int a_lcol = (lane >> 4) << 3;
    const int b_lrow = (lane & 7) + ((lane >> 4) & 1) * 8;
    const int b_lcol = ((lane >> 3) & 1) << 3;
    const uint32_t a_k0 = (uint32_t)(a_lcol >> 3);
    const uint32_t b_k0 = (uint32_t)(b_lcol >> 3);

    uint32_t a_rowoff[4], b_rowoff[2];
    uint32_t a_s[4], b_s[2];
#pragma unroll
    for (int f = 0; f < 4; f++) {
        int r = wm * 64 + f * 16 + a_lrow;
        a_rowoff[f] = (uint32_t)(r * 64);
        a_s[f] = (uint32_t)(r >> 1) & 3u;
    }
#pragma unroll
    for (int p = 0; p < 2; p++) {
        int r = wn * 32 + p * 16 + b_lrow;
        b_rowoff[p] = (uint32_t)(r * 64);
        b_s[p] = (uint32_t)(r >> 1) & 3u;
    }

    float acc[4][4][4];
#pragma unroll
    for (int i = 0; i < 4; i++)
#pragma unroll
        for (int j = 0; j < 4; j++)
#pragma unroll
            for (int c = 0; c < 4; c++) acc[i][j][c] = 0.0f;

    const int ldrow = tid >> 2;
    const int ldc   = tid & 3;
    const int crow  = tid >> 1;
    const int chalf = tid & 1;

    auto issue = [&](int kc) {
        int s = kc % 3;
#pragma unroll
        for (int i = 0; i < 4; i++) {
            int idx = tid + i * 256;
            int row = idx >> 3, c = idx & 7;
            int rg = block_row + row;
            if (rg >= M) rg = M - 1;
            const float* g = Af + (size_t)rg * 256 + kc * 32 + c * 4;
            uint32_t so = (uint32_t)(row * 128) +
                          (((uint32_t)(c ^ (row & 7))) << 4);
            cp_async16(sb + (uint32_t)(s * F_A32_STG) + so, g);
        }
        uint32_t bbase = sb + F_B_OFF + (uint32_t)s * F_B_STG;
#pragma unroll
        for (int h = 0; h < 2; h++) {
            int row = ldrow + h * 64;
            size_t gB = (size_t)(block_col + row) * 32 + kc * 4 + ldc;
            uint32_t so = swz(row, (uint32_t)ldc);
            cp_async16(bbase + so, Bhi4 + gB);
            cp_async16(bbase + TILE_SW + so, Blo4 + gB);
        }
        CP_COMMIT();
    };

    issue(0);
    issue(1);

    for (int kc = 0; kc < 8; kc++) {
        CP_WAIT(1);
        __syncthreads();
        if (kc < 6) issue(kc + 2);

        {
            const char* afb = smem + (kc % 3) * F_A32_STG + crow * 128;
            uint32_t rs = (uint32_t)(crow & 7);
            float4 v0 = *reinterpret_cast<const float4*>(
                afb + (((uint32_t)(chalf * 4 + 0) ^ rs) << 4));
            float4 v1 = *reinterpret_cast<const float4*>(
                afb + (((uint32_t)(chalf * 4 + 1) ^ rs) << 4));
            float4 v2 = *reinterpret_cast<const float4*>(
                afb + (((uint32_t)(chalf * 4 + 2) ^ rs) << 4));
            float4 v3 = *reinterpret_cast<const float4*>(
                afb + (((uint32_t)(chalf * 4 + 3) ^ rs) << 4));
            uint4 H0, H1, L0, L1;
            H0.x = pack_bf16x2(v0.x, v0.y); H0.y = pack_bf16x2(v0.z, v0.w);
            H0.z = pack_bf16x2(v1.x, v1.y); H0.w = pack_bf16x2(v1.z, v1.w);
            H1.x = pack_bf16x2(v2.x, v2.y); H1.y = pack_bf16x2(v2.z, v2.w);
            H1.z = pack_bf16x2(v3.x, v3.y); H1.w = pack_bf16x2(v3.z, v3.w);
            L0.x = pack_bf16x2(v0.x - __bfloat162float(__float2bfloat16(v0.x)),
                               v0.y - __bfloat162float(__float2bfloat16(v0.y)));
            L0.y = pack_bf16x2(v0.z - __bfloat162float(__float2bfloat16(v0.z)),
                               v0.w - __bfloat162float(__float2bfloat16(v0.w)));
            L0.z = pack_bf16x2(v1.x - __bfloat162float(__float2bfloat16(v1.x)),
                               v1.y - __bfloat162float(__float2bfloat16(v1.y)));
            L0.w = pack_bf16x2(v1.z - __bfloat162float(__float2bfloat16(v1.z)),
                               v1.w - __bfloat162float(__float2bfloat16(v1.w)));
            L1.x = pack_bf16x2(v2.x - __bfloat162float(__float2bfloat16(v2.x)),
                               v2.y - __bfloat162float(__float2bfloat16(v2.y)));
            L1.y = pack_bf16x2(v2.z - __bfloat162float(__float2bfloat16(v2.z)),
                               v2.w - __bfloat162float(__float2bfloat16(v2.w)));
            L1.z = pack_bf16x2(v3.x - __bfloat162float(__float2bfloat16(v3.x)),
                               v3.y - __bfloat162float(__float2bfloat16(v3.y)));
            L1.w = pack_bf16x2(v3.z - __bfloat162float(__float2bfloat16(v3.z)),
                               v3.w - __bfloat162float(__float2bfloat16(v3.w)));
            uint32_t cs = (uint32_t)(crow >> 1) & 3u;
            uint32_t g0 = ((uint32_t)(chalf * 2 + 0) ^ cs) << 4;
            uint32_t g1 = ((uint32_t)(chalf * 2 + 1) ^ cs) << 4;
            char* ah = smem + F_AHI + crow * 64;
            char* al = smem + F_ALO + crow * 64;
            *reinterpret_cast<uint4*>(ah + g0) = H0;
            *reinterpret_cast<uint4*>(ah + g1) = H1;
            *reinterpret_cast<uint4*>(al + g0) = L0;
            *reinterpret_cast<uint4*>(al + g1) = L1;
        }
        __syncthreads();

        uint32_t uAhi = sb + F_AHI;
        uint32_t uAlo = sb + F_ALO;
        uint32_t uBhi = sb + F_B_OFF + (uint32_t)(kc % 3) * F_B_STG;
        uint32_t uBlo = uBhi + TILE_SW;

        uint32_t ah[4][4], al[4][4], bh[2][4], bl[2][4];
#pragma unroll
        for (int ks16 = 0; ks16 < 2; ks16++) {
            const uint32_t kb = (uint32_t)(ks16 * 2);
#pragma unroll
            for (int f = 0; f < 4; f++) {
                uint32_t off = a_rowoff[f] + (((a_k0 + kb) ^ a_s[f]) << 4);
                ldsm_x4(uAhi + off, ah[f]);
                ldsm_x4(uAlo + off, al[f]);
            }
#pragma unroll
            for (int p = 0; p < 2; p++) {
                uint32_t off = b_rowoff[p] + (((b_k0 + kb) ^ b_s[p]) << 4);
                ldsm_x4(uBhi + off, bh[p]);
                ldsm_x4(uBlo + off, bl[p]);
            }
#pragma unroll
            for (int mf = 0; mf < 4; mf++)
#pragma unroll
                for (int nf = 0; nf < 4; nf++) {
                    int p = nf >> 1, q = (nf & 1) * 2;
                    mma16816(acc[mf][nf], ah[mf], bh[p][q], bh[p][q + 1]);
                    mma16816(acc[mf][nf], ah[mf], bl[p][q], bl[p][q + 1]);
                    mma16816(acc[mf][nf], al[mf], bh[p][q], bh[p][q + 1]);
                }
        }
    }

#pragma unroll
    for (int mf = 0; mf < 4; mf++) {
        int r0 = block_row + wm * 64 + mf * 16 + (lane >> 2);
        int r1 = r0 + 8;
#pragma unroll
        for (int nf = 0; nf < 4; nf++) {
            int col = block_col + wn * 32 + nf * 8 + (lane & 3) * 2;
            float b0 = bias[col], b1 = bias[col + 1];
            float v00 = fmaxf(acc[mf][nf][0] + b0, 0.f);
            float v01 = fmaxf(acc[mf][nf][1] + b1, 0.f);
            float v10 = fmaxf(acc[mf][nf][2] + b0, 0.f);
            float v11 = fmaxf(acc[mf][nf][3] + b1, 0.f);
            uint32_t hp0 = pack_bf16x2(v00, v01);
            uint32_t hp1 = pack_bf16x2(v10, v11);
            float w00 = v00 - __bfloat162float(__float2bfloat16(v00));
            float w01 = v01 - __bfloat162float(__float2bfloat16(v01));
            float w10 = v10 - __bfloat162float(__float2bfloat16(v10));
            float w11 = v11 - __bfloat162float(__float2bfloat16(v11));
            uint32_t lp0 = pack_bf16x2(w00, w01);
            uint32_t lp1 = pack_bf16x2(w10, w11);
            if (r0 < M) {
                *reinterpret_cast<uint32_t*>(Chi + (size_t)r0 * HID + col) = hp0;
                *reinterpret_cast<uint32_t*>(Clo + (size_t)r0 * HID + col) = lp0;
            }
            if (r1 < M) {
                *reinterpret_cast<uint32_t*>(Chi + (size_t)r1 * HID + col) = hp1;
                *reinterpret_cast<uint32_t*>(Clo + (size_t)r1 * HID + col) = lp1;
            }
        }
    }
}

// =================== fp32 tiled SGEMM (small head GEMM) =====================

__global__ __launch_bounds__(256)
void sgemm_bias_relu(int M, const float* __restrict__ A,
                     const float* __restrict__ B,
                     const float* __restrict__ bias,
                     float* __restrict__ C,
                     int N, int K, int doRelu) {
    __shared__ float As[8][128];
    __shared__ float Bs[8][128];

    const int tid       = threadIdx.x;
    const int block_row = blockIdx.y * 128;
    const int block_col = blockIdx.x * 128;

    const int aRow = tid >> 1;
    const int aCol = (tid & 1) << 2;
    const int bRow = tid >> 5;
    const int bCol = (tid & 31) << 2;
    const int trow = (tid >> 4) << 3;
    const int tcol = (tid & 15) << 3;

    float acc[8][8];
#pragma unroll
    for (int i = 0; i < 8; i++)
#pragma unroll
        for (int j = 0; j < 8; j++) acc[i][j] = 0.0f;

    for (int kt = 0; kt < K; kt += 8) {
        float4 av = make_float4(0.f, 0.f, 0.f, 0.f);
        if (block_row + aRow < M)
            av = *reinterpret_cast<const float4*>(&A[(size_t)(block_row + aRow) * K + kt + aCol]);
        As[aCol + 0][aRow] = av.x;
        As[aCol + 1][aRow] = av.y;
        As[aCol + 2][aRow] = av.z;
        As[aCol + 3][aRow] = av.w;

        float4 bv = *reinterpret_cast<const float4*>(&B[(size_t)(kt + bRow) * N + block_col + bCol]);
        *reinterpret_cast<float4*>(&Bs[bRow][bCol]) = bv;
        __syncthreads();

#pragma unroll
        for (int k = 0; k < 8; k++) {
            float ra[8], rb[8];
#pragma unroll
            for (int i = 0; i < 8; i++) ra[i] = As[k][trow + i];
#pragma unroll
            for (int j = 0; j < 8; j++) rb[j] = Bs[k][tcol + j];
#pragma unroll
            for (int i = 0; i < 8; i++)
#pragma unroll
                for (int j = 0; j < 8; j++)
                    acc[i][j] = fmaf(ra[i], rb[j], acc[i][j]);
        }
        __syncthreads();
    }

#pragma unroll
    for (int i = 0; i < 8; i++) {
        int r = block_row + trow + i;
        if (r < M) {
#pragma unroll
            for (int j = 0; j < 8; j += 4) {
                float4 v;
                v.x = acc[i][j + 0] + bias[block_col + tcol + j + 0];
                v.y = acc[i][j + 1] + bias[block_col + tcol + j + 1];
                v.z = acc[i][j + 2] + bias[block_col + tcol + j + 2];
                v.w = acc[i][j + 3] + bias[block_col + tcol + j + 3];
                if (doRelu) {
                    v.x = fmaxf(v.x, 0.f); v.y = fmaxf(v.y, 0.f);
                    v.z = fmaxf(v.z, 0.f); v.w = fmaxf(v.w, 0.f);
                }
                *reinterpret_cast<float4*>(&C[(size_t)r * N + block_col + tcol + j]) = v;
            }
        }
    }
}

// ============================ pool finalize + head ==========================

__global__ void pool_div(float* __restrict__ pooled,
                         const float* __restrict__ counts) {
    int i = blockIdx.x * blockDim.x + threadIdx.x;
    float c = counts[i >> 8];
    pooled[i] = pooled[i] / fmaxf(c, 1.0f);
}

__global__ void head_final(const float* __restrict__ hid,
                           const float* __restrict__ W,
                           const float* __restrict__ b,
                           float* __restrict__ out) {
    int m = blockIdx.x * blockDim.x + threadIdx.x;
    if (m >= N_GRAPHS) return;
    float a0 = b[0], a1 = b[1], a2 = b[2];
    const float* hs = hid + (size_t)m * 128;
#pragma unroll 8
    for (int k = 0; k < 128; k++) {
        float h = hs[k];
        a0 = fmaf(h, W[k * 3 + 0], a0);
        a1 = fmaf(h, W[k * 3 + 1], a1);
        a2 = fmaf(h, W[k * 3 + 2], a2);
    }
    out[m * 3 + 0] = a0;
    out[m * 3 + 1] = a1;
    out[m * 3 + 2] = a2;
}

// ============================ launch ========================================

extern "C" void kernel_launch(void* const* d_in, const int* in_sizes, int n_in,
                              void* d_out, int out_size) {
    const float* x     = (const float*)d_in[0];
    const int*   ei    = (const int*)d_in[1];
    const int*   batch = (const int*)d_in[2];

    const float* Wa[4], *ba[4], *Wb[4], *bb[4];
    for (int l = 0; l < 4; l++) {
        Wa[l] = (const float*)d_in[3 + 4 * l + 0];
        ba[l] = (const float*)d_in[3 + 4 * l + 1];
        Wb[l] = (const float*)d_in[3 + 4 * l + 2];
        bb[l] = (const float*)d_in[3 + 4 * l + 3];
    }
    const float* Wh1 = (const float*)d_in[19];
    const float* bh1 = (const float*)d_in[20];
    const float* Wh2 = (const float*)d_in[21];
    const float* bh2 = (const float*)d_in[22];
    float* out = (float*)d_out;

    __nv_bfloat16 *A2hi, *A2lo, *Whi, *Wlo;
    float *bufB, *bufC, *agg7, *pooled, *counts, *hid;
    cudaGetSymbolAddress((void**)&A2hi,   g_A2hi);
    cudaGetSymbolAddress((void**)&A2lo,   g_A2lo);
    cudaGetSymbolAddress((void**)&Whi,    g_Whi);
    cudaGetSymbolAddress((void**)&Wlo,    g_Wlo);
    cudaGetSymbolAddress((void**)&bufB,   g_bufB);
    cudaGetSymbolAddress((void**)&bufC,   g_bufC);
    cudaGetSymbolAddress((void**)&agg7,   g_agg7);
    cudaGetSymbolAddress((void**)&pooled, g_pooled);
    cudaGetSymbolAddress((void**)&counts, g_counts);
    cudaGetSymbolAddress((void**)&hid,    g_hid);

    cudaFuncSetAttribute(mma_gemm_split,
                         cudaFuncAttributeMaxDynamicSharedMemorySize, GEMM_SMEM);
    cudaFuncSetAttribute(mma_gemm_split_f32a,
                         cudaFuncAttributeMaxDynamicSharedMemorySize, F_SMEM);

    // ---- prologue: weights, counts, pooled init ----
    dim3 cw_grid(HID, 7);
    convert_weight_all<<<cw_grid, HID>>>(Wb[0], Wa[1], Wb[1], Wa[2], Wb[2],
                                         Wa[3], Wb[3], Whi, Wlo);
    cudaMemsetAsync(pooled, 0, (size_t)N_GRAPHS * HID * sizeof(float));
    cudaMemsetAsync(counts, 0, (size_t)N_GRAPHS * sizeof(float));
    count_kernel<<<(N_NODES + 255) / 256, 256>>>(batch, counts);

    dim3 mma_grid(2, (N_NODES + 127) / 128);

    // ---- layer 1 ----
    cudaMemcpyAsync(agg7, x, (size_t)N_NODES * 7 * sizeof(float),
                    cudaMemcpyDeviceToDevice);
    scatter_add_7<<<(N_EDGES + 255) / 256, 256>>>(x, ei, agg7);
    gemm_k7_relu_split<<<K7_BLOCKS, 256>>>(agg7, Wa[0], ba[0], A2hi, A2lo);
    mma_gemm_split<<<mma_grid, 256, GEMM_SMEM>>>(
        N_NODES, (const uint4*)A2hi, (const uint4*)A2lo,
        (const uint4*)Whi, (const uint4*)Wlo,
        bb[0], bufB, bufC, nullptr, nullptr, nullptr, nullptr, 0);

    // ---- layers 2..4 ----
    for (int l = 1; l < 4; l++) {
        scatter_add_256<<<((size_t)N_EDGES * 32 + 255) / 256, 256>>>(bufB, ei, bufC);
        mma_gemm_split_f32a<<<mma_grid, 256, F_SMEM>>>(
            N_NODES, bufC,
            (const uint4*)(Whi + (size_t)(2 * l - 1) * HID * HID),
            (const uint4*)(Wlo + (size_t)(2 * l - 1) * HID * HID),
            ba[l], A2hi, A2lo);
        if (l < 3) {
            mma_gemm_split<<<mma_grid, 256, GEMM_SMEM>>>(
                N_NODES, (const uint4*)A2hi, (const uint4*)A2lo,
                (const uint4*)(Whi + (size_t)(2 * l) * HID * HID),
                (const uint4*)(Wlo + (size_t)(2 * l) * HID * HID),
                bb[l], bufB, bufC, nullptr, nullptr, nullptr, nullptr, 0);
        } else {
            // final layer: fuse mean-pool accumulation into epilogue
            mma_gemm_split<<<mma_grid, 256, GEMM_SMEM>>>(
                N_NODES, (const uint4*)A2hi, (const uint4*)A2lo,
                (const uint4*)(Whi + (size_t)(2 * l) * HID * HID),
                (const uint4*)(Wlo + (size_t)(2 * l) * HID * HID),
                bb[l], nullptr, nullptr, nullptr, nullptr, batch, pooled, 2);
        }
    }

    // ---- pool finalize ----
    pool_div<<<N_GRAPHS * HID / 256, 256>>>(pooled, counts);

    // ---- head ----
    dim3 head_grid(1, (N_GRAPHS + 127) / 128);
    sgemm_bias_relu<<<head_grid, 256>>>(N_GRAPHS, pooled, Wh1, bh1, hid,
                                        128, 256, 1);
    head_final<<<(N_GRAPHS + 255) / 256, 256>>>(hid, Wh2, bh2, out);
}

// round 11
// speedup vs baseline: 2.5865x; 1.0276x over previous
#include <cuda_runtime.h>
#include <cuda_bf16.h>
#include <cstdint>

#define N_NODES  150000
#define N_EDGES  300000
#define N_GRAPHS 6000
#define HID      256

// ============================ mma.sync helpers ==============================

__device__ __forceinline__ uint32_t smem_u32(const void* p) {
    uint32_t addr;
    asm("{ .reg .u64 tmp; cvta.to.shared.u64 tmp, %1; cvt.u32.u64 %0, tmp; }"
        : "=r"(addr) : "l"(p));
    return addr;
}

__device__ __forceinline__ void ldsm_x4(uint32_t addr, uint32_t* r) {
    asm volatile("ldmatrix.sync.aligned.m8n8.x4.shared.b16 {%0,%1,%2,%3}, [%4];"
                 : "=r"(r[0]), "=r"(r[1]), "=r"(r[2]), "=r"(r[3]) : "r"(addr));
}

__device__ __forceinline__ void mma16816(float* d, const uint32_t* a,
                                         uint32_t b0, uint32_t b1) {
    asm volatile(
        "mma.sync.aligned.m16n8k16.row.col.f32.bf16.bf16.f32 "
        "{%0,%1,%2,%3}, {%4,%5,%6,%7}, {%8,%9}, {%0,%1,%2,%3};"
        : "+f"(d[0]), "+f"(d[1]), "+f"(d[2]), "+f"(d[3])
        : "r"(a[0]), "r"(a[1]), "r"(a[2]), "r"(a[3]), "r"(b0), "r"(b1));
}

__device__ __forceinline__ void cp_async16(uint32_t smem_addr, const void* g) {
    asm volatile("cp.async.cg.shared.global [%0], [%1], 16;"
                 :: "r"(smem_addr), "l"(g));
}
#define CP_COMMIT() asm volatile("cp.async.commit_group;" ::: "memory")
#define CP_WAIT(n)  asm volatile("cp.async.wait_group %0;" :: "n"(n) : "memory")

__device__ __forceinline__ uint32_t pack_bf16x2(float a, float b) {
    __nv_bfloat16 ha = __float2bfloat16(a);
    __nv_bfloat16 hb = __float2bfloat16(b);
    return ((uint32_t)__bfloat16_as_ushort(hb) << 16) | __bfloat16_as_ushort(ha);
}

// ============================ scratch buffers ===============================

__device__ __nv_bfloat16 g_A2hi[(size_t)N_NODES * HID];
__device__ __nv_bfloat16 g_A2lo[(size_t)N_NODES * HID];
__device__ float g_bufB[(size_t)N_NODES * HID];   // layer output h (gather src)
__device__ float g_bufC[(size_t)N_NODES * HID];   // scatter accumulator (init h)
__device__ float g_agg7[N_NODES * 7];
__device__ __nv_bfloat16 g_Whi[7 * HID * HID];    // weights, [N][K] bf16 hi
__device__ __nv_bfloat16 g_Wlo[7 * HID * HID];    // weights, [N][K] bf16 lo
__device__ float g_pooled[N_GRAPHS * HID];
__device__ float g_counts[N_GRAPHS];
__device__ float g_hid[N_GRAPHS * 128];

// ============================ small kernels =================================

__global__ void convert_weight_all(const float* __restrict__ W0,
                                   const float* __restrict__ W1,
                                   const float* __restrict__ W2,
                                   const float* __restrict__ W3,
                                   const float* __restrict__ W4,
                                   const float* __restrict__ W5,
                                   const float* __restrict__ W6,
                                   __nv_bfloat16* __restrict__ Whi,
                                   __nv_bfloat16* __restrict__ Wlo) {
    int w = blockIdx.y;
    const float* W = (w == 0) ? W0 : (w == 1) ? W1 : (w == 2) ? W2 :
                     (w == 3) ? W3 : (w == 4) ? W4 : (w == 5) ? W5 : W6;
    int n = blockIdx.x;   // 256
    int k = threadIdx.x;  // 256
    float v = W[k * HID + n];
    __nv_bfloat16 h = __float2bfloat16(v);
    size_t o = (size_t)w * HID * HID + n * HID + k;
    Whi[o] = h;
    Wlo[o] = __float2bfloat16(v - __bfloat162float(h));
}

__global__ void count_kernel(const int* __restrict__ batch,
                             float* __restrict__ counts) {
    int i = blockIdx.x * blockDim.x + threadIdx.x;
    if (i >= N_NODES) return;
    atomicAdd(&counts[batch[i]], 1.0f);
}

__global__ void scatter_add_7(const float* __restrict__ x,
                              const int* __restrict__ ei,
                              float* __restrict__ agg) {
    int e = blockIdx.x * blockDim.x + threadIdx.x;
    if (e >= N_EDGES) return;
    int s = ei[e];
    int d = ei[N_EDGES + e];
#pragma unroll
    for (int j = 0; j < 7; j++)
        atomicAdd(&agg[(size_t)d * 7 + j], x[(size_t)s * 7 + j]);
}

__global__ void scatter_add_256(const float* __restrict__ x,
                                const int* __restrict__ ei,
                                float* __restrict__ agg) {
    int gw   = (blockIdx.x * blockDim.x + threadIdx.x) >> 5;
    int lane = threadIdx.x & 31;
    if (gw >= N_EDGES) return;
    int s = ei[gw];
    int d = ei[N_EDGES + gw];
    const float* xs = x + (size_t)s * HID;
    float* ad = agg + (size_t)d * HID;
#pragma unroll
    for (int j = 0; j < 8; j++)
        atomicAdd(ad + lane + 32 * j, xs[lane + 32 * j]);
}

// layer-1 first GEMM (K=7): 64 threads per node, 4 cols/thread, uint2 stores
#define K7_BLOCKS 1184
__global__ void gemm_k7_relu_split(const float* __restrict__ A,
                                   const float* __restrict__ W,
                                   const float* __restrict__ bias,
                                   __nv_bfloat16* __restrict__ Chi,
                                   __nv_bfloat16* __restrict__ Clo) {
    const int grp = threadIdx.x >> 6;         // 0..3 (node sub-group)
    const int c4  = (threadIdx.x & 63) << 2;  // column base (0,4,...,252)

    float w[7][4];
#pragma unroll
    for (int j = 0; j < 7; j++) {
        float4 wv = *reinterpret_cast<const float4*>(&W[j * HID + c4]);
        w[j][0] = wv.x; w[j][1] = wv.y; w[j][2] = wv.z; w[j][3] = wv.w;
    }
    float4 bv = *reinterpret_cast<const float4*>(&bias[c4]);
    float bi[4] = {bv.x, bv.y, bv.z, bv.w};

    for (int m = blockIdx.x * 4 + grp; m < N_NODES; m += K7_BLOCKS * 4) {
        const float* xr = A + (size_t)m * 7;
        float x0 = xr[0], x1 = xr[1], x2 = xr[2], x3 = xr[3];
        float x4 = xr[4], x5 = xr[5], x6 = xr[6];
        float acc[4];
#pragma unroll
        for (int i = 0; i < 4; i++) {
            float a = bi[i];
            a = fmaf(x0, w[0][i], a);
            a = fmaf(x1, w[1][i], a);
            a = fmaf(x2, w[2][i], a);
            a = fmaf(x3, w[3][i], a);
            a = fmaf(x4, w[4][i], a);
            a = fmaf(x5, w[5][i], a);
            a = fmaf(x6, w[6][i], a);
            acc[i] = fmaxf(a, 0.0f);
        }
        uint2 hp, lp;
        hp.x = pack_bf16x2(acc[0], acc[1]);
        hp.y = pack_bf16x2(acc[2], acc[3]);
        lp.x = pack_bf16x2(acc[0] - __bfloat162float(__float2bfloat16(acc[0])),
                           acc[1] - __bfloat162float(__float2bfloat16(acc[1])));
        lp.y = pack_bf16x2(acc[2] - __bfloat162float(__float2bfloat16(acc[2])),
                           acc[3] - __bfloat162float(__float2bfloat16(acc[3])));
        *reinterpret_cast<uint2*>(Chi + (size_t)m * HID + c4) = hp;
        *reinterpret_cast<uint2*>(Clo + (size_t)m * HID + c4) = lp;
    }
}

// =================== GEMM variant 1: bf16 A, swizzled 3-stage ===============
// mode 0: Cf (+Cc) fp32 out.  mode 1: Chi/Clo bf16 split out.
// mode 2: atomic mean-pool accumulate into pooled[batch[r]*256+col].

#define TILE_SW  8192                   // 128 * 64 bytes
#define STAGE_SW (4 * TILE_SW)          // 32768 per stage (Ahi,Alo,Bhi,Blo)
#define GEMM_SMEM (3 * STAGE_SW)        // 98304 bytes, 3 stages

__device__ __forceinline__ uint32_t swz(int row, uint32_t kcol) {
    return (uint32_t)(row * 64) + (((kcol ^ ((uint32_t)(row >> 1) & 3u)) << 4));
}

__global__ __launch_bounds__(256, 2)
void mma_gemm_split(int M,
                    const uint4* __restrict__ Ahi4, const uint4* __restrict__ Alo4,
                    const uint4* __restrict__ Bhi4, const uint4* __restrict__ Blo4,
                    const float* __restrict__ bias,
                    float* __restrict__ Cf, float* __restrict__ Cc,
                    __nv_bfloat16* __restrict__ Chi,
                    __nv_bfloat16* __restrict__ Clo,
                    const int* __restrict__ batch,
                    float* __restrict__ pooled,
                    int mode) {
    extern __shared__ char smem[];
    const uint32_t sb = smem_u32(smem);

    const int tid  = threadIdx.x;
    const int wid  = tid >> 5;
    const int lane = tid & 31;
    const int wm   = wid & 1;
    const int wn   = wid >> 1;
    const int block_col = blockIdx.x * 128;
    const int block_row = blockIdx.y * 128;

    const int a_lrow = lane & 15;
    const int a_lcol = (lane >> 4) << 3;
    const int b_lrow = (lane & 7) + ((lane >> 4) & 1) * 8;
    const int b_lcol = ((lane >> 3) & 1) << 3;
    const uint32_t a_k0 = (uint32_t)(a_lcol >> 3);
    const uint32_t b_k0 = (uint32_t)(b_lcol >> 3);

    uint32_t a_rowoff[4], b_rowoff[2];
    uint32_t a_s[4], b_s[2];
#pragma unroll
    for (int f = 0; f < 4; f++) {
        int r = wm * 64 + f * 16 + a_lrow;
        a_rowoff[f] = (uint32_t)(r * 64);
        a_s[f] = (uint32_t)(r >> 1) & 3u;
    }
#pragma unroll
    for (int p = 0; p < 2; p++) {
        int r = wn * 32 + p * 16 + b_lrow;
        b_rowoff[p] = (uint32_t)(r * 64);
        b_s[p] = (uint32_t)(r >> 1) & 3u;
    }

    float acc[4][4][4];
#pragma unroll
    for (int i = 0; i < 4; i++)
#pragma unroll
        for (int j = 0; j < 4; j++)
#pragma unroll
            for (int c = 0; c < 4; c++) acc[i][j][c] = 0.0f;

    const int ldrow = tid >> 2;
    const int ldc   = tid & 3;

    auto issue = [&](int kc) {
        uint32_t sbase = sb + (uint32_t)(kc % 3) * STAGE_SW;
#pragma unroll
        for (int h = 0; h < 2; h++) {
            int row = ldrow + h * 64;
            int rg = block_row + row;
            if (rg >= M) rg = M - 1;
            size_t gA = (size_t)rg * 32 + kc * 4 + ldc;
            size_t gB = (size_t)(block_col + row) * 32 + kc * 4 + ldc;
            uint32_t so = swz(row, (uint32_t)ldc);
            cp_async16(sbase + 0 * TILE_SW + so, Ahi4 + gA);
            cp_async16(sbase + 1 * TILE_SW + so, Alo4 + gA);
            cp_async16(sbase + 2 * TILE_SW + so, Bhi4 + gB);
            cp_async16(sbase + 3 * TILE_SW + so, Blo4 + gB);
        }
        CP_COMMIT();
    };

    issue(0);
    issue(1);

    for (int kc = 0; kc < 8; kc++) {
        CP_WAIT(1);
        __syncthreads();
        if (kc < 6) issue(kc + 2);

        uint32_t base = sb + (uint32_t)(kc % 3) * STAGE_SW;
        uint32_t uAhi = base + 0 * TILE_SW;
        uint32_t uAlo = base + 1 * TILE_SW;
        uint32_t uBhi = base + 2 * TILE_SW;
        uint32_t uBlo = base + 3 * TILE_SW;

        uint32_t ah[4][4], al[4][4], bh[2][4], bl[2][4];
#pragma unroll
        for (int ks16 = 0; ks16 < 2; ks16++) {
            const uint32_t kb = (uint32_t)(ks16 * 2);
#pragma unroll
            for (int f = 0; f < 4; f++) {
                uint32_t off = a_rowoff[f] + (((a_k0 + kb) ^ a_s[f]) << 4);
                ldsm_x4(uAhi + off, ah[f]);
                ldsm_x4(uAlo + off, al[f]);
            }
#pragma unroll
            for (int p = 0; p < 2; p++) {
                uint32_t off = b_rowoff[p] + (((b_k0 + kb) ^ b_s[p]) << 4);
                ldsm_x4(uBhi + off, bh[p]);
                ldsm_x4(uBlo + off, bl[p]);
            }
#pragma unroll
            for (int mf = 0; mf < 4; mf++)
#pragma unroll
                for (int nf = 0; nf < 4; nf++) {
                    int p = nf >> 1, q = (nf & 1) * 2;
                    mma16816(acc[mf][nf], ah[mf], bh[p][q], bh[p][q + 1]);
                    mma16816(acc[mf][nf], ah[mf], bl[p][q], bl[p][q + 1]);
                    mma16816(acc[mf][nf], al[mf], bh[p][q], bh[p][q + 1]);
                }
        }
    }

    // ---- epilogue ----
#pragma unroll
    for (int mf = 0; mf < 4; mf++) {
        int r0 = block_row + wm * 64 + mf * 16 + (lane >> 2);
        int r1 = r0 + 8;
#pragma unroll
        for (int nf = 0; nf < 4; nf++) {
            int col = block_col + wn * 32 + nf * 8 + (lane & 3) * 2;
            float b0 = bias[col], b1 = bias[col + 1];
            float v00 = fmaxf(acc[mf][nf][0] + b0, 0.f);
            float v01 = fmaxf(acc[mf][nf][1] + b1, 0.f);
            float v10 = fmaxf(acc[mf][nf][2] + b0, 0.f);
            float v11 = fmaxf(acc[mf][nf][3] + b1, 0.f);
            if (mode == 0) {
                if (r0 < M) {
                    *reinterpret_cast<float2*>(&Cf[(size_t)r0 * HID + col]) =
                        make_float2(v00, v01);
                    *reinterpret_cast<float2*>(&Cc[(size_t)r0 * HID + col]) =
                        make_float2(v00, v01);
                }
                if (r1 < M) {
                    *reinterpret_cast<float2*>(&Cf[(size_t)r1 * HID + col]) =
                        make_float2(v10, v11);
                    *reinterpret_cast<float2*>(&Cc[(size_t)r1 * HID + col]) =
                        make_float2(v10, v11);
                }
            } else if (mode == 1) {
                uint32_t hp0 = pack_bf16x2(v00, v01);
                uint32_t hp1 = pack_bf16x2(v10, v11);
                float w00 = v00 - __bfloat162float(__float2bfloat16(v00));
                float w01 = v01 - __bfloat162float(__float2bfloat16(v01));
                float w10 = v10 - __bfloat162float(__float2bfloat16(v10));
                float w11 = v11 - __bfloat162float(__float2bfloat16(v11));
                uint32_t lp0 = pack_bf16x2(w00, w01);
                uint32_t lp1 = pack_bf16x2(w10, w11);
                if (r0 < M) {
                    *reinterpret_cast<uint32_t*>(Chi + (size_t)r0 * HID + col) = hp0;
                    *reinterpret_cast<uint32_t*>(Clo + (size_t)r0 * HID + col) = lp0;
                }
                if (r1 < M) {
                    *reinterpret_cast<uint32_t*>(Chi + (size_t)r1 * HID + col) = hp1;
                    *reinterpret_cast<uint32_t*>(Clo + (size_t)r1 * HID + col) = lp1;
                }
            } else {
                if (r0 < M) {
                    float* pd = pooled + (size_t)batch[r0] * HID + col;
                    atomicAdd(pd + 0, v00);
                    atomicAdd(pd + 1, v01);
                }
                if (r1 < M) {
                    float* pd = pooled + (size_t)batch[r1] * HID + col;
                    atomicAdd(pd + 0, v10);
                    atomicAdd(pd + 1, v11);
                }
            }
        }
    }
}

// =================== GEMM variant 2: fp32 A, in-kernel split, 3-stage =======

#define F_A32_STG 16384
#define F_B_OFF   (3 * F_A32_STG)
#define F_B_STG   (2 * TILE_SW)
#define F_AHI     (F_B_OFF + 3 * F_B_STG)
#define F_ALO     (F_AHI + TILE_SW)
#define F_SMEM    (F_ALO + TILE_SW)

__global__ __launch_bounds__(256, 2)
void mma_gemm_split_f32a(int M,
                         const float* __restrict__ Af,
                         const uint4* __restrict__ Bhi4,
                         const uint4* __restrict__ Blo4,
                         const float* __restrict__ bias,
                         __nv_bfloat16* __restrict__ Chi,
                         __nv_bfloat16* __restrict__ Clo) {
    extern __shared__ char smem[];
    const uint32_t sb = smem_u32(smem);

    const int tid  = threadIdx.x;
    const int wid  = tid >> 5;
    const int lane = tid & 31;
    const int wm   = wid & 1;
    const int wn   = wid >> 1;
    const int block_col = blockIdx.x * 128;
    const int block_row = blockIdx.y * 128;

    const int a_lrow = lane & 15;
    const int a_lcol = (lane >> 4) << 3;
    const int b_lrow = (lane & 7) + ((lane >> 4) & 1) * 8;
    const int b_lcol = ((lane >> 3) & 1) << 3;
    const uint32_t a_k0 = (uint32_t)(a_lcol >> 3);
    const uint32_t b_k0 = (uint32_t)(b_lcol >> 3);

    uint32_t a_rowoff[4], b_rowoff[2];
    uint32_t a_s[4], b_s[2];
#pragma unroll
    for (int f = 0; f < 4; f++) {
        int r = wm * 64 + f * 16 + a_lrow;
        a_rowoff[f] = (uint32_t)(r * 64);
        a_s[f] = (uint32_t)(r >> 1) & 3u;
    }
#pragma unroll
    for (int p = 0; p < 2; p++) {
        int r = wn * 32 + p * 16 + b_lrow;
        b_rowoff[p] = (uint32_t)(r * 64);
        b_s[p] = (uint32_t)(r >> 1) & 3u;
    }

    float acc[4][4][4];
#pragma unroll
    for (int i = 0; i < 4; i++)
#pragma unroll
        for (int j = 0; j < 4; j++)
#pragma unroll
            for (int c = 0; c < 4; c++) acc[i][j][c] = 0.0f;

    const int ldrow = tid >> 2;
    const int ldc   = tid & 3;
    const int crow  = tid >> 1;
    const int chalf = tid & 1;

    auto issue = [&](int kc) {
        int s = kc % 3;
#pragma unroll
        for (int i = 0; i < 4; i++) {
            int idx = tid + i * 256;
            int row = idx >> 3, c = idx & 7;
            int rg = block_row + row;
            if (rg >= M) rg = M - 1;
            const float* g = Af + (size_t)rg * 256 + kc * 32 + c * 4;
            uint32_t so = (uint32_t)(row * 128) +
                          (((uint32_t)(c ^ (row & 7))) << 4);
            cp_async16(sb + (uint32_t)(s * F_A32_STG) + so, g);
        }
        uint32_t bbase = sb + F_B_OFF + (uint32_t)s * F_B_STG;
#pragma unroll
        for (int h = 0; h < 2; h++) {
            int row = ldrow + h * 64;
            size_t gB = (size_t)(block_col + row) * 32 + kc * 4 + ldc;
            uint32_t so = swz(row, (uint32_t)ldc);
            cp_async16(bbase + so, Bhi4 + gB);
            cp_async16(bbase + TILE_SW + so, Blo4 + gB);
        }
        CP_COMMIT();
    };

    issue(0);
    issue(1);

    for (int kc = 0; kc < 8; kc++) {
        CP_WAIT(1);
        __syncthreads();
        if (kc < 6) issue(kc + 2);

        {
            const char* afb = smem + (kc % 3) * F_A32_STG + crow * 128;
            uint32_t rs = (uint32_t)(crow & 7);
            float4 v0 = *reinterpret_cast<const float4*>(
                afb + (((uint32_t)(chalf * 4 + 0) ^ rs) << 4));
            float4 v1 = *reinterpret_cast<const float4*>(
                afb + (((uint32_t)(chalf * 4 + 1) ^ rs) << 4));
            float4 v2 = *reinterpret_cast<const float4*>(
                afb + (((uint32_t)(chalf * 4 + 2) ^ rs) << 4));
            float4 v3 = *reinterpret_cast<const float4*>(
                afb + (((uint32_t)(chalf * 4 + 3) ^ rs) << 4));
            uint4 H0, H1, L0, L1;
            H0.x = pack_bf16x2(v0.x, v0.y); H0.y = pack_bf16x2(v0.z, v0.w);
            H0.z = pack_bf16x2(v1.x, v1.y); H0.w = pack_bf16x2(v1.z, v1.w);
            H1.x = pack_bf16x2(v2.x, v2.y); H1.y = pack_bf16x2(v2.z, v2.w);
            H1.z = pack_bf16x2(v3.x, v3.y); H1.w = pack_bf16x2(v3.z, v3.w);
            L0.x = pack_bf16x2(v0.x - __bfloat162float(__float2bfloat16(v0.x)),
                               v0.y - __bfloat162float(__float2bfloat16(v0.y)));
            L0.y = pack_bf16x2(v0.z - __bfloat162float(__float2bfloat16(v0.z)),
                               v0.w - __bfloat162float(__float2bfloat16(v0.w)));
            L0.z = pack_bf16x2(v1.x - __bfloat162float(__float2bfloat16(v1.x)),
                               v1.y - __bfloat162float(__float2bfloat16(v1.y)));
            L0.w = pack_bf16x2(v1.z - __bfloat162float(__float2bfloat16(v1.z)),
                               v1.w - __bfloat162float(__float2bfloat16(v1.w)));
            L1.x = pack_bf16x2(v2.x - __bfloat162float(__float2bfloat16(v2.x)),
                               v2.y - __bfloat162float(__float2bfloat16(v2.y)));
            L1.y = pack_bf16x2(v2.z - __bfloat162float(__float2bfloat16(v2.z)),
                               v2.w - __bfloat162float(__float2bfloat16(v2.w)));
            L1.z = pack_bf16x2(v3.x - __bfloat162float(__float2bfloat16(v3.x)),
                               v3.y - __bfloat162float(__float2bfloat16(v3.y)));
            L1.w = pack_bf16x2(v3.z - __bfloat162float(__float2bfloat16(v3.z)),
                               v3.w - __bfloat162float(__float2bfloat16(v3.w)));
            uint32_t cs = (uint32_t)(crow >> 1) & 3u;
            uint32_t g0 = ((uint32_t)(chalf * 2 + 0) ^ cs) << 4;
            uint32_t g1 = ((uint32_t)(chalf * 2 + 1) ^ cs) << 4;
            char* ah = smem + F_AHI + crow * 64;
            char* al = smem + F_ALO + crow * 64;
            *reinterpret_cast<uint4*>(ah + g0) = H0;
            *reinterpret_cast<uint4*>(ah + g1) = H1;
            *reinterpret_cast<uint4*>(al + g0) = L0;
            *reinterpret_cast<uint4*>(al + g1) = L1;
        }
        __syncthreads();

        uint32_t uAhi = sb + F_AHI;
        uint32_t uAlo = sb + F_ALO;
        uint32_t uBhi = sb + F_B_OFF + (uint32_t)(kc % 3) * F_B_STG;
        uint32_t uBlo = uBhi + TILE_SW;

        uint32_t ah[4][4], al[4][4], bh[2][4], bl[2][4];
#pragma unroll
        for (int ks16 = 0; ks16 < 2; ks16++) {
            const uint32_t kb = (uint32_t)(ks16 * 2);
#pragma unroll
            for (int f = 0; f < 4; f++) {
                uint32_t off = a_rowoff[f] + (((a_k0 + kb) ^ a_s[f]) << 4);
                ldsm_x4(uAhi + off, ah[f]);
                ldsm_x4(uAlo + off, al[f]);
            }
#pragma unroll
            for (int p = 0; p < 2; p++) {
                uint32_t off = b_rowoff[p] + (((b_k0 + kb) ^ b_s[p]) << 4);
                ldsm_x4(uBhi + off, bh[p]);
                ldsm_x4(uBlo + off, bl[p]);
            }
#pragma unroll
            for (int mf = 0; mf < 4; mf++)
#pragma unroll
                for (int nf = 0; nf < 4; nf++) {
                    int p = nf >> 1, q = (nf & 1) * 2;
                    mma16816(acc[mf][nf], ah[mf], bh[p][q], bh[p][q + 1]);
                    mma16816(acc[mf][nf], ah[mf], bl[p][q], bl[p][q + 1]);
                    mma16816(acc[mf][nf], al[mf], bh[p][q], bh[p][q + 1]);
                }
        }
    }

#pragma unroll
    for (int mf = 0; mf < 4; mf++) {
        int r0 = block_row + wm * 64 + mf * 16 + (lane >> 2);
        int r1 = r0 + 8;
#pragma unroll
        for (int nf = 0; nf < 4; nf++) {
            int col = block_col + wn * 32 + nf * 8 + (lane & 3) * 2;
            float b0 = bias[col], b1 = bias[col + 1];
            float v00 = fmaxf(acc[mf][nf][0] + b0, 0.f);
            float v01 = fmaxf(acc[mf][nf][1] + b1, 0.f);
            float v10 = fmaxf(acc[mf][nf][2] + b0, 0.f);
            float v11 = fmaxf(acc[mf][nf][3] + b1, 0.f);
            uint32_t hp0 = pack_bf16x2(v00, v01);
            uint32_t hp1 = pack_bf16x2(v10, v11);
            float w00 = v00 - __bfloat162float(__float2bfloat16(v00));
            float w01 = v01 - __bfloat162float(__float2bfloat16(v01));
            float w10 = v10 - __bfloat162float(__float2bfloat16(v10));
            float w11 = v11 - __bfloat162float(__float2bfloat16(v11));
            uint32_t lp0 = pack_bf16x2(w00, w01);
            uint32_t lp1 = pack_bf16x2(w10, w11);
            if (r0 < M) {
                *reinterpret_cast<uint32_t*>(Chi + (size_t)r0 * HID + col) = hp0;
                *reinterpret_cast<uint32_t*>(Clo + (size_t)r0 * HID + col) = lp0;
            }
            if (r1 < M) {
                *reinterpret_cast<uint32_t*>(Chi + (size_t)r1 * HID + col) = hp1;
                *reinterpret_cast<uint32_t*>(Clo + (size_t)r1 * HID + col) = lp1;
            }
        }
    }
}

// =================== fp32 tiled SGEMM (small head GEMM) =====================

__global__ __launch_bounds__(256)
void sgemm_bias_relu(int M, const float* __restrict__ A,
                     const float* __restrict__ B,
                     const float* __restrict__ bias,
                     float* __restrict__ C,
                     int N, int K, int doRelu) {
    __shared__ float As[8][128];
    __shared__ float Bs[8][128];

    const int tid       = threadIdx.x;
    const int block_row = blockIdx.y * 128;
    const int block_col = blockIdx.x * 128;

    const int aRow = tid >> 1;
    const int aCol = (tid & 1) << 2;
    const int bRow = tid >> 5;
    const int bCol = (tid & 31) << 2;
    const int trow = (tid >> 4) << 3;
    const int tcol = (tid & 15) << 3;

    float acc[8][8];
#pragma unroll
    for (int i = 0; i < 8; i++)
#pragma unroll
        for (int j = 0; j < 8; j++) acc[i][j] = 0.0f;

    for (int kt = 0; kt < K; kt += 8) {
        float4 av = make_float4(0.f, 0.f, 0.f, 0.f);
        if (block_row + aRow < M)
            av = *reinterpret_cast<const float4*>(&A[(size_t)(block_row + aRow) * K + kt + aCol]);
        As[aCol + 0][aRow] = av.x;
        As[aCol + 1][aRow] = av.y;
        As[aCol + 2][aRow] = av.z;
        As[aCol + 3][aRow] = av.w;

        float4 bv = *reinterpret_cast<const float4*>(&B[(size_t)(kt + bRow) * N + block_col + bCol]);
        *reinterpret_cast<float4*>(&Bs[bRow][bCol]) = bv;
        __syncthreads();

#pragma unroll
        for (int k = 0; k < 8; k++) {
            float ra[8], rb[8];
#pragma unroll
            for (int i = 0; i < 8; i++) ra[i] = As[k][trow + i];
#pragma unroll
            for (int j = 0; j < 8; j++) rb[j] = Bs[k][tcol + j];
#pragma unroll
            for (int i = 0; i < 8; i++)
#pragma unroll
                for (int j = 0; j < 8; j++)
                    acc[i][j] = fmaf(ra[i], rb[j], acc[i][j]);
        }
        __syncthreads();
    }

#pragma unroll
    for (int i = 0; i < 8; i++) {
        int r = block_row + trow + i;
        if (r < M) {
#pragma unroll
            for (int j = 0; j < 8; j += 4) {
                float4 v;
                v.x = acc[i][j + 0] + bias[block_col + tcol + j + 0];
                v.y = acc[i][j + 1] + bias[block_col + tcol + j + 1];
                v.z = acc[i][j + 2] + bias[block_col + tcol + j + 2];
                v.w = acc[i][j + 3] + bias[block_col + tcol + j + 3];
                if (doRelu) {
                    v.x = fmaxf(v.x, 0.f); v.y = fmaxf(v.y, 0.f);
                    v.z = fmaxf(v.z, 0.f); v.w = fmaxf(v.w, 0.f);
                }
                *reinterpret_cast<float4*>(&C[(size_t)r * N + block_col + tcol + j]) = v;
            }
        }
    }
}

// ============================ pool finalize + head ==========================

__global__ void pool_div(float* __restrict__ pooled,
                         const float* __restrict__ counts) {
    int i = blockIdx.x * blockDim.x + threadIdx.x;
    float c = counts[i >> 8];
    pooled[i] = pooled[i] / fmaxf(c, 1.0f);
}

__global__ void head_final(const float* __restrict__ hid,
                           const float* __restrict__ W,
                           const float* __restrict__ b,
                           float* __restrict__ out) {
    int m = blockIdx.x * blockDim.x + threadIdx.x;
    if (m >= N_GRAPHS) return;
    float a0 = b[0], a1 = b[1], a2 = b[2];
    const float* hs = hid + (size_t)m * 128;
#pragma unroll 8
    for (int k = 0; k < 128; k++) {
        float h = hs[k];
        a0 = fmaf(h, W[k * 3 + 0], a0);
        a1 = fmaf(h, W[k * 3 + 1], a1);
        a2 = fmaf(h, W[k * 3 + 2], a2);
    }
    out[m * 3 + 0] = a0;
    out[m * 3 + 1] = a1;
    out[m * 3 + 2] = a2;
}

// ============================ launch ========================================

extern "C" void kernel_launch(void* const* d_in, const int* in_sizes, int n_in,
                              void* d_out, int out_size) {
    const float* x     = (const float*)d_in[0];
    const int*   ei    = (const int*)d_in[1];
    const int*   batch = (const int*)d_in[2];

    const float* Wa[4], *ba[4], *Wb[4], *bb[4];
    for (int l = 0; l < 4; l++) {
        Wa[l] = (const float*)d_in[3 + 4 * l + 0];
        ba[l] = (const float*)d_in[3 + 4 * l + 1];
        Wb[l] = (const float*)d_in[3 + 4 * l + 2];
        bb[l] = (const float*)d_in[3 + 4 * l + 3];
    }
    const float* Wh1 = (const float*)d_in[19];
    const float* bh1 = (const float*)d_in[20];
    const float* Wh2 = (const float*)d_in[21];
    const float* bh2 = (const float*)d_in[22];
    float* out = (float*)d_out;

    __nv_bfloat16 *A2hi, *A2lo, *Whi, *Wlo;
    float *bufB, *bufC, *agg7, *pooled, *counts, *hid;
    cudaGetSymbolAddress((void**)&A2hi,   g_A2hi);
    cudaGetSymbolAddress((void**)&A2lo,   g_A2lo);
    cudaGetSymbolAddress((void**)&Whi,    g_Whi);
    cudaGetSymbolAddress((void**)&Wlo,    g_Wlo);
    cudaGetSymbolAddress((void**)&bufB,   g_bufB);
    cudaGetSymbolAddress((void**)&bufC,   g_bufC);
    cudaGetSymbolAddress((void**)&agg7,   g_agg7);
    cudaGetSymbolAddress((void**)&pooled, g_pooled);
    cudaGetSymbolAddress((void**)&counts, g_counts);
    cudaGetSymbolAddress((void**)&hid,    g_hid);

    cudaFuncSetAttribute(mma_gemm_split,
                         cudaFuncAttributeMaxDynamicSharedMemorySize, GEMM_SMEM);
    cudaFuncSetAttribute(mma_gemm_split_f32a,
                         cudaFuncAttributeMaxDynamicSharedMemorySize, F_SMEM);

    // ---- prologue: weights, counts, pooled init ----
    dim3 cw_grid(HID, 7);
    convert_weight_all<<<cw_grid, HID>>>(Wb[0], Wa[1], Wb[1], Wa[2], Wb[2],
                                         Wa[3], Wb[3], Whi, Wlo);
    cudaMemsetAsync(pooled, 0, (size_t)N_GRAPHS * HID * sizeof(float));
    cudaMemsetAsync(counts, 0, (size_t)N_GRAPHS * sizeof(float));
    count_kernel<<<(N_NODES + 255) / 256, 256>>>(batch, counts);

    dim3 mma_grid(2, (N_NODES + 127) / 128);

    // ---- layer 1 ----
    cudaMemcpyAsync(agg7, x, (size_t)N_NODES * 7 * sizeof(float),
                    cudaMemcpyDeviceToDevice);
    scatter_add_7<<<(N_EDGES + 255) / 256, 256>>>(x, ei, agg7);
    gemm_k7_relu_split<<<K7_BLOCKS, 256>>>(agg7, Wa[0], ba[0], A2hi, A2lo);
    mma_gemm_split<<<mma_grid, 256, GEMM_SMEM>>>(
        N_NODES, (const uint4*)A2hi, (const uint4*)A2lo,
        (const uint4*)Whi, (const uint4*)Wlo,
        bb[0], bufB, bufC, nullptr, nullptr, nullptr, nullptr, 0);

    // ---- layers 2..4 ----
    for (int l = 1; l < 4; l++) {
        scatter_add_256<<<((size_t)N_EDGES * 32 + 255) / 256, 256>>>(bufB, ei, bufC);
        mma_gemm_split_f32a<<<mma_grid, 256, F_SMEM>>>(
            N_NODES, bufC,
            (const uint4*)(Whi + (size_t)(2 * l - 1) * HID * HID),
            (const uint4*)(Wlo + (size_t)(2 * l - 1) * HID * HID),
            ba[l], A2hi, A2lo);
        if (l < 3) {
            mma_gemm_split<<<mma_grid, 256, GEMM_SMEM>>>(
                N_NODES, (const uint4*)A2hi, (const uint4*)A2lo,
                (const uint4*)(Whi + (size_t)(2 * l) * HID * HID),
                (const uint4*)(Wlo + (size_t)(2 * l) * HID * HID),
                bb[l], bufB, bufC, nullptr, nullptr, nullptr, nullptr, 0);
        } else {
            mma_gemm_split<<<mma_grid, 256, GEMM_SMEM>>>(
                N_NODES, (const uint4*)A2hi, (const uint4*)A2lo,
                (const uint4*)(Whi + (size_t)(2 * l) * HID * HID),
                (const uint4*)(Wlo + (size_t)(2 * l) * HID * HID),
                bb[l], nullptr, nullptr, nullptr, nullptr, batch, pooled, 2);
        }
    }

    // ---- pool finalize ----
    pool_div<<<N_GRAPHS * HID / 256, 256>>>(pooled, counts);

    // ---- head ----
    dim3 head_grid(1, (N_GRAPHS + 127) / 128);
    sgemm_bias_relu<<<head_grid, 256>>>(N_GRAPHS, pooled, Wh1, bh1, hid,
                                        128, 256, 1);
    head_final<<<(N_GRAPHS + 255) / 256, 256>>>(hid, Wh2, bh2, out);
}